// round 1
// baseline (speedup 1.0000x reference)
#include <cuda_runtime.h>
#include <cuda_bf16.h>
#include <math.h>

// Problem constants
#define BATCH 2
#define SEQ   2048
#define DMODEL 1024
#define NHEADS 16
#define DK    64
#define DFF   4096
#define MTOK  (BATCH*SEQ)          // 4096 tokens
#define LNEPS 1e-6f

// ---------------- static device scratch (no allocation allowed) ----------------
__device__ float g_h  [MTOK*DMODEL];   // LN1 output
__device__ float g_q  [MTOK*DMODEL];
__device__ float g_k  [MTOK*DMODEL];
__device__ float g_v  [MTOK*DMODEL];
__device__ float g_ctx[MTOK*DMODEL];
__device__ float g_x1 [MTOK*DMODEL];   // residual-1 output
__device__ float g_h2 [MTOK*DMODEL];   // LN2 output
__device__ float g_ff [MTOK*DFF];      // relu(ffn1) output (64 MB)
__device__ float g_scores[(size_t)BATCH*NHEADS*SEQ*SEQ]; // 512 MB

// ---------------- LayerNorm (scalar alpha/beta, ddof=1, eps on std) ----------------
__global__ __launch_bounds__(256) void ln_kernel(const float* __restrict__ x,
                                                 float* __restrict__ out,
                                                 const float* __restrict__ alpha,
                                                 const float* __restrict__ beta)
{
    const int row = blockIdx.x;
    const int tid = threadIdx.x;
    const float* xr = x + (size_t)row * DMODEL;
    float4 v = *(const float4*)&xr[tid * 4];

    float s1 = v.x + v.y + v.z + v.w;
    float s2 = v.x*v.x + v.y*v.y + v.z*v.z + v.w*v.w;

    // warp reduce
    for (int o = 16; o > 0; o >>= 1) {
        s1 += __shfl_down_sync(0xffffffffu, s1, o);
        s2 += __shfl_down_sync(0xffffffffu, s2, o);
    }
    __shared__ float ws1[8], ws2[8];
    int lane = tid & 31, wid = tid >> 5;
    if (lane == 0) { ws1[wid] = s1; ws2[wid] = s2; }
    __syncthreads();
    if (tid == 0) {
        float a = 0.f, b = 0.f;
        #pragma unroll
        for (int i = 0; i < 8; i++) { a += ws1[i]; b += ws2[i]; }
        ws1[0] = a; ws2[0] = b;
    }
    __syncthreads();
    float sum = ws1[0], sumsq = ws2[0];
    float mean = sum * (1.0f / DMODEL);
    float var  = (sumsq - (float)DMODEL * mean * mean) * (1.0f / (DMODEL - 1));
    var = fmaxf(var, 0.0f);
    float stdv = sqrtf(var);
    float a_ = alpha[0], b_ = beta[0];
    float inv = a_ / (stdv + LNEPS);

    float4 o4;
    o4.x = (v.x - mean) * inv + b_;
    o4.y = (v.y - mean) * inv + b_;
    o4.z = (v.z - mean) * inv + b_;
    o4.w = (v.w - mean) * inv + b_;
    *(float4*)&out[(size_t)row * DMODEL + tid * 4] = o4;
}

// ---------------- 128x128x8 tiled fp32 GEMM: C = A[M,K] * B[K,N] + bias (+res) (relu) ----------------
template<int RELU, int RES>
__global__ __launch_bounds__(256) void sgemm_bias(const float* __restrict__ A,
                                                  const float* __restrict__ Bm,
                                                  const float* __restrict__ bias,
                                                  const float* __restrict__ res,
                                                  float* __restrict__ C,
                                                  int K, int N)
{
    __shared__ float As[8][128];
    __shared__ float Bs[8][128];

    const int tid = threadIdx.x;
    const int row0 = blockIdx.y * 128;
    const int col0 = blockIdx.x * 128;

    const int aRow = tid >> 1;            // 0..127
    const int aCol = (tid & 1) * 4;       // 0 or 4
    const int bRow = tid >> 5;            // 0..7
    const int bCol = (tid & 31) << 2;     // 0..124

    const int ty = tid >> 4;              // 0..15 -> rows ty*8
    const int tx = tid & 15;              // 0..15 -> cols tx*8

    float acc[8][8];
    #pragma unroll
    for (int i = 0; i < 8; i++)
        #pragma unroll
        for (int j = 0; j < 8; j++) acc[i][j] = 0.f;

    const float* Aptr = A + (size_t)(row0 + aRow) * K + aCol;
    const float* Bptr = Bm + (size_t)bRow * N + col0 + bCol;

    for (int k0 = 0; k0 < K; k0 += 8) {
        float4 a4 = *(const float4*)(Aptr + k0);
        float4 b4 = *(const float4*)(Bptr + (size_t)k0 * N);
        As[aCol + 0][aRow] = a4.x;
        As[aCol + 1][aRow] = a4.y;
        As[aCol + 2][aRow] = a4.z;
        As[aCol + 3][aRow] = a4.w;
        *(float4*)&Bs[bRow][bCol] = b4;
        __syncthreads();

        #pragma unroll
        for (int kk = 0; kk < 8; kk++) {
            float a[8], b[8];
            *(float4*)&a[0] = *(const float4*)&As[kk][ty * 8];
            *(float4*)&a[4] = *(const float4*)&As[kk][ty * 8 + 4];
            *(float4*)&b[0] = *(const float4*)&Bs[kk][tx * 8];
            *(float4*)&b[4] = *(const float4*)&Bs[kk][tx * 8 + 4];
            #pragma unroll
            for (int i = 0; i < 8; i++)
                #pragma unroll
                for (int j = 0; j < 8; j++)
                    acc[i][j] = fmaf(a[i], b[j], acc[i][j]);
        }
        __syncthreads();
    }

    // epilogue
    float bvals[8];
    *(float4*)&bvals[0] = *(const float4*)&bias[col0 + tx * 8];
    *(float4*)&bvals[4] = *(const float4*)&bias[col0 + tx * 8 + 4];

    #pragma unroll
    for (int i = 0; i < 8; i++) {
        int r = row0 + ty * 8 + i;
        float* cr = C + (size_t)r * N + col0 + tx * 8;
        float out[8];
        #pragma unroll
        for (int j = 0; j < 8; j++) out[j] = acc[i][j] + bvals[j];
        if (RES) {
            const float* rr = res + (size_t)r * N + col0 + tx * 8;
            float4 r0 = *(const float4*)&rr[0];
            float4 r1 = *(const float4*)&rr[4];
            out[0] += r0.x; out[1] += r0.y; out[2] += r0.z; out[3] += r0.w;
            out[4] += r1.x; out[5] += r1.y; out[6] += r1.z; out[7] += r1.w;
        }
        if (RELU) {
            #pragma unroll
            for (int j = 0; j < 8; j++) out[j] = fmaxf(out[j], 0.f);
        }
        *(float4*)&cr[0] = *(const float4*)&out[0];
        *(float4*)&cr[4] = *(const float4*)&out[4];
    }
}

// ---------------- attention scores: S[bh,i,j] = (Q_i . K_j)/8, masked ----------------
__global__ __launch_bounds__(256) void scores_kernel(const float* __restrict__ q,
                                                     const float* __restrict__ k,
                                                     const int* __restrict__ mask,
                                                     float* __restrict__ scores)
{
    const int bh = blockIdx.z;
    const int b = bh >> 4;          // /NHEADS
    const int h = bh & 15;
    const int q0 = blockIdx.y * 64;
    const int k0 = blockIdx.x * 64;
    const int tid = threadIdx.x;

    __shared__ float Qs[64][65];
    __shared__ float Kst[64][65];   // transposed: Kst[d][j]

    const int hbase = h * DK;
    #pragma unroll
    for (int it = 0; it < 16; it++) {
        int idx = tid + it * 256;
        int r = idx >> 6, c = idx & 63;
        Qs[r][c]  = q[(size_t)(b * SEQ + q0 + r) * DMODEL + hbase + c];
        Kst[c][r] = k[(size_t)(b * SEQ + k0 + r) * DMODEL + hbase + c];
    }
    __syncthreads();

    const int ty = tid >> 4, tx = tid & 15;
    float acc[4][4];
    #pragma unroll
    for (int i = 0; i < 4; i++)
        #pragma unroll
        for (int j = 0; j < 4; j++) acc[i][j] = 0.f;

    #pragma unroll
    for (int d = 0; d < 64; d++) {
        float a[4], bb[4];
        #pragma unroll
        for (int i = 0; i < 4; i++) a[i] = Qs[ty * 4 + i][d];
        #pragma unroll
        for (int j = 0; j < 4; j++) bb[j] = Kst[d][tx * 4 + j];
        #pragma unroll
        for (int i = 0; i < 4; i++)
            #pragma unroll
            for (int j = 0; j < 4; j++)
                acc[i][j] = fmaf(a[i], bb[j], acc[i][j]);
    }

    #pragma unroll
    for (int i = 0; i < 4; i++) {
        int qi = q0 + ty * 4 + i;
        #pragma unroll
        for (int j = 0; j < 4; j++) {
            int kj = k0 + tx * 4 + j;
            int mv = mask[(size_t)b * SEQ * SEQ + (size_t)qi * SEQ + kj];
            float sv = (mv == 0) ? -1e9f : acc[i][j] * 0.125f;
            scores[((size_t)bh * SEQ + qi) * SEQ + kj] = sv;
        }
    }
}

// ---------------- softmax over last dim (2048), in place ----------------
__global__ __launch_bounds__(256) void softmax_kernel(float* __restrict__ s)
{
    const size_t row = blockIdx.x;
    const int tid = threadIdx.x;
    float* sr = s + row * SEQ;

    float4 v0 = *(const float4*)&sr[tid * 4];
    float4 v1 = *(const float4*)&sr[1024 + tid * 4];

    float m = fmaxf(fmaxf(fmaxf(v0.x, v0.y), fmaxf(v0.z, v0.w)),
                    fmaxf(fmaxf(v1.x, v1.y), fmaxf(v1.z, v1.w)));
    for (int o = 16; o > 0; o >>= 1) m = fmaxf(m, __shfl_down_sync(0xffffffffu, m, o));
    __shared__ float wbuf[8];
    int lane = tid & 31, wid = tid >> 5;
    if (lane == 0) wbuf[wid] = m;
    __syncthreads();
    if (tid == 0) {
        float mm = wbuf[0];
        #pragma unroll
        for (int i = 1; i < 8; i++) mm = fmaxf(mm, wbuf[i]);
        wbuf[0] = mm;
    }
    __syncthreads();
    m = wbuf[0];
    __syncthreads();

    float e[8];
    e[0] = expf(v0.x - m); e[1] = expf(v0.y - m); e[2] = expf(v0.z - m); e[3] = expf(v0.w - m);
    e[4] = expf(v1.x - m); e[5] = expf(v1.y - m); e[6] = expf(v1.z - m); e[7] = expf(v1.w - m);
    float sum = 0.f;
    #pragma unroll
    for (int i = 0; i < 8; i++) sum += e[i];
    for (int o = 16; o > 0; o >>= 1) sum += __shfl_down_sync(0xffffffffu, sum, o);
    if (lane == 0) wbuf[wid] = sum;
    __syncthreads();
    if (tid == 0) {
        float ss = 0.f;
        #pragma unroll
        for (int i = 0; i < 8; i++) ss += wbuf[i];
        wbuf[0] = ss;
    }
    __syncthreads();
    float inv = 1.0f / wbuf[0];

    float4 o0, o1;
    o0.x = e[0] * inv; o0.y = e[1] * inv; o0.z = e[2] * inv; o0.w = e[3] * inv;
    o1.x = e[4] * inv; o1.y = e[5] * inv; o1.z = e[6] * inv; o1.w = e[7] * inv;
    *(float4*)&sr[tid * 4] = o0;
    *(float4*)&sr[1024 + tid * 4] = o1;
}

// ---------------- context: ctx[b,i,h*64+d] = sum_j P[bh,i,j] * V[b,j,h*64+d] ----------------
__global__ __launch_bounds__(256) void ctx_kernel(const float* __restrict__ P,
                                                  const float* __restrict__ v,
                                                  float* __restrict__ ctx)
{
    const int bh = blockIdx.y;
    const int b = bh >> 4, h = bh & 15;
    const int i0 = blockIdx.x * 64;
    const int tid = threadIdx.x;
    const int hbase = h * DK;

    __shared__ float Ps[64][65];
    __shared__ float Vs[64][65];

    const int ty = tid >> 4, tx = tid & 15;
    float acc[4][4];
    #pragma unroll
    for (int i = 0; i < 4; i++)
        #pragma unroll
        for (int j = 0; j < 4; j++) acc[i][j] = 0.f;

    for (int jt = 0; jt < SEQ / 64; jt++) {
        int j0 = jt * 64;
        #pragma unroll
        for (int it = 0; it < 16; it++) {
            int idx = tid + it * 256;
            int r = idx >> 6, c = idx & 63;
            Ps[r][c] = P[((size_t)bh * SEQ + i0 + r) * SEQ + j0 + c];
            Vs[r][c] = v[(size_t)(b * SEQ + j0 + r) * DMODEL + hbase + c];
        }
        __syncthreads();

        #pragma unroll
        for (int jj = 0; jj < 64; jj++) {
            float a[4], bb[4];
            #pragma unroll
            for (int i = 0; i < 4; i++) a[i] = Ps[ty * 4 + i][jj];
            #pragma unroll
            for (int j = 0; j < 4; j++) bb[j] = Vs[jj][tx * 4 + j];
            #pragma unroll
            for (int i = 0; i < 4; i++)
                #pragma unroll
                for (int j = 0; j < 4; j++)
                    acc[i][j] = fmaf(a[i], bb[j], acc[i][j]);
        }
        __syncthreads();
    }

    #pragma unroll
    for (int i = 0; i < 4; i++) {
        int r = b * SEQ + i0 + ty * 4 + i;
        #pragma unroll
        for (int j = 0; j < 4; j++)
            ctx[(size_t)r * DMODEL + hbase + tx * 4 + j] = acc[i][j];
    }
}

// ---------------- launch ----------------
extern "C" void kernel_launch(void* const* d_in, const int* in_sizes, int n_in,
                              void* d_out, int out_size)
{
    const float* x    = (const float*)d_in[0];
    const int*   mask = (const int*)  d_in[1];
    const float* wq = (const float*)d_in[2];  const float* bq = (const float*)d_in[3];
    const float* wk = (const float*)d_in[4];  const float* bk = (const float*)d_in[5];
    const float* wv = (const float*)d_in[6];  const float* bv = (const float*)d_in[7];
    const float* wo = (const float*)d_in[8];  const float* bo = (const float*)d_in[9];
    const float* w1 = (const float*)d_in[10]; const float* b1 = (const float*)d_in[11];
    const float* w2 = (const float*)d_in[12]; const float* b2 = (const float*)d_in[13];
    const float* ln1_a = (const float*)d_in[14]; const float* ln1_b = (const float*)d_in[15];
    const float* ln2_a = (const float*)d_in[16]; const float* ln2_b = (const float*)d_in[17];
    float* out = (float*)d_out;

    float *p_h, *p_q, *p_k, *p_v, *p_ctx, *p_x1, *p_h2, *p_ff, *p_sc;
    cudaGetSymbolAddress((void**)&p_h,  g_h);
    cudaGetSymbolAddress((void**)&p_q,  g_q);
    cudaGetSymbolAddress((void**)&p_k,  g_k);
    cudaGetSymbolAddress((void**)&p_v,  g_v);
    cudaGetSymbolAddress((void**)&p_ctx,g_ctx);
    cudaGetSymbolAddress((void**)&p_x1, g_x1);
    cudaGetSymbolAddress((void**)&p_h2, g_h2);
    cudaGetSymbolAddress((void**)&p_ff, g_ff);
    cudaGetSymbolAddress((void**)&p_sc, g_scores);

    // 1) LN1
    ln_kernel<<<MTOK, 256>>>(x, p_h, ln1_a, ln1_b);

    // 2) Q,K,V projections  (M=4096, N=1024, K=1024)
    dim3 gProj(DMODEL / 128, MTOK / 128);
    sgemm_bias<0,0><<<gProj, 256>>>(p_h, wq, bq, nullptr, p_q, DMODEL, DMODEL);
    sgemm_bias<0,0><<<gProj, 256>>>(p_h, wk, bk, nullptr, p_k, DMODEL, DMODEL);
    sgemm_bias<0,0><<<gProj, 256>>>(p_h, wv, bv, nullptr, p_v, DMODEL, DMODEL);

    // 3) scores + softmax + ctx
    scores_kernel<<<dim3(SEQ / 64, SEQ / 64, BATCH * NHEADS), 256>>>(p_q, p_k, mask, p_sc);
    softmax_kernel<<<BATCH * NHEADS * SEQ, 256>>>(p_sc);
    ctx_kernel<<<dim3(SEQ / 64, BATCH * NHEADS), 256>>>(p_sc, p_v, p_ctx);

    // 4) O projection + residual -> x1
    sgemm_bias<0,1><<<gProj, 256>>>(p_ctx, wo, bo, x, p_x1, DMODEL, DMODEL);

    // 5) LN2
    ln_kernel<<<MTOK, 256>>>(p_x1, p_h2, ln2_a, ln2_b);

    // 6) FFN1 + ReLU  (M=4096, N=4096, K=1024)
    sgemm_bias<1,0><<<dim3(DFF / 128, MTOK / 128), 256>>>(p_h2, w1, b1, nullptr, p_ff, DMODEL, DFF);

    // 7) FFN2 + residual -> out  (M=4096, N=1024, K=4096)
    sgemm_bias<0,1><<<gProj, 256>>>(p_ff, w2, b2, p_x1, out, DFF, DMODEL);
}

// round 2
// speedup vs baseline: 1.2093x; 1.2093x over previous
#include <cuda_runtime.h>
#include <cuda_bf16.h>
#include <math.h>
#include <mma.h>

using namespace nvcuda;

// Problem constants
#define BATCH 2
#define SEQ   2048
#define DMODEL 1024
#define NHEADS 16
#define DK    64
#define DFF   4096
#define MTOK  (BATCH*SEQ)          // 4096 tokens
#define LNEPS 1e-6f

// ---------------- static device scratch (no allocation allowed) ----------------
__device__ float g_h  [MTOK*DMODEL];   // LN1 output
__device__ float g_q  [MTOK*DMODEL];
__device__ float g_k  [MTOK*DMODEL];
__device__ float g_v  [MTOK*DMODEL];
__device__ float g_ctx[MTOK*DMODEL];
__device__ float g_x1 [MTOK*DMODEL];   // residual-1 output
__device__ float g_h2 [MTOK*DMODEL];   // LN2 output
__device__ float g_ff [MTOK*DFF];      // relu(ffn1) output (64 MB)
__device__ float g_scores[(size_t)BATCH*NHEADS*SEQ*SEQ]; // 512 MB

// ---------------- LayerNorm (scalar alpha/beta, ddof=1, eps on std) ----------------
__global__ __launch_bounds__(256) void ln_kernel(const float* __restrict__ x,
                                                 float* __restrict__ out,
                                                 const float* __restrict__ alpha,
                                                 const float* __restrict__ beta)
{
    const int row = blockIdx.x;
    const int tid = threadIdx.x;
    const float* xr = x + (size_t)row * DMODEL;
    float4 v = *(const float4*)&xr[tid * 4];

    float s1 = v.x + v.y + v.z + v.w;
    float s2 = v.x*v.x + v.y*v.y + v.z*v.z + v.w*v.w;

    for (int o = 16; o > 0; o >>= 1) {
        s1 += __shfl_down_sync(0xffffffffu, s1, o);
        s2 += __shfl_down_sync(0xffffffffu, s2, o);
    }
    __shared__ float ws1[8], ws2[8];
    int lane = tid & 31, wid = tid >> 5;
    if (lane == 0) { ws1[wid] = s1; ws2[wid] = s2; }
    __syncthreads();
    if (tid == 0) {
        float a = 0.f, b = 0.f;
        #pragma unroll
        for (int i = 0; i < 8; i++) { a += ws1[i]; b += ws2[i]; }
        ws1[0] = a; ws2[0] = b;
    }
    __syncthreads();
    float sum = ws1[0], sumsq = ws2[0];
    float mean = sum * (1.0f / DMODEL);
    float var  = (sumsq - (float)DMODEL * mean * mean) * (1.0f / (DMODEL - 1));
    var = fmaxf(var, 0.0f);
    float stdv = sqrtf(var);
    float a_ = alpha[0], b_ = beta[0];
    float inv = a_ / (stdv + LNEPS);

    float4 o4;
    o4.x = (v.x - mean) * inv + b_;
    o4.y = (v.y - mean) * inv + b_;
    o4.z = (v.z - mean) * inv + b_;
    o4.w = (v.w - mean) * inv + b_;
    *(float4*)&out[(size_t)row * DMODEL + tid * 4] = o4;
}

// =============================================================================
// TF32 wmma GEMM: C[M,N] = A[M,K]*B[K,N] + bias (+res) (relu)
// Block tile 128x128, BK=32, 8 warps each computing 64x32 (4x2 tiles of 16x16).
// =============================================================================
#define LDA_S 36     // A smem leading dim (floats), mult of 4
#define LDB_S 132    // B smem leading dim (floats), mult of 4

template<int RELU, int RES>
__global__ __launch_bounds__(256) void gemm_tf32(const float* __restrict__ A,
                                                 const float* __restrict__ Bm,
                                                 const float* __restrict__ bias,
                                                 const float* __restrict__ res,
                                                 float* __restrict__ C,
                                                 int K, int N)
{
    __shared__ float As[128 * LDA_S];
    __shared__ float Bs[32 * LDB_S];
    __shared__ float stage[8 * 256];

    const int tid = threadIdx.x;
    const int warpId = tid >> 5;
    const int lane = tid & 31;
    const int row0 = blockIdx.y * 128;
    const int col0 = blockIdx.x * 128;
    const int warpRow = warpId & 1;   // 0..1 -> 64-row slab
    const int warpCol = warpId >> 1;  // 0..3 -> 32-col slab

    wmma::fragment<wmma::accumulator, 16, 16, 8, float> acc[4][2];
    #pragma unroll
    for (int i = 0; i < 4; i++)
        #pragma unroll
        for (int j = 0; j < 2; j++)
            wmma::fill_fragment(acc[i][j], 0.0f);

    // loader indices
    const int aRow = tid >> 3;           // 0..31 (it adds 32)
    const int aCol = (tid & 7) * 4;
    const int bRow = tid >> 5;           // 0..7 (it adds 8)
    const int bCol = (tid & 31) * 4;

    const int nChunks = K / 32;

    // load chunk 0
    #pragma unroll
    for (int it = 0; it < 4; it++) {
        int r = aRow + it * 32;
        float4 a4 = *(const float4*)&A[(size_t)(row0 + r) * K + aCol];
        *(float4*)&As[r * LDA_S + aCol] = a4;
        int br = bRow + it * 8;
        float4 b4 = *(const float4*)&Bm[(size_t)br * N + col0 + bCol];
        *(float4*)&Bs[br * LDB_S + bCol] = b4;
    }
    __syncthreads();

    float4 ra[4], rb[4];
    for (int c = 0; c < nChunks; c++) {
        if (c + 1 < nChunks) {
            int k0 = (c + 1) * 32;
            #pragma unroll
            for (int it = 0; it < 4; it++) {
                int r = aRow + it * 32;
                ra[it] = *(const float4*)&A[(size_t)(row0 + r) * K + k0 + aCol];
                int br = bRow + it * 8;
                rb[it] = *(const float4*)&Bm[(size_t)(k0 + br) * N + col0 + bCol];
            }
        }
        // compute from smem
        #pragma unroll
        for (int kk = 0; kk < 4; kk++) {
            wmma::fragment<wmma::matrix_a, 16, 16, 8, wmma::precision::tf32, wmma::row_major> af[4];
            wmma::fragment<wmma::matrix_b, 16, 16, 8, wmma::precision::tf32, wmma::row_major> bf[2];
            #pragma unroll
            for (int i = 0; i < 4; i++) {
                wmma::load_matrix_sync(af[i], &As[(warpRow * 64 + i * 16) * LDA_S + kk * 8], LDA_S);
                #pragma unroll
                for (int t = 0; t < af[i].num_elements; t++)
                    af[i].x[t] = wmma::__float_to_tf32(af[i].x[t]);
            }
            #pragma unroll
            for (int j = 0; j < 2; j++) {
                wmma::load_matrix_sync(bf[j], &Bs[(kk * 8) * LDB_S + warpCol * 32 + j * 16], LDB_S);
                #pragma unroll
                for (int t = 0; t < bf[j].num_elements; t++)
                    bf[j].x[t] = wmma::__float_to_tf32(bf[j].x[t]);
            }
            #pragma unroll
            for (int i = 0; i < 4; i++)
                #pragma unroll
                for (int j = 0; j < 2; j++)
                    wmma::mma_sync(acc[i][j], af[i], bf[j], acc[i][j]);
        }
        if (c + 1 < nChunks) {
            __syncthreads();
            #pragma unroll
            for (int it = 0; it < 4; it++) {
                int r = aRow + it * 32;
                *(float4*)&As[r * LDA_S + aCol] = ra[it];
                int br = bRow + it * 8;
                *(float4*)&Bs[br * LDB_S + bCol] = rb[it];
            }
            __syncthreads();
        }
    }

    // epilogue: stage each 16x16 tile through smem, add bias/res/relu, write
    float* st = &stage[warpId * 256];
    const int srow = lane >> 1;
    const int scol = (lane & 1) * 8;
    #pragma unroll
    for (int i = 0; i < 4; i++) {
        #pragma unroll
        for (int j = 0; j < 2; j++) {
            __syncwarp();
            wmma::store_matrix_sync(st, acc[i][j], 16, wmma::mem_row_major);
            __syncwarp();
            int gr = row0 + warpRow * 64 + i * 16 + srow;
            int gc = col0 + warpCol * 32 + j * 16 + scol;
            float4 v0 = *(float4*)&st[srow * 16 + scol];
            float4 v1 = *(float4*)&st[srow * 16 + scol + 4];
            float4 bb0 = *(const float4*)&bias[gc];
            float4 bb1 = *(const float4*)&bias[gc + 4];
            v0.x += bb0.x; v0.y += bb0.y; v0.z += bb0.z; v0.w += bb0.w;
            v1.x += bb1.x; v1.y += bb1.y; v1.z += bb1.z; v1.w += bb1.w;
            if (RES) {
                const float* rr = res + (size_t)gr * N + gc;
                float4 r0 = *(const float4*)&rr[0];
                float4 r1 = *(const float4*)&rr[4];
                v0.x += r0.x; v0.y += r0.y; v0.z += r0.z; v0.w += r0.w;
                v1.x += r1.x; v1.y += r1.y; v1.z += r1.z; v1.w += r1.w;
            }
            if (RELU) {
                v0.x = fmaxf(v0.x, 0.f); v0.y = fmaxf(v0.y, 0.f);
                v0.z = fmaxf(v0.z, 0.f); v0.w = fmaxf(v0.w, 0.f);
                v1.x = fmaxf(v1.x, 0.f); v1.y = fmaxf(v1.y, 0.f);
                v1.z = fmaxf(v1.z, 0.f); v1.w = fmaxf(v1.w, 0.f);
            }
            float* cr = C + (size_t)gr * N + gc;
            *(float4*)&cr[0] = v0;
            *(float4*)&cr[4] = v1;
        }
    }
}

// =============================================================================
// Scores: S[bh,qi,kj] = mask ? (Q_qi . K_kj)/8 : -1e9   (wmma TF32)
// Block tile 128(q) x 128(k), K-dim = 64 (one chunk). Dynamic smem.
// =============================================================================
__global__ __launch_bounds__(256) void scores_wmma(const float* __restrict__ q,
                                                   const float* __restrict__ k,
                                                   const int* __restrict__ mask,
                                                   float* __restrict__ scores)
{
    extern __shared__ float dsm[];
    float* Qs = dsm;                 // [128][64]
    float* Ks = dsm + 128 * 64;      // [128][64] (row = k-index, col = d)
    float* stageAll = dsm + 2 * 128 * 64; // 8*256

    const int bh = blockIdx.z;
    const int b = bh >> 4;
    const int h = bh & 15;
    const int q0 = blockIdx.y * 128;
    const int k0 = blockIdx.x * 128;
    const int tid = threadIdx.x;
    const int warpId = tid >> 5;
    const int lane = tid & 31;
    const int hbase = h * DK;

    // load Q,K tiles: 128 rows x 64 cols each
    {
        const int row = tid >> 4;          // 0..15 (+16 per it)
        const int col = (tid & 15) * 4;
        #pragma unroll
        for (int it = 0; it < 8; it++) {
            int r = row + it * 16;
            *(float4*)&Qs[r * 64 + col] =
                *(const float4*)&q[(size_t)(b * SEQ + q0 + r) * DMODEL + hbase + col];
            *(float4*)&Ks[r * 64 + col] =
                *(const float4*)&k[(size_t)(b * SEQ + k0 + r) * DMODEL + hbase + col];
        }
    }
    __syncthreads();

    const int warpRow = warpId & 1;
    const int warpCol = warpId >> 1;

    wmma::fragment<wmma::accumulator, 16, 16, 8, float> acc[4][2];
    #pragma unroll
    for (int i = 0; i < 4; i++)
        #pragma unroll
        for (int j = 0; j < 2; j++)
            wmma::fill_fragment(acc[i][j], 0.0f);

    #pragma unroll
    for (int kk = 0; kk < 8; kk++) {
        wmma::fragment<wmma::matrix_a, 16, 16, 8, wmma::precision::tf32, wmma::row_major> af[4];
        wmma::fragment<wmma::matrix_b, 16, 16, 8, wmma::precision::tf32, wmma::col_major> bf[2];
        #pragma unroll
        for (int i = 0; i < 4; i++) {
            wmma::load_matrix_sync(af[i], &Qs[(warpRow * 64 + i * 16) * 64 + kk * 8], 64);
            #pragma unroll
            for (int t = 0; t < af[i].num_elements; t++)
                af[i].x[t] = wmma::__float_to_tf32(af[i].x[t]);
        }
        #pragma unroll
        for (int j = 0; j < 2; j++) {
            // col_major: element (kd, n) at Ks[n*64 + kd]
            wmma::load_matrix_sync(bf[j], &Ks[(warpCol * 32 + j * 16) * 64 + kk * 8], 64);
            #pragma unroll
            for (int t = 0; t < bf[j].num_elements; t++)
                bf[j].x[t] = wmma::__float_to_tf32(bf[j].x[t]);
        }
        #pragma unroll
        for (int i = 0; i < 4; i++)
            #pragma unroll
            for (int j = 0; j < 2; j++)
                wmma::mma_sync(acc[i][j], af[i], bf[j], acc[i][j]);
    }

    float* st = &stageAll[warpId * 256];
    const int srow = lane >> 1;
    const int scol = (lane & 1) * 8;
    #pragma unroll
    for (int i = 0; i < 4; i++) {
        #pragma unroll
        for (int j = 0; j < 2; j++) {
            __syncwarp();
            wmma::store_matrix_sync(st, acc[i][j], 16, wmma::mem_row_major);
            __syncwarp();
            int qi = q0 + warpRow * 64 + i * 16 + srow;
            int kj = k0 + warpCol * 32 + j * 16 + scol;
            float4 v0 = *(float4*)&st[srow * 16 + scol];
            float4 v1 = *(float4*)&st[srow * 16 + scol + 4];
            const int* mp = &mask[(size_t)b * SEQ * SEQ + (size_t)qi * SEQ + kj];
            int4 m0 = *(const int4*)&mp[0];
            int4 m1 = *(const int4*)&mp[4];
            float4 o0, o1;
            o0.x = (m0.x == 0) ? -1e9f : v0.x * 0.125f;
            o0.y = (m0.y == 0) ? -1e9f : v0.y * 0.125f;
            o0.z = (m0.z == 0) ? -1e9f : v0.z * 0.125f;
            o0.w = (m0.w == 0) ? -1e9f : v0.w * 0.125f;
            o1.x = (m1.x == 0) ? -1e9f : v1.x * 0.125f;
            o1.y = (m1.y == 0) ? -1e9f : v1.y * 0.125f;
            o1.z = (m1.z == 0) ? -1e9f : v1.z * 0.125f;
            o1.w = (m1.w == 0) ? -1e9f : v1.w * 0.125f;
            float* sp = &scores[((size_t)bh * SEQ + qi) * SEQ + kj];
            *(float4*)&sp[0] = o0;
            *(float4*)&sp[4] = o1;
        }
    }
}

// ---------------- softmax over last dim (2048), in place ----------------
__global__ __launch_bounds__(256) void softmax_kernel(float* __restrict__ s)
{
    const size_t row = blockIdx.x;
    const int tid = threadIdx.x;
    float* sr = s + row * SEQ;

    float4 v0 = *(const float4*)&sr[tid * 4];
    float4 v1 = *(const float4*)&sr[1024 + tid * 4];

    float m = fmaxf(fmaxf(fmaxf(v0.x, v0.y), fmaxf(v0.z, v0.w)),
                    fmaxf(fmaxf(v1.x, v1.y), fmaxf(v1.z, v1.w)));
    for (int o = 16; o > 0; o >>= 1) m = fmaxf(m, __shfl_down_sync(0xffffffffu, m, o));
    __shared__ float wbuf[8];
    int lane = tid & 31, wid = tid >> 5;
    if (lane == 0) wbuf[wid] = m;
    __syncthreads();
    if (tid == 0) {
        float mm = wbuf[0];
        #pragma unroll
        for (int i = 1; i < 8; i++) mm = fmaxf(mm, wbuf[i]);
        wbuf[0] = mm;
    }
    __syncthreads();
    m = wbuf[0];
    __syncthreads();

    float e[8];
    e[0] = expf(v0.x - m); e[1] = expf(v0.y - m); e[2] = expf(v0.z - m); e[3] = expf(v0.w - m);
    e[4] = expf(v1.x - m); e[5] = expf(v1.y - m); e[6] = expf(v1.z - m); e[7] = expf(v1.w - m);
    float sum = 0.f;
    #pragma unroll
    for (int i = 0; i < 8; i++) sum += e[i];
    for (int o = 16; o > 0; o >>= 1) sum += __shfl_down_sync(0xffffffffu, sum, o);
    if (lane == 0) wbuf[wid] = sum;
    __syncthreads();
    if (tid == 0) {
        float ss = 0.f;
        #pragma unroll
        for (int i = 0; i < 8; i++) ss += wbuf[i];
        wbuf[0] = ss;
    }
    __syncthreads();
    float inv = 1.0f / wbuf[0];

    float4 o0, o1;
    o0.x = e[0] * inv; o0.y = e[1] * inv; o0.z = e[2] * inv; o0.w = e[3] * inv;
    o1.x = e[4] * inv; o1.y = e[5] * inv; o1.z = e[6] * inv; o1.w = e[7] * inv;
    *(float4*)&sr[tid * 4] = o0;
    *(float4*)&sr[1024 + tid * 4] = o1;
}

// =============================================================================
// Context: ctx[b,i,hbase+d] = sum_j P[bh,i,j] * V[b,j,hbase+d]   (wmma TF32)
// Block: 128 rows (i) x 64 cols (d), K over j in chunks of 32.
// 8 warps each 32x32 (2x2 tiles of 16x16).
// =============================================================================
#define LDP_S 36
#define LDV_S 68

__global__ __launch_bounds__(256) void ctx_wmma(const float* __restrict__ P,
                                                const float* __restrict__ v,
                                                float* __restrict__ ctx)
{
    __shared__ float Ps[128 * LDP_S];
    __shared__ float Vs[32 * LDV_S];
    __shared__ float stage[8 * 256];

    const int bh = blockIdx.y;
    const int b = bh >> 4, h = bh & 15;
    const int i0 = blockIdx.x * 128;
    const int tid = threadIdx.x;
    const int warpId = tid >> 5;
    const int lane = tid & 31;
    const int hbase = h * DK;

    const int warpRow = warpId & 3;    // 0..3 -> 32-row slab
    const int warpCol = warpId >> 2;   // 0..1 -> 32-col slab

    wmma::fragment<wmma::accumulator, 16, 16, 8, float> acc[2][2];
    #pragma unroll
    for (int i = 0; i < 2; i++)
        #pragma unroll
        for (int j = 0; j < 2; j++)
            wmma::fill_fragment(acc[i][j], 0.0f);

    const int pRow = tid >> 3;          // 0..31 (+32 per it)
    const int pCol = (tid & 7) * 4;
    const int vRow = tid >> 4;          // 0..15 (+16 per it)
    const int vCol = (tid & 15) * 4;

    // load chunk 0
    #pragma unroll
    for (int it = 0; it < 4; it++) {
        int r = pRow + it * 32;
        *(float4*)&Ps[r * LDP_S + pCol] =
            *(const float4*)&P[((size_t)bh * SEQ + i0 + r) * SEQ + pCol];
    }
    #pragma unroll
    for (int it = 0; it < 2; it++) {
        int r = vRow + it * 16;
        *(float4*)&Vs[r * LDV_S + vCol] =
            *(const float4*)&v[(size_t)(b * SEQ + r) * DMODEL + hbase + vCol];
    }
    __syncthreads();

    float4 rp[4], rv[2];
    const int nChunks = SEQ / 32;
    for (int c = 0; c < nChunks; c++) {
        if (c + 1 < nChunks) {
            int j0 = (c + 1) * 32;
            #pragma unroll
            for (int it = 0; it < 4; it++) {
                int r = pRow + it * 32;
                rp[it] = *(const float4*)&P[((size_t)bh * SEQ + i0 + r) * SEQ + j0 + pCol];
            }
            #pragma unroll
            for (int it = 0; it < 2; it++) {
                int r = vRow + it * 16;
                rv[it] = *(const float4*)&v[(size_t)(b * SEQ + j0 + r) * DMODEL + hbase + vCol];
            }
        }
        #pragma unroll
        for (int kk = 0; kk < 4; kk++) {
            wmma::fragment<wmma::matrix_a, 16, 16, 8, wmma::precision::tf32, wmma::row_major> af[2];
            wmma::fragment<wmma::matrix_b, 16, 16, 8, wmma::precision::tf32, wmma::row_major> bf[2];
            #pragma unroll
            for (int i = 0; i < 2; i++) {
                wmma::load_matrix_sync(af[i], &Ps[(warpRow * 32 + i * 16) * LDP_S + kk * 8], LDP_S);
                #pragma unroll
                for (int t = 0; t < af[i].num_elements; t++)
                    af[i].x[t] = wmma::__float_to_tf32(af[i].x[t]);
            }
            #pragma unroll
            for (int j = 0; j < 2; j++) {
                wmma::load_matrix_sync(bf[j], &Vs[(kk * 8) * LDV_S + warpCol * 32 + j * 16], LDV_S);
                #pragma unroll
                for (int t = 0; t < bf[j].num_elements; t++)
                    bf[j].x[t] = wmma::__float_to_tf32(bf[j].x[t]);
            }
            #pragma unroll
            for (int i = 0; i < 2; i++)
                #pragma unroll
                for (int j = 0; j < 2; j++)
                    wmma::mma_sync(acc[i][j], af[i], bf[j], acc[i][j]);
        }
        if (c + 1 < nChunks) {
            __syncthreads();
            #pragma unroll
            for (int it = 0; it < 4; it++) {
                int r = pRow + it * 32;
                *(float4*)&Ps[r * LDP_S + pCol] = rp[it];
            }
            #pragma unroll
            for (int it = 0; it < 2; it++) {
                int r = vRow + it * 16;
                *(float4*)&Vs[r * LDV_S + vCol] = rv[it];
            }
            __syncthreads();
        }
    }

    float* st = &stage[warpId * 256];
    const int srow = lane >> 1;
    const int scol = (lane & 1) * 8;
    #pragma unroll
    for (int i = 0; i < 2; i++) {
        #pragma unroll
        for (int j = 0; j < 2; j++) {
            __syncwarp();
            wmma::store_matrix_sync(st, acc[i][j], 16, wmma::mem_row_major);
            __syncwarp();
            int gr = b * SEQ + i0 + warpRow * 32 + i * 16 + srow;
            int gc = hbase + warpCol * 32 + j * 16 + scol;
            float4 v0 = *(float4*)&st[srow * 16 + scol];
            float4 v1 = *(float4*)&st[srow * 16 + scol + 4];
            float* cp = &ctx[(size_t)gr * DMODEL + gc];
            *(float4*)&cp[0] = v0;
            *(float4*)&cp[4] = v1;
        }
    }
}

// ---------------- launch ----------------
extern "C" void kernel_launch(void* const* d_in, const int* in_sizes, int n_in,
                              void* d_out, int out_size)
{
    const float* x    = (const float*)d_in[0];
    const int*   mask = (const int*)  d_in[1];
    const float* wq = (const float*)d_in[2];  const float* bq = (const float*)d_in[3];
    const float* wk = (const float*)d_in[4];  const float* bk = (const float*)d_in[5];
    const float* wv = (const float*)d_in[6];  const float* bv = (const float*)d_in[7];
    const float* wo = (const float*)d_in[8];  const float* bo = (const float*)d_in[9];
    const float* w1 = (const float*)d_in[10]; const float* b1 = (const float*)d_in[11];
    const float* w2 = (const float*)d_in[12]; const float* b2 = (const float*)d_in[13];
    const float* ln1_a = (const float*)d_in[14]; const float* ln1_b = (const float*)d_in[15];
    const float* ln2_a = (const float*)d_in[16]; const float* ln2_b = (const float*)d_in[17];
    float* out = (float*)d_out;

    float *p_h, *p_q, *p_k, *p_v, *p_ctx, *p_x1, *p_h2, *p_ff, *p_sc;
    cudaGetSymbolAddress((void**)&p_h,  g_h);
    cudaGetSymbolAddress((void**)&p_q,  g_q);
    cudaGetSymbolAddress((void**)&p_k,  g_k);
    cudaGetSymbolAddress((void**)&p_v,  g_v);
    cudaGetSymbolAddress((void**)&p_ctx,g_ctx);
    cudaGetSymbolAddress((void**)&p_x1, g_x1);
    cudaGetSymbolAddress((void**)&p_h2, g_h2);
    cudaGetSymbolAddress((void**)&p_ff, g_ff);
    cudaGetSymbolAddress((void**)&p_sc, g_scores);

    // dynamic smem for scores kernel: 2*(128*64) + 8*256 floats
    const int SC_SMEM = (2 * 128 * 64 + 8 * 256) * (int)sizeof(float);
    cudaFuncSetAttribute(scores_wmma, cudaFuncAttributeMaxDynamicSharedMemorySize, SC_SMEM);

    // 1) LN1
    ln_kernel<<<MTOK, 256>>>(x, p_h, ln1_a, ln1_b);

    // 2) Q,K,V projections  (M=4096, N=1024, K=1024)
    dim3 gProj(DMODEL / 128, MTOK / 128);
    gemm_tf32<0,0><<<gProj, 256>>>(p_h, wq, bq, nullptr, p_q, DMODEL, DMODEL);
    gemm_tf32<0,0><<<gProj, 256>>>(p_h, wk, bk, nullptr, p_k, DMODEL, DMODEL);
    gemm_tf32<0,0><<<gProj, 256>>>(p_h, wv, bv, nullptr, p_v, DMODEL, DMODEL);

    // 3) scores + softmax + ctx
    scores_wmma<<<dim3(SEQ / 128, SEQ / 128, BATCH * NHEADS), 256, SC_SMEM>>>(p_q, p_k, mask, p_sc);
    softmax_kernel<<<BATCH * NHEADS * SEQ, 256>>>(p_sc);
    ctx_wmma<<<dim3(SEQ / 128, BATCH * NHEADS), 256>>>(p_sc, p_v, p_ctx);

    // 4) O projection + residual -> x1
    gemm_tf32<0,1><<<gProj, 256>>>(p_ctx, wo, bo, x, p_x1, DMODEL, DMODEL);

    // 5) LN2
    ln_kernel<<<MTOK, 256>>>(p_x1, p_h2, ln2_a, ln2_b);

    // 6) FFN1 + ReLU  (M=4096, N=4096, K=1024)
    gemm_tf32<1,0><<<dim3(DFF / 128, MTOK / 128), 256>>>(p_h2, w1, b1, nullptr, p_ff, DMODEL, DFF);

    // 7) FFN2 + residual -> out  (M=4096, N=1024, K=4096)
    gemm_tf32<0,1><<<gProj, 256>>>(p_ff, w2, b2, p_x1, out, DFF, DMODEL);
}

// round 6
// speedup vs baseline: 1.7552x; 1.4514x over previous
#include <cuda_runtime.h>
#include <cuda_bf16.h>
#include <math.h>
#include <mma.h>
#include <cstdint>

using namespace nvcuda;

// Problem constants
#define BATCH 2
#define SEQ   2048
#define DMODEL 1024
#define NHEADS 16
#define DK    64
#define DFF   4096
#define MTOK  (BATCH*SEQ)
#define LNEPS 1e-6f

// ---------------- static device scratch ----------------
__device__ float g_h  [MTOK*DMODEL];
__device__ float g_q  [MTOK*DMODEL];
__device__ float g_k  [MTOK*DMODEL];
__device__ float g_v  [MTOK*DMODEL];
__device__ float g_ctx[MTOK*DMODEL];
__device__ float g_x1 [MTOK*DMODEL];
__device__ float g_h2 [MTOK*DMODEL];
__device__ float g_ff [MTOK*DFF];
__device__ float g_scores[(size_t)BATCH*NHEADS*SEQ*SEQ];

// tf32 conversion: destination must be .b32 register
__device__ __forceinline__ float to_tf32(float x) {
    uint32_t r;
    asm("cvt.rna.tf32.f32 %0, %1;" : "=r"(r) : "f"(x));
    return __uint_as_float(r);
}

// raw tf32 mma: A/B operands are .b32 regs, C/D are .f32
__device__ __forceinline__ void mma16n8k8(float* d, const uint32_t* a, const uint32_t* b, const float* c) {
    asm volatile(
        "mma.sync.aligned.m16n8k8.row.col.f32.tf32.tf32.f32 "
        "{%0,%1,%2,%3}, {%4,%5,%6,%7}, {%8,%9}, {%10,%11,%12,%13};"
        : "=f"(d[0]), "=f"(d[1]), "=f"(d[2]), "=f"(d[3])
        : "r"(a[0]), "r"(a[1]), "r"(a[2]), "r"(a[3]),
          "r"(b[0]), "r"(b[1]),
          "f"(c[0]), "f"(c[1]), "f"(c[2]), "f"(c[3]));
}

// ---------------- LayerNorm ----------------
__global__ __launch_bounds__(256) void ln_kernel(const float* __restrict__ x,
                                                 float* __restrict__ out,
                                                 const float* __restrict__ alpha,
                                                 const float* __restrict__ beta)
{
    const int row = blockIdx.x;
    const int tid = threadIdx.x;
    const float* xr = x + (size_t)row * DMODEL;
    float4 v = *(const float4*)&xr[tid * 4];

    float s1 = v.x + v.y + v.z + v.w;
    float s2 = v.x*v.x + v.y*v.y + v.z*v.z + v.w*v.w;
    for (int o = 16; o > 0; o >>= 1) {
        s1 += __shfl_down_sync(0xffffffffu, s1, o);
        s2 += __shfl_down_sync(0xffffffffu, s2, o);
    }
    __shared__ float ws1[8], ws2[8];
    int lane = tid & 31, wid = tid >> 5;
    if (lane == 0) { ws1[wid] = s1; ws2[wid] = s2; }
    __syncthreads();
    if (tid == 0) {
        float a = 0.f, b = 0.f;
        #pragma unroll
        for (int i = 0; i < 8; i++) { a += ws1[i]; b += ws2[i]; }
        ws1[0] = a; ws2[0] = b;
    }
    __syncthreads();
    float sum = ws1[0], sumsq = ws2[0];
    float mean = sum * (1.0f / DMODEL);
    float var  = (sumsq - (float)DMODEL * mean * mean) * (1.0f / (DMODEL - 1));
    var = fmaxf(var, 0.0f);
    float stdv = sqrtf(var);
    float inv = alpha[0] / (stdv + LNEPS);
    float b_ = beta[0];
    float4 o4;
    o4.x = (v.x - mean) * inv + b_;
    o4.y = (v.y - mean) * inv + b_;
    o4.z = (v.z - mean) * inv + b_;
    o4.w = (v.w - mean) * inv + b_;
    *(float4*)&out[(size_t)row * DMODEL + tid * 4] = o4;
}

// =============================================================================
// Raw-mma TF32 GEMM: C[M,N] = A[M,K]*B[K,N] + bias (+res) (relu)
// Tile 128x128, BK=32, 8 warps (2x4), warp tile 64x32 (4 m-tiles x 4 n-tiles).
// Operands converted to tf32 at staging; no CVT in inner loop.
// =============================================================================
#define LDA_S 36   // A smem row stride (floats)
#define LDB_S 132  // B smem row stride (floats)
#define GEMM_SMEM ((2*128*LDA_S + 2*32*LDB_S) * 4)

template<int RELU, int RES>
__global__ __launch_bounds__(256) void gemm_mma(const float* __restrict__ A,
                                                const float* __restrict__ Bm,
                                                const float* __restrict__ bias,
                                                const float* __restrict__ res,
                                                float* __restrict__ C,
                                                int K, int N)
{
    extern __shared__ float sm[];
    float* As = sm;                       // [2][128][LDA_S]
    float* Bs = sm + 2 * 128 * LDA_S;     // [2][32][LDB_S]

    const int tid = threadIdx.x;
    const int warpId = tid >> 5;
    const int lane = tid & 31;
    const int g = lane >> 2;      // 0..7
    const int t4 = lane & 3;      // 0..3
    const int row0 = blockIdx.y * 128;
    const int col0 = blockIdx.x * 128;
    const int wr = warpId & 1;    // 0..1 -> 64-row slab
    const int wc = warpId >> 1;   // 0..3 -> 32-col slab

    float acc[4][4][4];
    #pragma unroll
    for (int i = 0; i < 4; i++)
        #pragma unroll
        for (int j = 0; j < 4; j++)
            #pragma unroll
            for (int r = 0; r < 4; r++) acc[i][j][r] = 0.f;

    // staging indices
    const int aRow = tid >> 1;            // 0..127
    const int aColB = (tid & 1) * 16;     // 0 or 16
    const int bK = tid >> 3;              // 0..31
    const int bN = (tid & 7) * 4;         // 0..28

    const int nChunks = K / 32;

    // ---- stage chunk 0 ----
    {
        const float* asrc = A + (size_t)(row0 + aRow) * K + aColB;
        #pragma unroll
        for (int i = 0; i < 4; i++) {
            float4 v = *(const float4*)(asrc + i * 4);
            float* d = &As[aRow * LDA_S + aColB + i * 4];
            d[0] = to_tf32(v.x); d[1] = to_tf32(v.y); d[2] = to_tf32(v.z); d[3] = to_tf32(v.w);
        }
        const float* bsrc = Bm + (size_t)bK * N + col0 + bN;
        #pragma unroll
        for (int i = 0; i < 4; i++) {
            float4 v = *(const float4*)(bsrc + i * 32);
            float* d = &Bs[bK * LDB_S + bN + i * 32];
            d[0] = to_tf32(v.x); d[1] = to_tf32(v.y); d[2] = to_tf32(v.z); d[3] = to_tf32(v.w);
        }
    }
    __syncthreads();

    float4 ra[4], rb[4];
    for (int c = 0; c < nChunks; c++) {
        const int buf = c & 1;
        const uint32_t* Ab = (const uint32_t*)(As + buf * 128 * LDA_S);
        const uint32_t* Bb = (const uint32_t*)(Bs + buf * 32 * LDB_S);

        if (c + 1 < nChunks) {
            const int k0 = (c + 1) * 32;
            const float* asrc = A + (size_t)(row0 + aRow) * K + k0 + aColB;
            #pragma unroll
            for (int i = 0; i < 4; i++) ra[i] = *(const float4*)(asrc + i * 4);
            const float* bsrc = Bm + (size_t)(k0 + bK) * N + col0 + bN;
            #pragma unroll
            for (int i = 0; i < 4; i++) rb[i] = *(const float4*)(bsrc + i * 32);
        }

        // compute 4 K8 steps
        #pragma unroll
        for (int s = 0; s < 4; s++) {
            const int kb = s * 8;
            uint32_t af[4][4];
            uint32_t bf[4][2];
            #pragma unroll
            for (int mi = 0; mi < 4; mi++) {
                const int r = wr * 64 + mi * 16 + g;
                af[mi][0] = Ab[r * LDA_S + kb + t4];
                af[mi][1] = Ab[(r + 8) * LDA_S + kb + t4];
                af[mi][2] = Ab[r * LDA_S + kb + t4 + 4];
                af[mi][3] = Ab[(r + 8) * LDA_S + kb + t4 + 4];
            }
            #pragma unroll
            for (int ni = 0; ni < 4; ni++) {
                const int n = wc * 32 + ni * 8 + g;
                bf[ni][0] = Bb[(kb + t4) * LDB_S + n];
                bf[ni][1] = Bb[(kb + t4 + 4) * LDB_S + n];
            }
            #pragma unroll
            for (int mi = 0; mi < 4; mi++)
                #pragma unroll
                for (int ni = 0; ni < 4; ni++)
                    mma16n8k8(acc[mi][ni], af[mi], bf[ni], acc[mi][ni]);
        }

        if (c + 1 < nChunks) {
            __syncthreads();
            const int nb = (c + 1) & 1;
            float* Ad = As + nb * 128 * LDA_S;
            float* Bd = Bs + nb * 32 * LDB_S;
            #pragma unroll
            for (int i = 0; i < 4; i++) {
                float* d = &Ad[aRow * LDA_S + aColB + i * 4];
                d[0] = to_tf32(ra[i].x); d[1] = to_tf32(ra[i].y);
                d[2] = to_tf32(ra[i].z); d[3] = to_tf32(ra[i].w);
            }
            #pragma unroll
            for (int i = 0; i < 4; i++) {
                float* d = &Bd[bK * LDB_S + bN + i * 32];
                d[0] = to_tf32(rb[i].x); d[1] = to_tf32(rb[i].y);
                d[2] = to_tf32(rb[i].z); d[3] = to_tf32(rb[i].w);
            }
            __syncthreads();
        }
    }

    // ---- epilogue: direct global writes (float2 per tile-row) ----
    #pragma unroll
    for (int mi = 0; mi < 4; mi++) {
        #pragma unroll
        for (int half = 0; half < 2; half++) {
            const int gr = row0 + wr * 64 + mi * 16 + g + half * 8;
            float* crow = C + (size_t)gr * N;
            const float* rrow = RES ? (res + (size_t)gr * N) : nullptr;
            #pragma unroll
            for (int ni = 0; ni < 4; ni++) {
                const int gc = col0 + wc * 32 + ni * 8 + t4 * 2;
                float2 o;
                o.x = acc[mi][ni][half * 2 + 0];
                o.y = acc[mi][ni][half * 2 + 1];
                float2 bb = *(const float2*)&bias[gc];
                o.x += bb.x; o.y += bb.y;
                if (RES) {
                    float2 rr = *(const float2*)&rrow[gc];
                    o.x += rr.x; o.y += rr.y;
                }
                if (RELU) {
                    o.x = fmaxf(o.x, 0.f);
                    o.y = fmaxf(o.y, 0.f);
                }
                *(float2*)&crow[gc] = o;
            }
        }
    }
}

// =============================================================================
// Scores (wmma TF32, staged-cvt): S = mask ? QK^T/8 : -1e9
// =============================================================================
__global__ __launch_bounds__(256) void scores_wmma(const float* __restrict__ q,
                                                   const float* __restrict__ k,
                                                   const int* __restrict__ mask,
                                                   float* __restrict__ scores)
{
    extern __shared__ float dsm[];
    float* Qs = dsm;
    float* Ks = dsm + 128 * 64;
    float* stageAll = dsm + 2 * 128 * 64;

    const int bh = blockIdx.z;
    const int b = bh >> 4;
    const int h = bh & 15;
    const int q0 = blockIdx.y * 128;
    const int k0 = blockIdx.x * 128;
    const int tid = threadIdx.x;
    const int warpId = tid >> 5;
    const int lane = tid & 31;
    const int hbase = h * DK;

    {
        const int row = tid >> 4;
        const int col = (tid & 15) * 4;
        #pragma unroll
        for (int it = 0; it < 8; it++) {
            int r = row + it * 16;
            float4 qv = *(const float4*)&q[(size_t)(b * SEQ + q0 + r) * DMODEL + hbase + col];
            float4 kv = *(const float4*)&k[(size_t)(b * SEQ + k0 + r) * DMODEL + hbase + col];
            float* qd = &Qs[r * 64 + col];
            float* kd = &Ks[r * 64 + col];
            qd[0] = to_tf32(qv.x); qd[1] = to_tf32(qv.y); qd[2] = to_tf32(qv.z); qd[3] = to_tf32(qv.w);
            kd[0] = to_tf32(kv.x); kd[1] = to_tf32(kv.y); kd[2] = to_tf32(kv.z); kd[3] = to_tf32(kv.w);
        }
    }
    __syncthreads();

    const int warpRow = warpId & 1;
    const int warpCol = warpId >> 1;

    wmma::fragment<wmma::accumulator, 16, 16, 8, float> acc[4][2];
    #pragma unroll
    for (int i = 0; i < 4; i++)
        #pragma unroll
        for (int j = 0; j < 2; j++)
            wmma::fill_fragment(acc[i][j], 0.0f);

    #pragma unroll
    for (int kk = 0; kk < 8; kk++) {
        wmma::fragment<wmma::matrix_a, 16, 16, 8, wmma::precision::tf32, wmma::row_major> af[4];
        wmma::fragment<wmma::matrix_b, 16, 16, 8, wmma::precision::tf32, wmma::col_major> bf[2];
        #pragma unroll
        for (int i = 0; i < 4; i++)
            wmma::load_matrix_sync(af[i], &Qs[(warpRow * 64 + i * 16) * 64 + kk * 8], 64);
        #pragma unroll
        for (int j = 0; j < 2; j++)
            wmma::load_matrix_sync(bf[j], &Ks[(warpCol * 32 + j * 16) * 64 + kk * 8], 64);
        #pragma unroll
        for (int i = 0; i < 4; i++)
            #pragma unroll
            for (int j = 0; j < 2; j++)
                wmma::mma_sync(acc[i][j], af[i], bf[j], acc[i][j]);
    }

    float* st = &stageAll[warpId * 256];
    const int srow = lane >> 1;
    const int scol = (lane & 1) * 8;
    #pragma unroll
    for (int i = 0; i < 4; i++) {
        #pragma unroll
        for (int j = 0; j < 2; j++) {
            __syncwarp();
            wmma::store_matrix_sync(st, acc[i][j], 16, wmma::mem_row_major);
            __syncwarp();
            int qi = q0 + warpRow * 64 + i * 16 + srow;
            int kj = k0 + warpCol * 32 + j * 16 + scol;
            float4 v0 = *(float4*)&st[srow * 16 + scol];
            float4 v1 = *(float4*)&st[srow * 16 + scol + 4];
            const int* mp = &mask[(size_t)b * SEQ * SEQ + (size_t)qi * SEQ + kj];
            int4 m0 = *(const int4*)&mp[0];
            int4 m1 = *(const int4*)&mp[4];
            float4 o0, o1;
            o0.x = (m0.x == 0) ? -1e9f : v0.x * 0.125f;
            o0.y = (m0.y == 0) ? -1e9f : v0.y * 0.125f;
            o0.z = (m0.z == 0) ? -1e9f : v0.z * 0.125f;
            o0.w = (m0.w == 0) ? -1e9f : v0.w * 0.125f;
            o1.x = (m1.x == 0) ? -1e9f : v1.x * 0.125f;
            o1.y = (m1.y == 0) ? -1e9f : v1.y * 0.125f;
            o1.z = (m1.z == 0) ? -1e9f : v1.z * 0.125f;
            o1.w = (m1.w == 0) ? -1e9f : v1.w * 0.125f;
            float* sp = &scores[((size_t)bh * SEQ + qi) * SEQ + kj];
            *(float4*)&sp[0] = o0;
            *(float4*)&sp[4] = o1;
        }
    }
}

// ---------------- softmax (2048), in place ----------------
__global__ __launch_bounds__(256) void softmax_kernel(float* __restrict__ s)
{
    const size_t row = blockIdx.x;
    const int tid = threadIdx.x;
    float* sr = s + row * SEQ;

    float4 v0 = *(const float4*)&sr[tid * 4];
    float4 v1 = *(const float4*)&sr[1024 + tid * 4];

    float m = fmaxf(fmaxf(fmaxf(v0.x, v0.y), fmaxf(v0.z, v0.w)),
                    fmaxf(fmaxf(v1.x, v1.y), fmaxf(v1.z, v1.w)));
    for (int o = 16; o > 0; o >>= 1) m = fmaxf(m, __shfl_down_sync(0xffffffffu, m, o));
    __shared__ float wbuf[8];
    int lane = tid & 31, wid = tid >> 5;
    if (lane == 0) wbuf[wid] = m;
    __syncthreads();
    if (tid == 0) {
        float mm = wbuf[0];
        #pragma unroll
        for (int i = 1; i < 8; i++) mm = fmaxf(mm, wbuf[i]);
        wbuf[0] = mm;
    }
    __syncthreads();
    m = wbuf[0];
    __syncthreads();

    float e[8];
    e[0] = expf(v0.x - m); e[1] = expf(v0.y - m); e[2] = expf(v0.z - m); e[3] = expf(v0.w - m);
    e[4] = expf(v1.x - m); e[5] = expf(v1.y - m); e[6] = expf(v1.z - m); e[7] = expf(v1.w - m);
    float sum = 0.f;
    #pragma unroll
    for (int i = 0; i < 8; i++) sum += e[i];
    for (int o = 16; o > 0; o >>= 1) sum += __shfl_down_sync(0xffffffffu, sum, o);
    if (lane == 0) wbuf[wid] = sum;
    __syncthreads();
    if (tid == 0) {
        float ss = 0.f;
        #pragma unroll
        for (int i = 0; i < 8; i++) ss += wbuf[i];
        wbuf[0] = ss;
    }
    __syncthreads();
    float inv = 1.0f / wbuf[0];

    float4 o0, o1;
    o0.x = e[0] * inv; o0.y = e[1] * inv; o0.z = e[2] * inv; o0.w = e[3] * inv;
    o1.x = e[4] * inv; o1.y = e[5] * inv; o1.z = e[6] * inv; o1.w = e[7] * inv;
    *(float4*)&sr[tid * 4] = o0;
    *(float4*)&sr[1024 + tid * 4] = o1;
}

// =============================================================================
// Context (wmma TF32, staged-cvt): ctx = P @ V  per head
// =============================================================================
#define LDP_S 36
#define LDV_S 68

__global__ __launch_bounds__(256) void ctx_wmma(const float* __restrict__ P,
                                                const float* __restrict__ v,
                                                float* __restrict__ ctx)
{
    __shared__ float Ps[128 * LDP_S];
    __shared__ float Vs[32 * LDV_S];
    __shared__ float stage[8 * 256];

    const int bh = blockIdx.y;
    const int b = bh >> 4, h = bh & 15;
    const int i0 = blockIdx.x * 128;
    const int tid = threadIdx.x;
    const int warpId = tid >> 5;
    const int lane = tid & 31;
    const int hbase = h * DK;

    const int warpRow = warpId & 3;
    const int warpCol = warpId >> 2;

    wmma::fragment<wmma::accumulator, 16, 16, 8, float> acc[2][2];
    #pragma unroll
    for (int i = 0; i < 2; i++)
        #pragma unroll
        for (int j = 0; j < 2; j++)
            wmma::fill_fragment(acc[i][j], 0.0f);

    const int pRow = tid >> 3;
    const int pCol = (tid & 7) * 4;
    const int vRow = tid >> 4;
    const int vCol = (tid & 15) * 4;

    #pragma unroll
    for (int it = 0; it < 4; it++) {
        int r = pRow + it * 32;
        float4 pv = *(const float4*)&P[((size_t)bh * SEQ + i0 + r) * SEQ + pCol];
        float* d = &Ps[r * LDP_S + pCol];
        d[0] = to_tf32(pv.x); d[1] = to_tf32(pv.y); d[2] = to_tf32(pv.z); d[3] = to_tf32(pv.w);
    }
    #pragma unroll
    for (int it = 0; it < 2; it++) {
        int r = vRow + it * 16;
        float4 vv = *(const float4*)&v[(size_t)(b * SEQ + r) * DMODEL + hbase + vCol];
        float* d = &Vs[r * LDV_S + vCol];
        d[0] = to_tf32(vv.x); d[1] = to_tf32(vv.y); d[2] = to_tf32(vv.z); d[3] = to_tf32(vv.w);
    }
    __syncthreads();

    float4 rp[4], rv[2];
    const int nChunks = SEQ / 32;
    for (int c = 0; c < nChunks; c++) {
        if (c + 1 < nChunks) {
            int j0 = (c + 1) * 32;
            #pragma unroll
            for (int it = 0; it < 4; it++) {
                int r = pRow + it * 32;
                rp[it] = *(const float4*)&P[((size_t)bh * SEQ + i0 + r) * SEQ + j0 + pCol];
            }
            #pragma unroll
            for (int it = 0; it < 2; it++) {
                int r = vRow + it * 16;
                rv[it] = *(const float4*)&v[(size_t)(b * SEQ + j0 + r) * DMODEL + hbase + vCol];
            }
        }
        #pragma unroll
        for (int kk = 0; kk < 4; kk++) {
            wmma::fragment<wmma::matrix_a, 16, 16, 8, wmma::precision::tf32, wmma::row_major> af[2];
            wmma::fragment<wmma::matrix_b, 16, 16, 8, wmma::precision::tf32, wmma::row_major> bf[2];
            #pragma unroll
            for (int i = 0; i < 2; i++)
                wmma::load_matrix_sync(af[i], &Ps[(warpRow * 32 + i * 16) * LDP_S + kk * 8], LDP_S);
            #pragma unroll
            for (int j = 0; j < 2; j++)
                wmma::load_matrix_sync(bf[j], &Vs[(kk * 8) * LDV_S + warpCol * 32 + j * 16], LDV_S);
            #pragma unroll
            for (int i = 0; i < 2; i++)
                #pragma unroll
                for (int j = 0; j < 2; j++)
                    wmma::mma_sync(acc[i][j], af[i], bf[j], acc[i][j]);
        }
        if (c + 1 < nChunks) {
            __syncthreads();
            #pragma unroll
            for (int it = 0; it < 4; it++) {
                int r = pRow + it * 32;
                float* d = &Ps[r * LDP_S + pCol];
                d[0] = to_tf32(rp[it].x); d[1] = to_tf32(rp[it].y);
                d[2] = to_tf32(rp[it].z); d[3] = to_tf32(rp[it].w);
            }
            #pragma unroll
            for (int it = 0; it < 2; it++) {
                int r = vRow + it * 16;
                float* d = &Vs[r * LDV_S + vCol];
                d[0] = to_tf32(rv[it].x); d[1] = to_tf32(rv[it].y);
                d[2] = to_tf32(rv[it].z); d[3] = to_tf32(rv[it].w);
            }
            __syncthreads();
        }
    }

    float* st = &stage[warpId * 256];
    const int srow = lane >> 1;
    const int scol = (lane & 1) * 8;
    #pragma unroll
    for (int i = 0; i < 2; i++) {
        #pragma unroll
        for (int j = 0; j < 2; j++) {
            __syncwarp();
            wmma::store_matrix_sync(st, acc[i][j], 16, wmma::mem_row_major);
            __syncwarp();
            int gr = b * SEQ + i0 + warpRow * 32 + i * 16 + srow;
            int gc = hbase + warpCol * 32 + j * 16 + scol;
            float4 v0 = *(float4*)&st[srow * 16 + scol];
            float4 v1 = *(float4*)&st[srow * 16 + scol + 4];
            float* cp = &ctx[(size_t)gr * DMODEL + gc];
            *(float4*)&cp[0] = v0;
            *(float4*)&cp[4] = v1;
        }
    }
}

// ---------------- launch ----------------
extern "C" void kernel_launch(void* const* d_in, const int* in_sizes, int n_in,
                              void* d_out, int out_size)
{
    const float* x    = (const float*)d_in[0];
    const int*   mask = (const int*)  d_in[1];
    const float* wq = (const float*)d_in[2];  const float* bq = (const float*)d_in[3];
    const float* wk = (const float*)d_in[4];  const float* bk = (const float*)d_in[5];
    const float* wv = (const float*)d_in[6];  const float* bv = (const float*)d_in[7];
    const float* wo = (const float*)d_in[8];  const float* bo = (const float*)d_in[9];
    const float* w1 = (const float*)d_in[10]; const float* b1 = (const float*)d_in[11];
    const float* w2 = (const float*)d_in[12]; const float* b2 = (const float*)d_in[13];
    const float* ln1_a = (const float*)d_in[14]; const float* ln1_b = (const float*)d_in[15];
    const float* ln2_a = (const float*)d_in[16]; const float* ln2_b = (const float*)d_in[17];
    float* out = (float*)d_out;

    float *p_h, *p_q, *p_k, *p_v, *p_ctx, *p_x1, *p_h2, *p_ff, *p_sc;
    cudaGetSymbolAddress((void**)&p_h,  g_h);
    cudaGetSymbolAddress((void**)&p_q,  g_q);
    cudaGetSymbolAddress((void**)&p_k,  g_k);
    cudaGetSymbolAddress((void**)&p_v,  g_v);
    cudaGetSymbolAddress((void**)&p_ctx,g_ctx);
    cudaGetSymbolAddress((void**)&p_x1, g_x1);
    cudaGetSymbolAddress((void**)&p_h2, g_h2);
    cudaGetSymbolAddress((void**)&p_ff, g_ff);
    cudaGetSymbolAddress((void**)&p_sc, g_scores);

    const int SC_SMEM = (2 * 128 * 64 + 8 * 256) * (int)sizeof(float);
    cudaFuncSetAttribute(scores_wmma, cudaFuncAttributeMaxDynamicSharedMemorySize, SC_SMEM);
    cudaFuncSetAttribute(gemm_mma<0,0>, cudaFuncAttributeMaxDynamicSharedMemorySize, GEMM_SMEM);
    cudaFuncSetAttribute(gemm_mma<0,1>, cudaFuncAttributeMaxDynamicSharedMemorySize, GEMM_SMEM);
    cudaFuncSetAttribute(gemm_mma<1,0>, cudaFuncAttributeMaxDynamicSharedMemorySize, GEMM_SMEM);

    // 1) LN1
    ln_kernel<<<MTOK, 256>>>(x, p_h, ln1_a, ln1_b);

    // 2) QKV projections
    dim3 gProj(DMODEL / 128, MTOK / 128);
    gemm_mma<0,0><<<gProj, 256, GEMM_SMEM>>>(p_h, wq, bq, nullptr, p_q, DMODEL, DMODEL);
    gemm_mma<0,0><<<gProj, 256, GEMM_SMEM>>>(p_h, wk, bk, nullptr, p_k, DMODEL, DMODEL);
    gemm_mma<0,0><<<gProj, 256, GEMM_SMEM>>>(p_h, wv, bv, nullptr, p_v, DMODEL, DMODEL);

    // 3) attention
    scores_wmma<<<dim3(SEQ / 128, SEQ / 128, BATCH * NHEADS), 256, SC_SMEM>>>(p_q, p_k, mask, p_sc);
    softmax_kernel<<<BATCH * NHEADS * SEQ, 256>>>(p_sc);
    ctx_wmma<<<dim3(SEQ / 128, BATCH * NHEADS), 256>>>(p_sc, p_v, p_ctx);

    // 4) O projection + residual
    gemm_mma<0,1><<<gProj, 256, GEMM_SMEM>>>(p_ctx, wo, bo, x, p_x1, DMODEL, DMODEL);

    // 5) LN2
    ln_kernel<<<MTOK, 256>>>(p_x1, p_h2, ln2_a, ln2_b);

    // 6) FFN1 + ReLU
    gemm_mma<1,0><<<dim3(DFF / 128, MTOK / 128), 256, GEMM_SMEM>>>(p_h2, w1, b1, nullptr, p_ff, DMODEL, DFF);

    // 7) FFN2 + residual -> out
    gemm_mma<0,1><<<gProj, 256, GEMM_SMEM>>>(p_ff, w2, b2, p_x1, out, DFF, DMODEL);
}

// round 8
// speedup vs baseline: 2.7131x; 1.5458x over previous
#include <cuda_runtime.h>
#include <cuda_bf16.h>
#include <math.h>
#include <cstdint>

// Problem constants
#define BATCH 2
#define SEQ   2048
#define DMODEL 1024
#define NHEADS 16
#define DK    64
#define DFF   4096
#define MTOK  (BATCH*SEQ)
#define LNEPS 1e-6f

// ---------------- static device scratch ----------------
__device__ float g_h  [MTOK*DMODEL];
__device__ float g_q  [MTOK*DMODEL];
__device__ float g_k  [MTOK*DMODEL];
__device__ float g_v  [MTOK*DMODEL];
__device__ float g_ctx[MTOK*DMODEL];
__device__ float g_x1 [MTOK*DMODEL];
__device__ float g_h2 [MTOK*DMODEL];
__device__ float g_ff [MTOK*DFF];

// tf32 conversion: destination must be .b32 register
__device__ __forceinline__ float to_tf32(float x) {
    uint32_t r;
    asm("cvt.rna.tf32.f32 %0, %1;" : "=r"(r) : "f"(x));
    return __uint_as_float(r);
}

// raw tf32 mma: A/B operands are .b32 regs, C/D are .f32
__device__ __forceinline__ void mma16n8k8(float* d, const uint32_t* a, const uint32_t* b, const float* c) {
    asm volatile(
        "mma.sync.aligned.m16n8k8.row.col.f32.tf32.tf32.f32 "
        "{%0,%1,%2,%3}, {%4,%5,%6,%7}, {%8,%9}, {%10,%11,%12,%13};"
        : "=f"(d[0]), "=f"(d[1]), "=f"(d[2]), "=f"(d[3])
        : "r"(a[0]), "r"(a[1]), "r"(a[2]), "r"(a[3]),
          "r"(b[0]), "r"(b[1]),
          "f"(c[0]), "f"(c[1]), "f"(c[2]), "f"(c[3]));
}

// ---------------- LayerNorm ----------------
__global__ __launch_bounds__(256) void ln_kernel(const float* __restrict__ x,
                                                 float* __restrict__ out,
                                                 const float* __restrict__ alpha,
                                                 const float* __restrict__ beta)
{
    const int row = blockIdx.x;
    const int tid = threadIdx.x;
    const float* xr = x + (size_t)row * DMODEL;
    float4 v = *(const float4*)&xr[tid * 4];

    float s1 = v.x + v.y + v.z + v.w;
    float s2 = v.x*v.x + v.y*v.y + v.z*v.z + v.w*v.w;
    for (int o = 16; o > 0; o >>= 1) {
        s1 += __shfl_down_sync(0xffffffffu, s1, o);
        s2 += __shfl_down_sync(0xffffffffu, s2, o);
    }
    __shared__ float ws1[8], ws2[8];
    int lane = tid & 31, wid = tid >> 5;
    if (lane == 0) { ws1[wid] = s1; ws2[wid] = s2; }
    __syncthreads();
    if (tid == 0) {
        float a = 0.f, b = 0.f;
        #pragma unroll
        for (int i = 0; i < 8; i++) { a += ws1[i]; b += ws2[i]; }
        ws1[0] = a; ws2[0] = b;
    }
    __syncthreads();
    float sum = ws1[0], sumsq = ws2[0];
    float mean = sum * (1.0f / DMODEL);
    float var  = (sumsq - (float)DMODEL * mean * mean) * (1.0f / (DMODEL - 1));
    var = fmaxf(var, 0.0f);
    float stdv = sqrtf(var);
    float inv = alpha[0] / (stdv + LNEPS);
    float b_ = beta[0];
    float4 o4;
    o4.x = (v.x - mean) * inv + b_;
    o4.y = (v.y - mean) * inv + b_;
    o4.z = (v.z - mean) * inv + b_;
    o4.w = (v.w - mean) * inv + b_;
    *(float4*)&out[(size_t)row * DMODEL + tid * 4] = o4;
}

// =============================================================================
// Raw-mma TF32 GEMM: C[M,N] = A[M,K]*B[K,N] + bias (+res) (relu)
// Tile 128x128, BK=32, 8 warps (2x4), warp tile 64x32.
// __launch_bounds__(256,2): cap regs at 128 for 2 CTAs/SM.
// =============================================================================
#define LDA_S 36
#define LDB_S 132
#define GEMM_SMEM ((2*128*LDA_S + 2*32*LDB_S) * 4)

template<int RELU, int RES>
__global__ __launch_bounds__(256, 2) void gemm_mma(const float* __restrict__ A,
                                                   const float* __restrict__ Bm,
                                                   const float* __restrict__ bias,
                                                   const float* __restrict__ res,
                                                   float* __restrict__ C,
                                                   int K, int N)
{
    extern __shared__ float sm[];
    float* As = sm;                       // [2][128][LDA_S]
    float* Bs = sm + 2 * 128 * LDA_S;     // [2][32][LDB_S]

    const int tid = threadIdx.x;
    const int warpId = tid >> 5;
    const int lane = tid & 31;
    const int g = lane >> 2;
    const int t4 = lane & 3;
    const int row0 = blockIdx.y * 128;
    const int col0 = blockIdx.x * 128;
    const int wr = warpId & 1;
    const int wc = warpId >> 1;

    float acc[4][4][4];
    #pragma unroll
    for (int i = 0; i < 4; i++)
        #pragma unroll
        for (int j = 0; j < 4; j++)
            #pragma unroll
            for (int r = 0; r < 4; r++) acc[i][j][r] = 0.f;

    const int aRow = tid >> 1;
    const int aColB = (tid & 1) * 16;
    const int bK = tid >> 3;
    const int bN = (tid & 7) * 4;

    const int nChunks = K / 32;

    {
        const float* asrc = A + (size_t)(row0 + aRow) * K + aColB;
        #pragma unroll
        for (int i = 0; i < 4; i++) {
            float4 v = *(const float4*)(asrc + i * 4);
            float* d = &As[aRow * LDA_S + aColB + i * 4];
            d[0] = to_tf32(v.x); d[1] = to_tf32(v.y); d[2] = to_tf32(v.z); d[3] = to_tf32(v.w);
        }
        const float* bsrc = Bm + (size_t)bK * N + col0 + bN;
        #pragma unroll
        for (int i = 0; i < 4; i++) {
            float4 v = *(const float4*)(bsrc + i * 32);
            float* d = &Bs[bK * LDB_S + bN + i * 32];
            d[0] = to_tf32(v.x); d[1] = to_tf32(v.y); d[2] = to_tf32(v.z); d[3] = to_tf32(v.w);
        }
    }
    __syncthreads();

    float4 ra[4], rb[4];
    for (int c = 0; c < nChunks; c++) {
        const int buf = c & 1;
        const uint32_t* Ab = (const uint32_t*)(As + buf * 128 * LDA_S);
        const uint32_t* Bb = (const uint32_t*)(Bs + buf * 32 * LDB_S);

        if (c + 1 < nChunks) {
            const int k0 = (c + 1) * 32;
            const float* asrc = A + (size_t)(row0 + aRow) * K + k0 + aColB;
            #pragma unroll
            for (int i = 0; i < 4; i++) ra[i] = *(const float4*)(asrc + i * 4);
            const float* bsrc = Bm + (size_t)(k0 + bK) * N + col0 + bN;
            #pragma unroll
            for (int i = 0; i < 4; i++) rb[i] = *(const float4*)(bsrc + i * 32);
        }

        #pragma unroll
        for (int s = 0; s < 4; s++) {
            const int kb = s * 8;
            uint32_t af[4][4];
            uint32_t bf[4][2];
            #pragma unroll
            for (int mi = 0; mi < 4; mi++) {
                const int r = wr * 64 + mi * 16 + g;
                af[mi][0] = Ab[r * LDA_S + kb + t4];
                af[mi][1] = Ab[(r + 8) * LDA_S + kb + t4];
                af[mi][2] = Ab[r * LDA_S + kb + t4 + 4];
                af[mi][3] = Ab[(r + 8) * LDA_S + kb + t4 + 4];
            }
            #pragma unroll
            for (int ni = 0; ni < 4; ni++) {
                const int n = wc * 32 + ni * 8 + g;
                bf[ni][0] = Bb[(kb + t4) * LDB_S + n];
                bf[ni][1] = Bb[(kb + t4 + 4) * LDB_S + n];
            }
            #pragma unroll
            for (int mi = 0; mi < 4; mi++)
                #pragma unroll
                for (int ni = 0; ni < 4; ni++)
                    mma16n8k8(acc[mi][ni], af[mi], bf[ni], acc[mi][ni]);
        }

        if (c + 1 < nChunks) {
            __syncthreads();
            const int nb = (c + 1) & 1;
            float* Ad = As + nb * 128 * LDA_S;
            float* Bd = Bs + nb * 32 * LDB_S;
            #pragma unroll
            for (int i = 0; i < 4; i++) {
                float* d = &Ad[aRow * LDA_S + aColB + i * 4];
                d[0] = to_tf32(ra[i].x); d[1] = to_tf32(ra[i].y);
                d[2] = to_tf32(ra[i].z); d[3] = to_tf32(ra[i].w);
            }
            #pragma unroll
            for (int i = 0; i < 4; i++) {
                float* d = &Bd[bK * LDB_S + bN + i * 32];
                d[0] = to_tf32(rb[i].x); d[1] = to_tf32(rb[i].y);
                d[2] = to_tf32(rb[i].z); d[3] = to_tf32(rb[i].w);
            }
            __syncthreads();
        }
    }

    #pragma unroll
    for (int mi = 0; mi < 4; mi++) {
        #pragma unroll
        for (int half = 0; half < 2; half++) {
            const int gr = row0 + wr * 64 + mi * 16 + g + half * 8;
            float* crow = C + (size_t)gr * N;
            const float* rrow = RES ? (res + (size_t)gr * N) : nullptr;
            #pragma unroll
            for (int ni = 0; ni < 4; ni++) {
                const int gc = col0 + wc * 32 + ni * 8 + t4 * 2;
                float2 o;
                o.x = acc[mi][ni][half * 2 + 0];
                o.y = acc[mi][ni][half * 2 + 1];
                float2 bb = *(const float2*)&bias[gc];
                o.x += bb.x; o.y += bb.y;
                if (RES) {
                    float2 rr = *(const float2*)&rrow[gc];
                    o.x += rr.x; o.y += rr.y;
                }
                if (RELU) {
                    o.x = fmaxf(o.x, 0.f);
                    o.y = fmaxf(o.y, 0.f);
                }
                *(float2*)&crow[gc] = o;
            }
        }
    }
}

// =============================================================================
// Flash attention (tf32 mma, online softmax). One CTA = 128 q-rows of one
// (batch, head); 8 warps x 16 rows each. j processed in 64-wide tiles.
// ctx written in merged-head layout [B*S][DMODEL].
// =============================================================================
#define LDQ 68
#define LDK 68
#define LDV 72
#define LDP 68
#define FA_Q_OFF 0
#define FA_K_OFF (128*LDQ)
#define FA_V_OFF (FA_K_OFF + 64*LDK)
#define FA_P_OFF (FA_V_OFF + 64*LDV)
#define FA_SMEM  ((FA_P_OFF + 8*16*LDP) * 4)

__global__ __launch_bounds__(256) void flash_attn(const float* __restrict__ q,
                                                  const float* __restrict__ k,
                                                  const float* __restrict__ v,
                                                  const int* __restrict__ mask,
                                                  float* __restrict__ ctx)
{
    extern __shared__ float fsm[];
    float* Qs = fsm + FA_Q_OFF;
    float* Ks = fsm + FA_K_OFF;
    float* Vs = fsm + FA_V_OFF;

    const int bh = blockIdx.y;
    const int b = bh >> 4;
    const int h = bh & 15;
    const int hbase = h * DK;
    const int q0 = blockIdx.x * 128;
    const int tid = threadIdx.x;
    const int warpId = tid >> 5;
    const int lane = tid & 31;
    const int g = lane >> 2;
    const int t4 = lane & 3;

    float* Pw = fsm + FA_P_OFF + warpId * 16 * LDP;

    // ---- stage Q tile [128][64] (tf32) ----
    {
        const int row = tid >> 1;
        const int c0 = (tid & 1) * 32;
        const float* src = q + (size_t)(b * SEQ + q0 + row) * DMODEL + hbase + c0;
        float* dst = &Qs[row * LDQ + c0];
        #pragma unroll
        for (int i = 0; i < 8; i++) {
            float4 x = *(const float4*)(src + i * 4);
            float4 y;
            y.x = to_tf32(x.x); y.y = to_tf32(x.y); y.z = to_tf32(x.z); y.w = to_tf32(x.w);
            *(float4*)(dst + i * 4) = y;
        }
    }
    __syncthreads();

    // per-thread state: rows r0 = warp*16+g, r1 = +8
    float mprev0 = -1e30f, mprev1 = -1e30f;
    float l0 = 0.f, l1 = 0.f;
    float oacc[8][4];
    #pragma unroll
    for (int i = 0; i < 8; i++)
        #pragma unroll
        for (int j = 0; j < 4; j++) oacc[i][j] = 0.f;

    const int r0g = q0 + warpId * 16 + g;      // global q row (first half)
    const size_t maskBase = (size_t)b * SEQ * SEQ;

    for (int jt = 0; jt < SEQ / 64; jt++) {
        const int j0 = jt * 64;
        // ---- stage K,V tiles [64][64] (tf32) ----
        {
            const int row = tid >> 2;
            const int c0 = (tid & 3) * 16;
            const float* ksrc = k + (size_t)(b * SEQ + j0 + row) * DMODEL + hbase + c0;
            const float* vsrc = v + (size_t)(b * SEQ + j0 + row) * DMODEL + hbase + c0;
            float* kdst = &Ks[row * LDK + c0];
            float* vdst = &Vs[row * LDV + c0];
            #pragma unroll
            for (int i = 0; i < 4; i++) {
                float4 x = *(const float4*)(ksrc + i * 4);
                float4 y;
                y.x = to_tf32(x.x); y.y = to_tf32(x.y); y.z = to_tf32(x.z); y.w = to_tf32(x.w);
                *(float4*)(kdst + i * 4) = y;
                float4 xv = *(const float4*)(vsrc + i * 4);
                float4 yv;
                yv.x = to_tf32(xv.x); yv.y = to_tf32(xv.y); yv.z = to_tf32(xv.z); yv.w = to_tf32(xv.w);
                *(float4*)(vdst + i * 4) = yv;
            }
        }
        __syncthreads();

        // ---- S = Q·K^T for this warp's 16 rows x 64 cols ----
        float s[8][4];
        #pragma unroll
        for (int nt = 0; nt < 8; nt++)
            #pragma unroll
            for (int r = 0; r < 4; r++) s[nt][r] = 0.f;

        const uint32_t* Qb = (const uint32_t*)Qs;
        const uint32_t* Kb = (const uint32_t*)Ks;
        #pragma unroll
        for (int k8 = 0; k8 < 8; k8++) {
            const int kb = k8 * 8;
            uint32_t af[4];
            const int qr = warpId * 16 + g;
            af[0] = Qb[qr * LDQ + kb + t4];
            af[1] = Qb[(qr + 8) * LDQ + kb + t4];
            af[2] = Qb[qr * LDQ + kb + t4 + 4];
            af[3] = Qb[(qr + 8) * LDQ + kb + t4 + 4];
            #pragma unroll
            for (int nt = 0; nt < 8; nt++) {
                uint32_t bf[2];
                bf[0] = Kb[(nt * 8 + g) * LDK + kb + t4];
                bf[1] = Kb[(nt * 8 + g) * LDK + kb + t4 + 4];
                mma16n8k8(s[nt], af, bf, s[nt]);
            }
        }

        // ---- scale + mask + online softmax ----
        float mc0 = -1e30f, mc1 = -1e30f;
        #pragma unroll
        for (int nt = 0; nt < 8; nt++) {
            const int col = j0 + nt * 8 + 2 * t4;
            int2 m0 = *(const int2*)&mask[maskBase + (size_t)r0g * SEQ + col];
            int2 m1 = *(const int2*)&mask[maskBase + (size_t)(r0g + 8) * SEQ + col];
            s[nt][0] = (m0.x == 0) ? -1e9f : s[nt][0] * 0.125f;
            s[nt][1] = (m0.y == 0) ? -1e9f : s[nt][1] * 0.125f;
            s[nt][2] = (m1.x == 0) ? -1e9f : s[nt][2] * 0.125f;
            s[nt][3] = (m1.y == 0) ? -1e9f : s[nt][3] * 0.125f;
            mc0 = fmaxf(mc0, fmaxf(s[nt][0], s[nt][1]));
            mc1 = fmaxf(mc1, fmaxf(s[nt][2], s[nt][3]));
        }
        mc0 = fmaxf(mc0, __shfl_xor_sync(0xffffffffu, mc0, 1));
        mc0 = fmaxf(mc0, __shfl_xor_sync(0xffffffffu, mc0, 2));
        mc1 = fmaxf(mc1, __shfl_xor_sync(0xffffffffu, mc1, 1));
        mc1 = fmaxf(mc1, __shfl_xor_sync(0xffffffffu, mc1, 2));

        const float mn0 = fmaxf(mprev0, mc0);
        const float mn1 = fmaxf(mprev1, mc1);
        const float a0 = __expf(mprev0 - mn0);
        const float a1 = __expf(mprev1 - mn1);

        float lc0 = 0.f, lc1 = 0.f;
        #pragma unroll
        for (int nt = 0; nt < 8; nt++) {
            float p0 = __expf(s[nt][0] - mn0);
            float p1 = __expf(s[nt][1] - mn0);
            float p2 = __expf(s[nt][2] - mn1);
            float p3 = __expf(s[nt][3] - mn1);
            lc0 += p0 + p1;
            lc1 += p2 + p3;
            float2 w0; w0.x = to_tf32(p0); w0.y = to_tf32(p1);
            float2 w1; w1.x = to_tf32(p2); w1.y = to_tf32(p3);
            *(float2*)&Pw[g * LDP + nt * 8 + 2 * t4] = w0;
            *(float2*)&Pw[(g + 8) * LDP + nt * 8 + 2 * t4] = w1;
        }
        lc0 += __shfl_xor_sync(0xffffffffu, lc0, 1);
        lc0 += __shfl_xor_sync(0xffffffffu, lc0, 2);
        lc1 += __shfl_xor_sync(0xffffffffu, lc1, 1);
        lc1 += __shfl_xor_sync(0xffffffffu, lc1, 2);
        l0 = l0 * a0 + lc0;
        l1 = l1 * a1 + lc1;

        #pragma unroll
        for (int dn = 0; dn < 8; dn++) {
            oacc[dn][0] *= a0; oacc[dn][1] *= a0;
            oacc[dn][2] *= a1; oacc[dn][3] *= a1;
        }
        mprev0 = mn0; mprev1 = mn1;

        __syncwarp();

        // ---- O += P·V ----
        const uint32_t* Pb = (const uint32_t*)Pw;
        const uint32_t* Vb = (const uint32_t*)Vs;
        #pragma unroll
        for (int j8 = 0; j8 < 8; j8++) {
            const int kb = j8 * 8;
            uint32_t af[4];
            af[0] = Pb[g * LDP + kb + t4];
            af[1] = Pb[(g + 8) * LDP + kb + t4];
            af[2] = Pb[g * LDP + kb + t4 + 4];
            af[3] = Pb[(g + 8) * LDP + kb + t4 + 4];
            #pragma unroll
            for (int dn = 0; dn < 8; dn++) {
                uint32_t bf[2];
                bf[0] = Vb[(kb + t4) * LDV + dn * 8 + g];
                bf[1] = Vb[(kb + t4 + 4) * LDV + dn * 8 + g];
                mma16n8k8(oacc[dn], af, bf, oacc[dn]);
            }
        }
        __syncthreads();
    }

    // ---- epilogue: divide by l, write merged-head ctx ----
    const float inv0 = 1.0f / l0;
    const float inv1 = 1.0f / l1;
    float* c0row = ctx + (size_t)(b * SEQ + r0g) * DMODEL + hbase;
    float* c1row = ctx + (size_t)(b * SEQ + r0g + 8) * DMODEL + hbase;
    #pragma unroll
    for (int dn = 0; dn < 8; dn++) {
        const int dc = dn * 8 + 2 * t4;
        float2 w0; w0.x = oacc[dn][0] * inv0; w0.y = oacc[dn][1] * inv0;
        float2 w1; w1.x = oacc[dn][2] * inv1; w1.y = oacc[dn][3] * inv1;
        *(float2*)&c0row[dc] = w0;
        *(float2*)&c1row[dc] = w1;
    }
}

// ---------------- launch ----------------
extern "C" void kernel_launch(void* const* d_in, const int* in_sizes, int n_in,
                              void* d_out, int out_size)
{
    const float* x    = (const float*)d_in[0];
    const int*   mask = (const int*)  d_in[1];
    const float* wq = (const float*)d_in[2];  const float* bq = (const float*)d_in[3];
    const float* wk = (const float*)d_in[4];  const float* bk = (const float*)d_in[5];
    const float* wv = (const float*)d_in[6];  const float* bv = (const float*)d_in[7];
    const float* wo = (const float*)d_in[8];  const float* bo = (const float*)d_in[9];
    const float* w1 = (const float*)d_in[10]; const float* b1 = (const float*)d_in[11];
    const float* w2 = (const float*)d_in[12]; const float* b2 = (const float*)d_in[13];
    const float* ln1_a = (const float*)d_in[14]; const float* ln1_b = (const float*)d_in[15];
    const float* ln2_a = (const float*)d_in[16]; const float* ln2_b = (const float*)d_in[17];
    float* out = (float*)d_out;

    float *p_h, *p_q, *p_k, *p_v, *p_ctx, *p_x1, *p_h2, *p_ff;
    cudaGetSymbolAddress((void**)&p_h,  g_h);
    cudaGetSymbolAddress((void**)&p_q,  g_q);
    cudaGetSymbolAddress((void**)&p_k,  g_k);
    cudaGetSymbolAddress((void**)&p_v,  g_v);
    cudaGetSymbolAddress((void**)&p_ctx,g_ctx);
    cudaGetSymbolAddress((void**)&p_x1, g_x1);
    cudaGetSymbolAddress((void**)&p_h2, g_h2);
    cudaGetSymbolAddress((void**)&p_ff, g_ff);

    cudaFuncSetAttribute(gemm_mma<0,0>, cudaFuncAttributeMaxDynamicSharedMemorySize, GEMM_SMEM);
    cudaFuncSetAttribute(gemm_mma<0,1>, cudaFuncAttributeMaxDynamicSharedMemorySize, GEMM_SMEM);
    cudaFuncSetAttribute(gemm_mma<1,0>, cudaFuncAttributeMaxDynamicSharedMemorySize, GEMM_SMEM);
    cudaFuncSetAttribute(flash_attn, cudaFuncAttributeMaxDynamicSharedMemorySize, FA_SMEM);

    // 1) LN1
    ln_kernel<<<MTOK, 256>>>(x, p_h, ln1_a, ln1_b);

    // 2) QKV projections
    dim3 gProj(DMODEL / 128, MTOK / 128);
    gemm_mma<0,0><<<gProj, 256, GEMM_SMEM>>>(p_h, wq, bq, nullptr, p_q, DMODEL, DMODEL);
    gemm_mma<0,0><<<gProj, 256, GEMM_SMEM>>>(p_h, wk, bk, nullptr, p_k, DMODEL, DMODEL);
    gemm_mma<0,0><<<gProj, 256, GEMM_SMEM>>>(p_h, wv, bv, nullptr, p_v, DMODEL, DMODEL);

    // 3) fused attention -> ctx (merged heads)
    flash_attn<<<dim3(SEQ / 128, BATCH * NHEADS), 256, FA_SMEM>>>(p_q, p_k, p_v, mask, p_ctx);

    // 4) O projection + residual
    gemm_mma<0,1><<<gProj, 256, GEMM_SMEM>>>(p_ctx, wo, bo, x, p_x1, DMODEL, DMODEL);

    // 5) LN2
    ln_kernel<<<MTOK, 256>>>(p_x1, p_h2, ln2_a, ln2_b);

    // 6) FFN1 + ReLU
    gemm_mma<1,0><<<dim3(DFF / 128, MTOK / 128), 256, GEMM_SMEM>>>(p_h2, w1, b1, nullptr, p_ff, DMODEL, DFF);

    // 7) FFN2 + residual -> out
    gemm_mma<0,1><<<gProj, 256, GEMM_SMEM>>>(p_ff, w2, b2, p_x1, out, DFF, DMODEL);
}

// round 9
// speedup vs baseline: 2.7347x; 1.0080x over previous
#include <cuda_runtime.h>
#include <cuda_bf16.h>
#include <math.h>
#include <cstdint>

// Problem constants
#define BATCH 2
#define SEQ   2048
#define DMODEL 1024
#define NHEADS 16
#define DK    64
#define DFF   4096
#define MTOK  (BATCH*SEQ)
#define LNEPS 1e-6f

// ---------------- static device scratch ----------------
__device__ float g_q  [MTOK*DMODEL];
__device__ float g_k  [MTOK*DMODEL];
__device__ float g_v  [MTOK*DMODEL];
__device__ float g_ctx[MTOK*DMODEL];
__device__ float g_x1 [MTOK*DMODEL];
__device__ float g_ff [MTOK*DFF];
__device__ float g_ln1[MTOK*2];   // (s, t) per row for LN1
__device__ float g_ln2[MTOK*2];   // (s, t) per row for LN2

// tf32 conversion: destination must be .b32 register
__device__ __forceinline__ float to_tf32(float x) {
    uint32_t r;
    asm("cvt.rna.tf32.f32 %0, %1;" : "=r"(r) : "f"(x));
    return __uint_as_float(r);
}

// raw tf32 mma: A/B operands are .b32 regs, C/D are .f32
__device__ __forceinline__ void mma16n8k8(float* d, const uint32_t* a, const uint32_t* b, const float* c) {
    asm volatile(
        "mma.sync.aligned.m16n8k8.row.col.f32.tf32.tf32.f32 "
        "{%0,%1,%2,%3}, {%4,%5,%6,%7}, {%8,%9}, {%10,%11,%12,%13};"
        : "=f"(d[0]), "=f"(d[1]), "=f"(d[2]), "=f"(d[3])
        : "r"(a[0]), "r"(a[1]), "r"(a[2]), "r"(a[3]),
          "r"(b[0]), "r"(b[1]),
          "f"(c[0]), "f"(c[1]), "f"(c[2]), "f"(c[3]));
}

// ---------------- LN stats: per-row scale s = a/(std+eps), shift t = b - mean*s ----------------
__global__ __launch_bounds__(256) void ln_stats(const float* __restrict__ x,
                                                float* __restrict__ st,
                                                const float* __restrict__ alpha,
                                                const float* __restrict__ beta)
{
    const int row = blockIdx.x;
    const int tid = threadIdx.x;
    const float* xr = x + (size_t)row * DMODEL;
    float4 v = *(const float4*)&xr[tid * 4];

    float s1 = v.x + v.y + v.z + v.w;
    float s2 = v.x*v.x + v.y*v.y + v.z*v.z + v.w*v.w;
    for (int o = 16; o > 0; o >>= 1) {
        s1 += __shfl_down_sync(0xffffffffu, s1, o);
        s2 += __shfl_down_sync(0xffffffffu, s2, o);
    }
    __shared__ float ws1[8], ws2[8];
    int lane = tid & 31, wid = tid >> 5;
    if (lane == 0) { ws1[wid] = s1; ws2[wid] = s2; }
    __syncthreads();
    if (tid == 0) {
        float a = 0.f, b = 0.f;
        #pragma unroll
        for (int i = 0; i < 8; i++) { a += ws1[i]; b += ws2[i]; }
        float mean = a * (1.0f / DMODEL);
        float var  = (b - (float)DMODEL * mean * mean) * (1.0f / (DMODEL - 1));
        var = fmaxf(var, 0.0f);
        float s = alpha[0] / (sqrtf(var) + LNEPS);
        float t = beta[0] - mean * s;
        *(float2*)&st[row * 2] = make_float2(s, t);
    }
}

// =============================================================================
// Raw-mma TF32 GEMM: C = A*B + bias (+res) (relu), optional LN-apply on A.
// Tile 128x128, BK=32, 8 warps, warp tile 64x32. LDB_S=136 (conflict-free B frags).
// QKV mode: blockIdx.x>>3 selects (B,bias,C) among 3 matrices of N=1024.
// =============================================================================
#define LDA_S 36
#define LDB_S 136
#define GEMM_SMEM ((2*128*LDA_S + 2*32*LDB_S) * 4)

template<int RELU, int RES, int LNA, int QKV>
__global__ __launch_bounds__(256, 2) void gemm_mma(const float* __restrict__ A,
                                                   const float* __restrict__ B0,
                                                   const float* __restrict__ B1,
                                                   const float* __restrict__ B2,
                                                   const float* __restrict__ bias0,
                                                   const float* __restrict__ bias1,
                                                   const float* __restrict__ bias2,
                                                   const float* __restrict__ res,
                                                   const float* __restrict__ lnst,
                                                   float* __restrict__ C0,
                                                   float* __restrict__ C1,
                                                   float* __restrict__ C2,
                                                   int K, int N)
{
    extern __shared__ float sm[];
    float* As = sm;                       // [2][128][LDA_S]
    float* Bs = sm + 2 * 128 * LDA_S;     // [2][32][LDB_S]

    const int tid = threadIdx.x;
    const int warpId = tid >> 5;
    const int lane = tid & 31;
    const int g = lane >> 2;
    const int t4 = lane & 3;
    const int row0 = blockIdx.y * 128;

    const float* Bm = B0;
    const float* bias = bias0;
    float* C = C0;
    int col0;
    if (QKV) {
        const int sel = blockIdx.x >> 3;
        col0 = (blockIdx.x & 7) * 128;
        if (sel == 1) { Bm = B1; bias = bias1; C = C1; }
        else if (sel == 2) { Bm = B2; bias = bias2; C = C2; }
    } else {
        col0 = blockIdx.x * 128;
    }

    const int wr = warpId & 1;
    const int wc = warpId >> 1;

    float acc[4][4][4];
    #pragma unroll
    for (int i = 0; i < 4; i++)
        #pragma unroll
        for (int j = 0; j < 4; j++)
            #pragma unroll
            for (int r = 0; r < 4; r++) acc[i][j][r] = 0.f;

    const int aRow = tid >> 1;
    const int aColB = (tid & 1) * 16;
    const int bK = tid >> 3;
    const int bN = (tid & 7) * 4;

    float sA = 1.f, tA = 0.f;
    if (LNA) {
        float2 st = *(const float2*)&lnst[(row0 + aRow) * 2];
        sA = st.x; tA = st.y;
    }

    const int nChunks = K / 32;

    {
        const float* asrc = A + (size_t)(row0 + aRow) * K + aColB;
        #pragma unroll
        for (int i = 0; i < 4; i++) {
            float4 v = *(const float4*)(asrc + i * 4);
            if (LNA) {
                v.x = fmaf(v.x, sA, tA); v.y = fmaf(v.y, sA, tA);
                v.z = fmaf(v.z, sA, tA); v.w = fmaf(v.w, sA, tA);
            }
            float* d = &As[aRow * LDA_S + aColB + i * 4];
            d[0] = to_tf32(v.x); d[1] = to_tf32(v.y); d[2] = to_tf32(v.z); d[3] = to_tf32(v.w);
        }
        const float* bsrc = Bm + (size_t)bK * N + col0 + bN;
        #pragma unroll
        for (int i = 0; i < 4; i++) {
            float4 v = *(const float4*)(bsrc + i * 32);
            float* d = &Bs[bK * LDB_S + bN + i * 32];
            d[0] = to_tf32(v.x); d[1] = to_tf32(v.y); d[2] = to_tf32(v.z); d[3] = to_tf32(v.w);
        }
    }
    __syncthreads();

    float4 ra[4], rb[4];
    for (int c = 0; c < nChunks; c++) {
        const int buf = c & 1;
        const uint32_t* Ab = (const uint32_t*)(As + buf * 128 * LDA_S);
        const uint32_t* Bb = (const uint32_t*)(Bs + buf * 32 * LDB_S);

        if (c + 1 < nChunks) {
            const int k0 = (c + 1) * 32;
            const float* asrc = A + (size_t)(row0 + aRow) * K + k0 + aColB;
            #pragma unroll
            for (int i = 0; i < 4; i++) ra[i] = *(const float4*)(asrc + i * 4);
            const float* bsrc = Bm + (size_t)(k0 + bK) * N + col0 + bN;
            #pragma unroll
            for (int i = 0; i < 4; i++) rb[i] = *(const float4*)(bsrc + i * 32);
        }

        #pragma unroll
        for (int s = 0; s < 4; s++) {
            const int kb = s * 8;
            uint32_t af[4][4];
            uint32_t bf[4][2];
            #pragma unroll
            for (int mi = 0; mi < 4; mi++) {
                const int r = wr * 64 + mi * 16 + g;
                af[mi][0] = Ab[r * LDA_S + kb + t4];
                af[mi][1] = Ab[(r + 8) * LDA_S + kb + t4];
                af[mi][2] = Ab[r * LDA_S + kb + t4 + 4];
                af[mi][3] = Ab[(r + 8) * LDA_S + kb + t4 + 4];
            }
            #pragma unroll
            for (int ni = 0; ni < 4; ni++) {
                const int n = wc * 32 + ni * 8 + g;
                bf[ni][0] = Bb[(kb + t4) * LDB_S + n];
                bf[ni][1] = Bb[(kb + t4 + 4) * LDB_S + n];
            }
            #pragma unroll
            for (int mi = 0; mi < 4; mi++)
                #pragma unroll
                for (int ni = 0; ni < 4; ni++)
                    mma16n8k8(acc[mi][ni], af[mi], bf[ni], acc[mi][ni]);
        }

        if (c + 1 < nChunks) {
            __syncthreads();
            const int nb = (c + 1) & 1;
            float* Ad = As + nb * 128 * LDA_S;
            float* Bd = Bs + nb * 32 * LDB_S;
            #pragma unroll
            for (int i = 0; i < 4; i++) {
                float4 v = ra[i];
                if (LNA) {
                    v.x = fmaf(v.x, sA, tA); v.y = fmaf(v.y, sA, tA);
                    v.z = fmaf(v.z, sA, tA); v.w = fmaf(v.w, sA, tA);
                }
                float* d = &Ad[aRow * LDA_S + aColB + i * 4];
                d[0] = to_tf32(v.x); d[1] = to_tf32(v.y);
                d[2] = to_tf32(v.z); d[3] = to_tf32(v.w);
            }
            #pragma unroll
            for (int i = 0; i < 4; i++) {
                float* d = &Bd[bK * LDB_S + bN + i * 32];
                d[0] = to_tf32(rb[i].x); d[1] = to_tf32(rb[i].y);
                d[2] = to_tf32(rb[i].z); d[3] = to_tf32(rb[i].w);
            }
            __syncthreads();
        }
    }

    #pragma unroll
    for (int mi = 0; mi < 4; mi++) {
        #pragma unroll
        for (int half = 0; half < 2; half++) {
            const int gr = row0 + wr * 64 + mi * 16 + g + half * 8;
            float* crow = C + (size_t)gr * N;
            const float* rrow = RES ? (res + (size_t)gr * N) : nullptr;
            #pragma unroll
            for (int ni = 0; ni < 4; ni++) {
                const int gc = col0 + wc * 32 + ni * 8 + t4 * 2;
                float2 o;
                o.x = acc[mi][ni][half * 2 + 0];
                o.y = acc[mi][ni][half * 2 + 1];
                float2 bb = *(const float2*)&bias[gc];
                o.x += bb.x; o.y += bb.y;
                if (RES) {
                    float2 rr = *(const float2*)&rrow[gc];
                    o.x += rr.x; o.y += rr.y;
                }
                if (RELU) {
                    o.x = fmaxf(o.x, 0.f);
                    o.y = fmaxf(o.y, 0.f);
                }
                *(float2*)&crow[gc] = o;
            }
        }
    }
}

// =============================================================================
// Flash attention (tf32 mma, online softmax). One CTA = 128 q-rows of one
// (batch, head); 8 warps x 16 rows each. j processed in 64-wide tiles.
// =============================================================================
#define LDQ 68
#define LDK 68
#define LDV 72
#define LDP 68
#define FA_Q_OFF 0
#define FA_K_OFF (128*LDQ)
#define FA_V_OFF (FA_K_OFF + 64*LDK)
#define FA_P_OFF (FA_V_OFF + 64*LDV)
#define FA_SMEM  ((FA_P_OFF + 8*16*LDP) * 4)

__global__ __launch_bounds__(256, 2) void flash_attn(const float* __restrict__ q,
                                                     const float* __restrict__ k,
                                                     const float* __restrict__ v,
                                                     const int* __restrict__ mask,
                                                     float* __restrict__ ctx)
{
    extern __shared__ float fsm[];
    float* Qs = fsm + FA_Q_OFF;
    float* Ks = fsm + FA_K_OFF;
    float* Vs = fsm + FA_V_OFF;

    const int bh = blockIdx.y;
    const int b = bh >> 4;
    const int h = bh & 15;
    const int hbase = h * DK;
    const int q0 = blockIdx.x * 128;
    const int tid = threadIdx.x;
    const int warpId = tid >> 5;
    const int lane = tid & 31;
    const int g = lane >> 2;
    const int t4 = lane & 3;

    float* Pw = fsm + FA_P_OFF + warpId * 16 * LDP;

    {
        const int row = tid >> 1;
        const int c0 = (tid & 1) * 32;
        const float* src = q + (size_t)(b * SEQ + q0 + row) * DMODEL + hbase + c0;
        float* dst = &Qs[row * LDQ + c0];
        #pragma unroll
        for (int i = 0; i < 8; i++) {
            float4 x = *(const float4*)(src + i * 4);
            float4 y;
            y.x = to_tf32(x.x); y.y = to_tf32(x.y); y.z = to_tf32(x.z); y.w = to_tf32(x.w);
            *(float4*)(dst + i * 4) = y;
        }
    }
    __syncthreads();

    float mprev0 = -1e30f, mprev1 = -1e30f;
    float l0 = 0.f, l1 = 0.f;
    float oacc[8][4];
    #pragma unroll
    for (int i = 0; i < 8; i++)
        #pragma unroll
        for (int j = 0; j < 4; j++) oacc[i][j] = 0.f;

    const int r0g = q0 + warpId * 16 + g;
    const size_t maskBase = (size_t)b * SEQ * SEQ;

    for (int jt = 0; jt < SEQ / 64; jt++) {
        const int j0 = jt * 64;
        {
            const int row = tid >> 2;
            const int c0 = (tid & 3) * 16;
            const float* ksrc = k + (size_t)(b * SEQ + j0 + row) * DMODEL + hbase + c0;
            const float* vsrc = v + (size_t)(b * SEQ + j0 + row) * DMODEL + hbase + c0;
            float* kdst = &Ks[row * LDK + c0];
            float* vdst = &Vs[row * LDV + c0];
            #pragma unroll
            for (int i = 0; i < 4; i++) {
                float4 x = *(const float4*)(ksrc + i * 4);
                float4 y;
                y.x = to_tf32(x.x); y.y = to_tf32(x.y); y.z = to_tf32(x.z); y.w = to_tf32(x.w);
                *(float4*)(kdst + i * 4) = y;
                float4 xv = *(const float4*)(vsrc + i * 4);
                float4 yv;
                yv.x = to_tf32(xv.x); yv.y = to_tf32(xv.y); yv.z = to_tf32(xv.z); yv.w = to_tf32(xv.w);
                *(float4*)(vdst + i * 4) = yv;
            }
        }
        __syncthreads();

        float s[8][4];
        #pragma unroll
        for (int nt = 0; nt < 8; nt++)
            #pragma unroll
            for (int r = 0; r < 4; r++) s[nt][r] = 0.f;

        const uint32_t* Qb = (const uint32_t*)Qs;
        const uint32_t* Kb = (const uint32_t*)Ks;
        #pragma unroll
        for (int k8 = 0; k8 < 8; k8++) {
            const int kb = k8 * 8;
            uint32_t af[4];
            const int qr = warpId * 16 + g;
            af[0] = Qb[qr * LDQ + kb + t4];
            af[1] = Qb[(qr + 8) * LDQ + kb + t4];
            af[2] = Qb[qr * LDQ + kb + t4 + 4];
            af[3] = Qb[(qr + 8) * LDQ + kb + t4 + 4];
            #pragma unroll
            for (int nt = 0; nt < 8; nt++) {
                uint32_t bf[2];
                bf[0] = Kb[(nt * 8 + g) * LDK + kb + t4];
                bf[1] = Kb[(nt * 8 + g) * LDK + kb + t4 + 4];
                mma16n8k8(s[nt], af, bf, s[nt]);
            }
        }

        float mc0 = -1e30f, mc1 = -1e30f;
        #pragma unroll
        for (int nt = 0; nt < 8; nt++) {
            const int col = j0 + nt * 8 + 2 * t4;
            int2 m0 = *(const int2*)&mask[maskBase + (size_t)r0g * SEQ + col];
            int2 m1 = *(const int2*)&mask[maskBase + (size_t)(r0g + 8) * SEQ + col];
            s[nt][0] = (m0.x == 0) ? -1e9f : s[nt][0] * 0.125f;
            s[nt][1] = (m0.y == 0) ? -1e9f : s[nt][1] * 0.125f;
            s[nt][2] = (m1.x == 0) ? -1e9f : s[nt][2] * 0.125f;
            s[nt][3] = (m1.y == 0) ? -1e9f : s[nt][3] * 0.125f;
            mc0 = fmaxf(mc0, fmaxf(s[nt][0], s[nt][1]));
            mc1 = fmaxf(mc1, fmaxf(s[nt][2], s[nt][3]));
        }
        mc0 = fmaxf(mc0, __shfl_xor_sync(0xffffffffu, mc0, 1));
        mc0 = fmaxf(mc0, __shfl_xor_sync(0xffffffffu, mc0, 2));
        mc1 = fmaxf(mc1, __shfl_xor_sync(0xffffffffu, mc1, 1));
        mc1 = fmaxf(mc1, __shfl_xor_sync(0xffffffffu, mc1, 2));

        const float mn0 = fmaxf(mprev0, mc0);
        const float mn1 = fmaxf(mprev1, mc1);
        const float a0 = __expf(mprev0 - mn0);
        const float a1 = __expf(mprev1 - mn1);

        float lc0 = 0.f, lc1 = 0.f;
        #pragma unroll
        for (int nt = 0; nt < 8; nt++) {
            float p0 = __expf(s[nt][0] - mn0);
            float p1 = __expf(s[nt][1] - mn0);
            float p2 = __expf(s[nt][2] - mn1);
            float p3 = __expf(s[nt][3] - mn1);
            lc0 += p0 + p1;
            lc1 += p2 + p3;
            float2 w0; w0.x = to_tf32(p0); w0.y = to_tf32(p1);
            float2 w1; w1.x = to_tf32(p2); w1.y = to_tf32(p3);
            *(float2*)&Pw[g * LDP + nt * 8 + 2 * t4] = w0;
            *(float2*)&Pw[(g + 8) * LDP + nt * 8 + 2 * t4] = w1;
        }
        lc0 += __shfl_xor_sync(0xffffffffu, lc0, 1);
        lc0 += __shfl_xor_sync(0xffffffffu, lc0, 2);
        lc1 += __shfl_xor_sync(0xffffffffu, lc1, 1);
        lc1 += __shfl_xor_sync(0xffffffffu, lc1, 2);
        l0 = l0 * a0 + lc0;
        l1 = l1 * a1 + lc1;

        #pragma unroll
        for (int dn = 0; dn < 8; dn++) {
            oacc[dn][0] *= a0; oacc[dn][1] *= a0;
            oacc[dn][2] *= a1; oacc[dn][3] *= a1;
        }
        mprev0 = mn0; mprev1 = mn1;

        __syncwarp();

        const uint32_t* Pb = (const uint32_t*)Pw;
        const uint32_t* Vb = (const uint32_t*)Vs;
        #pragma unroll
        for (int j8 = 0; j8 < 8; j8++) {
            const int kb = j8 * 8;
            uint32_t af[4];
            af[0] = Pb[g * LDP + kb + t4];
            af[1] = Pb[(g + 8) * LDP + kb + t4];
            af[2] = Pb[g * LDP + kb + t4 + 4];
            af[3] = Pb[(g + 8) * LDP + kb + t4 + 4];
            #pragma unroll
            for (int dn = 0; dn < 8; dn++) {
                uint32_t bf[2];
                bf[0] = Vb[(kb + t4) * LDV + dn * 8 + g];
                bf[1] = Vb[(kb + t4 + 4) * LDV + dn * 8 + g];
                mma16n8k8(oacc[dn], af, bf, oacc[dn]);
            }
        }
        __syncthreads();
    }

    const float inv0 = 1.0f / l0;
    const float inv1 = 1.0f / l1;
    float* c0row = ctx + (size_t)(b * SEQ + r0g) * DMODEL + hbase;
    float* c1row = ctx + (size_t)(b * SEQ + r0g + 8) * DMODEL + hbase;
    #pragma unroll
    for (int dn = 0; dn < 8; dn++) {
        const int dc = dn * 8 + 2 * t4;
        float2 w0; w0.x = oacc[dn][0] * inv0; w0.y = oacc[dn][1] * inv0;
        float2 w1; w1.x = oacc[dn][2] * inv1; w1.y = oacc[dn][3] * inv1;
        *(float2*)&c0row[dc] = w0;
        *(float2*)&c1row[dc] = w1;
    }
}

// ---------------- launch ----------------
extern "C" void kernel_launch(void* const* d_in, const int* in_sizes, int n_in,
                              void* d_out, int out_size)
{
    const float* x    = (const float*)d_in[0];
    const int*   mask = (const int*)  d_in[1];
    const float* wq = (const float*)d_in[2];  const float* bq = (const float*)d_in[3];
    const float* wk = (const float*)d_in[4];  const float* bk = (const float*)d_in[5];
    const float* wv = (const float*)d_in[6];  const float* bv = (const float*)d_in[7];
    const float* wo = (const float*)d_in[8];  const float* bo = (const float*)d_in[9];
    const float* w1 = (const float*)d_in[10]; const float* b1 = (const float*)d_in[11];
    const float* w2 = (const float*)d_in[12]; const float* b2 = (const float*)d_in[13];
    const float* ln1_a = (const float*)d_in[14]; const float* ln1_b = (const float*)d_in[15];
    const float* ln2_a = (const float*)d_in[16]; const float* ln2_b = (const float*)d_in[17];
    float* out = (float*)d_out;

    float *p_q, *p_k, *p_v, *p_ctx, *p_x1, *p_ff, *p_l1, *p_l2;
    cudaGetSymbolAddress((void**)&p_q,  g_q);
    cudaGetSymbolAddress((void**)&p_k,  g_k);
    cudaGetSymbolAddress((void**)&p_v,  g_v);
    cudaGetSymbolAddress((void**)&p_ctx,g_ctx);
    cudaGetSymbolAddress((void**)&p_x1, g_x1);
    cudaGetSymbolAddress((void**)&p_ff, g_ff);
    cudaGetSymbolAddress((void**)&p_l1, g_ln1);
    cudaGetSymbolAddress((void**)&p_l2, g_ln2);

    cudaFuncSetAttribute(gemm_mma<0,0,1,1>, cudaFuncAttributeMaxDynamicSharedMemorySize, GEMM_SMEM);
    cudaFuncSetAttribute(gemm_mma<0,1,0,0>, cudaFuncAttributeMaxDynamicSharedMemorySize, GEMM_SMEM);
    cudaFuncSetAttribute(gemm_mma<1,0,1,0>, cudaFuncAttributeMaxDynamicSharedMemorySize, GEMM_SMEM);
    cudaFuncSetAttribute(flash_attn, cudaFuncAttributeMaxDynamicSharedMemorySize, FA_SMEM);

    // 1) LN1 stats
    ln_stats<<<MTOK, 256>>>(x, p_l1, ln1_a, ln1_b);

    // 2) Fused QKV projection (LN applied in staging)
    gemm_mma<0,0,1,1><<<dim3(24, MTOK / 128), 256, GEMM_SMEM>>>(
        x, wq, wk, wv, bq, bk, bv, nullptr, p_l1, p_q, p_k, p_v, DMODEL, DMODEL);

    // 3) fused attention -> ctx (merged heads)
    flash_attn<<<dim3(SEQ / 128, BATCH * NHEADS), 256, FA_SMEM>>>(p_q, p_k, p_v, mask, p_ctx);

    // 4) O projection + residual -> x1
    gemm_mma<0,1,0,0><<<dim3(8, MTOK / 128), 256, GEMM_SMEM>>>(
        p_ctx, wo, nullptr, nullptr, bo, nullptr, nullptr, x, nullptr,
        p_x1, nullptr, nullptr, DMODEL, DMODEL);

    // 5) LN2 stats
    ln_stats<<<MTOK, 256>>>(p_x1, p_l2, ln2_a, ln2_b);

    // 6) FFN1 + ReLU (LN applied in staging)
    gemm_mma<1,0,1,0><<<dim3(DFF / 128, MTOK / 128), 256, GEMM_SMEM>>>(
        p_x1, w1, nullptr, nullptr, b1, nullptr, nullptr, nullptr, p_l2,
        p_ff, nullptr, nullptr, DMODEL, DFF);

    // 7) FFN2 + residual -> out
    gemm_mma<0,1,0,0><<<dim3(8, MTOK / 128), 256, GEMM_SMEM>>>(
        p_ff, w2, nullptr, nullptr, b2, nullptr, nullptr, p_x1, nullptr,
        out, nullptr, nullptr, DFF, DMODEL);
}

// round 10
// speedup vs baseline: 2.7421x; 1.0027x over previous
#include <cuda_runtime.h>
#include <cuda_bf16.h>
#include <math.h>
#include <cstdint>

// Problem constants
#define BATCH 2
#define SEQ   2048
#define DMODEL 1024
#define NHEADS 16
#define DK    64
#define DFF   4096
#define MTOK  (BATCH*SEQ)
#define LNEPS 1e-6f

// ---------------- static device scratch ----------------
__device__ float g_q  [MTOK*DMODEL];
__device__ float g_k  [MTOK*DMODEL];
__device__ float g_v  [MTOK*DMODEL];
__device__ float g_ctx[MTOK*DMODEL];
__device__ float g_x1 [MTOK*DMODEL];
__device__ float g_ff [MTOK*DFF];
__device__ float g_ln1[MTOK*2];
__device__ float g_ln2[MTOK*2];

__device__ __forceinline__ uint32_t smem_u32(const void* p) {
    uint32_t a;
    asm("{ .reg .u64 t; cvta.to.shared.u64 t, %1; cvt.u32.u64 %0, t; }" : "=r"(a) : "l"(p));
    return a;
}
__device__ __forceinline__ void cp_async16(uint32_t saddr, const void* gaddr) {
    asm volatile("cp.async.cg.shared.global [%0], [%1], 16;" :: "r"(saddr), "l"(gaddr) : "memory");
}
#define CP_COMMIT() asm volatile("cp.async.commit_group;" ::: "memory")
#define CP_WAIT0()  asm volatile("cp.async.wait_group 0;" ::: "memory")

// raw tf32 mma: A/B operands .b32 (raw fp32 => HW truncates to tf32), C/D .f32
__device__ __forceinline__ void mma16n8k8(float* d, const uint32_t* a, const uint32_t* b, const float* c) {
    asm volatile(
        "mma.sync.aligned.m16n8k8.row.col.f32.tf32.tf32.f32 "
        "{%0,%1,%2,%3}, {%4,%5,%6,%7}, {%8,%9}, {%10,%11,%12,%13};"
        : "=f"(d[0]), "=f"(d[1]), "=f"(d[2]), "=f"(d[3])
        : "r"(a[0]), "r"(a[1]), "r"(a[2]), "r"(a[3]),
          "r"(b[0]), "r"(b[1]),
          "f"(c[0]), "f"(c[1]), "f"(c[2]), "f"(c[3]));
}

// ---------------- LN stats: s = a/(std+eps), t = b - mean*s ----------------
__global__ __launch_bounds__(256) void ln_stats(const float* __restrict__ x,
                                                float* __restrict__ st,
                                                const float* __restrict__ alpha,
                                                const float* __restrict__ beta)
{
    const int row = blockIdx.x;
    const int tid = threadIdx.x;
    const float* xr = x + (size_t)row * DMODEL;
    float4 v = *(const float4*)&xr[tid * 4];

    float s1 = v.x + v.y + v.z + v.w;
    float s2 = v.x*v.x + v.y*v.y + v.z*v.z + v.w*v.w;
    for (int o = 16; o > 0; o >>= 1) {
        s1 += __shfl_down_sync(0xffffffffu, s1, o);
        s2 += __shfl_down_sync(0xffffffffu, s2, o);
    }
    __shared__ float ws1[8], ws2[8];
    int lane = tid & 31, wid = tid >> 5;
    if (lane == 0) { ws1[wid] = s1; ws2[wid] = s2; }
    __syncthreads();
    if (tid == 0) {
        float a = 0.f, b = 0.f;
        #pragma unroll
        for (int i = 0; i < 8; i++) { a += ws1[i]; b += ws2[i]; }
        float mean = a * (1.0f / DMODEL);
        float var  = (b - (float)DMODEL * mean * mean) * (1.0f / (DMODEL - 1));
        var = fmaxf(var, 0.0f);
        float s = alpha[0] / (sqrtf(var) + LNEPS);
        float t = beta[0] - mean * s;
        *(float2*)&st[row * 2] = make_float2(s, t);
    }
}

// =============================================================================
// Raw-mma TF32 GEMM with cp.async staging (raw fp32 in smem, HW-truncated tf32).
// Tile 128x128, BK=32, 8 warps, warp tile 64x32.
// =============================================================================
#define LDA_S 36   // 144B row, 16B-aligned
#define LDB_S 136  // 544B row, 16B-aligned
#define GEMM_SMEM ((2*128*LDA_S + 2*32*LDB_S) * 4)

template<int RELU, int RES, int LNA, int QKV>
__global__ __launch_bounds__(256, 2) void gemm_mma(const float* __restrict__ A,
                                                   const float* __restrict__ B0,
                                                   const float* __restrict__ B1,
                                                   const float* __restrict__ B2,
                                                   const float* __restrict__ bias0,
                                                   const float* __restrict__ bias1,
                                                   const float* __restrict__ bias2,
                                                   const float* __restrict__ res,
                                                   const float* __restrict__ lnst,
                                                   float* __restrict__ C0,
                                                   float* __restrict__ C1,
                                                   float* __restrict__ C2,
                                                   int K, int N)
{
    extern __shared__ float sm[];
    float* As = sm;                       // [2][128][LDA_S]
    float* Bs = sm + 2 * 128 * LDA_S;     // [2][32][LDB_S]
    const uint32_t AsB = smem_u32(As);
    const uint32_t BsB = smem_u32(Bs);

    const int tid = threadIdx.x;
    const int warpId = tid >> 5;
    const int lane = tid & 31;
    const int g = lane >> 2;
    const int t4 = lane & 3;
    const int row0 = blockIdx.y * 128;

    const float* Bm = B0;
    const float* bias = bias0;
    float* C = C0;
    int col0;
    if (QKV) {
        const int sel = blockIdx.x >> 3;
        col0 = (blockIdx.x & 7) * 128;
        if (sel == 1) { Bm = B1; bias = bias1; C = C1; }
        else if (sel == 2) { Bm = B2; bias = bias2; C = C2; }
    } else {
        col0 = blockIdx.x * 128;
    }

    const int wr = warpId & 1;
    const int wc = warpId >> 1;

    float acc[4][4][4];
    #pragma unroll
    for (int i = 0; i < 4; i++)
        #pragma unroll
        for (int j = 0; j < 4; j++)
            #pragma unroll
            for (int r = 0; r < 4; r++) acc[i][j][r] = 0.f;

    // staging indices
    const int aRow = tid >> 1;            // 0..127
    const int aColB = (tid & 1) * 16;     // 0 or 16
    const int bK = tid >> 3;              // 0..31
    const int bN16 = (tid & 7) * 16;      // 0..112

    float sA = 1.f, tA = 0.f;
    if (LNA) {
        float2 st = *(const float2*)&lnst[(row0 + aRow) * 2];
        sA = st.x; tA = st.y;
    }

    const float* aBase = A + (size_t)(row0 + aRow) * K + aColB;
    const float* bBase = Bm + (size_t)bK * N + col0 + bN16;

    const int nChunks = K / 32;

    // ---- prologue: stage chunk 0 ----
    if (LNA) {
        #pragma unroll
        for (int i = 0; i < 4; i++) {
            float4 v = *(const float4*)(aBase + i * 4);
            v.x = fmaf(v.x, sA, tA); v.y = fmaf(v.y, sA, tA);
            v.z = fmaf(v.z, sA, tA); v.w = fmaf(v.w, sA, tA);
            *(float4*)&As[aRow * LDA_S + aColB + i * 4] = v;
        }
    } else {
        #pragma unroll
        for (int i = 0; i < 4; i++)
            cp_async16(AsB + (aRow * LDA_S + aColB + i * 4) * 4, aBase + i * 4);
    }
    #pragma unroll
    for (int i = 0; i < 4; i++)
        cp_async16(BsB + (bK * LDB_S + bN16 + i * 4) * 4, bBase + i * 4);
    CP_COMMIT();
    CP_WAIT0();
    __syncthreads();

    float4 ra[4];
    for (int c = 0; c < nChunks; c++) {
        const int buf = c & 1;
        const int nb = (c + 1) & 1;
        if (c + 1 < nChunks) {
            const int k0 = (c + 1) * 32;
            if (LNA) {
                #pragma unroll
                for (int i = 0; i < 4; i++) ra[i] = *(const float4*)(aBase + k0 + i * 4);
            } else {
                #pragma unroll
                for (int i = 0; i < 4; i++)
                    cp_async16(AsB + (nb * 128 * LDA_S + aRow * LDA_S + aColB + i * 4) * 4,
                               aBase + k0 + i * 4);
            }
            #pragma unroll
            for (int i = 0; i < 4; i++)
                cp_async16(BsB + (nb * 32 * LDB_S + bK * LDB_S + bN16 + i * 4) * 4,
                           bBase + (size_t)k0 * N + i * 4);
            CP_COMMIT();
        }

        const uint32_t* Ab = (const uint32_t*)(As + buf * 128 * LDA_S);
        const uint32_t* Bb = (const uint32_t*)(Bs + buf * 32 * LDB_S);

        #pragma unroll
        for (int s = 0; s < 4; s++) {
            const int kb = s * 8;
            uint32_t af[4][4];
            uint32_t bf[4][2];
            #pragma unroll
            for (int mi = 0; mi < 4; mi++) {
                const int r = wr * 64 + mi * 16 + g;
                af[mi][0] = Ab[r * LDA_S + kb + t4];
                af[mi][1] = Ab[(r + 8) * LDA_S + kb + t4];
                af[mi][2] = Ab[r * LDA_S + kb + t4 + 4];
                af[mi][3] = Ab[(r + 8) * LDA_S + kb + t4 + 4];
            }
            #pragma unroll
            for (int ni = 0; ni < 4; ni++) {
                const int n = wc * 32 + ni * 8 + g;
                bf[ni][0] = Bb[(kb + t4) * LDB_S + n];
                bf[ni][1] = Bb[(kb + t4 + 4) * LDB_S + n];
            }
            #pragma unroll
            for (int mi = 0; mi < 4; mi++)
                #pragma unroll
                for (int ni = 0; ni < 4; ni++)
                    mma16n8k8(acc[mi][ni], af[mi], bf[ni], acc[mi][ni]);
        }

        __syncthreads();   // all warps done reading buf (it becomes nb at c+2)
        if (c + 1 < nChunks) {
            if (LNA) {
                #pragma unroll
                for (int i = 0; i < 4; i++) {
                    float4 v = ra[i];
                    v.x = fmaf(v.x, sA, tA); v.y = fmaf(v.y, sA, tA);
                    v.z = fmaf(v.z, sA, tA); v.w = fmaf(v.w, sA, tA);
                    *(float4*)&As[nb * 128 * LDA_S + aRow * LDA_S + aColB + i * 4] = v;
                }
            }
            CP_WAIT0();
            __syncthreads();
        }
    }

    // ---- epilogue ----
    #pragma unroll
    for (int mi = 0; mi < 4; mi++) {
        #pragma unroll
        for (int half = 0; half < 2; half++) {
            const int gr = row0 + wr * 64 + mi * 16 + g + half * 8;
            float* crow = C + (size_t)gr * N;
            const float* rrow = RES ? (res + (size_t)gr * N) : nullptr;
            #pragma unroll
            for (int ni = 0; ni < 4; ni++) {
                const int gc = col0 + wc * 32 + ni * 8 + t4 * 2;
                float2 o;
                o.x = acc[mi][ni][half * 2 + 0];
                o.y = acc[mi][ni][half * 2 + 1];
                float2 bb = *(const float2*)&bias[gc];
                o.x += bb.x; o.y += bb.y;
                if (RES) {
                    float2 rr = *(const float2*)&rrow[gc];
                    o.x += rr.x; o.y += rr.y;
                }
                if (RELU) {
                    o.x = fmaxf(o.x, 0.f);
                    o.y = fmaxf(o.y, 0.f);
                }
                *(float2*)&crow[gc] = o;
            }
        }
    }
}

// =============================================================================
// Flash attention (raw-fp32 tf32 mma, online softmax, cp.async staging)
// =============================================================================
#define LDQ 68
#define LDK 68
#define LDV 72
#define LDP 68
#define FA_Q_OFF 0
#define FA_K_OFF (128*LDQ)
#define FA_V_OFF (FA_K_OFF + 64*LDK)
#define FA_P_OFF (FA_V_OFF + 64*LDV)
#define FA_SMEM  ((FA_P_OFF + 8*16*LDP) * 4)

__global__ __launch_bounds__(256, 2) void flash_attn(const float* __restrict__ q,
                                                     const float* __restrict__ k,
                                                     const float* __restrict__ v,
                                                     const int* __restrict__ mask,
                                                     float* __restrict__ ctx)
{
    extern __shared__ float fsm[];
    float* Qs = fsm + FA_Q_OFF;
    float* Ks = fsm + FA_K_OFF;
    float* Vs = fsm + FA_V_OFF;
    const uint32_t QsB = smem_u32(Qs);
    const uint32_t KsB = smem_u32(Ks);
    const uint32_t VsB = smem_u32(Vs);

    const int bh = blockIdx.y;
    const int b = bh >> 4;
    const int h = bh & 15;
    const int hbase = h * DK;
    const int q0 = blockIdx.x * 128;
    const int tid = threadIdx.x;
    const int warpId = tid >> 5;
    const int lane = tid & 31;
    const int g = lane >> 2;
    const int t4 = lane & 3;

    float* Pw = fsm + FA_P_OFF + warpId * 16 * LDP;

    // ---- stage Q tile [128][64] via cp.async ----
    {
        const int row = tid >> 1;
        const int c0 = (tid & 1) * 32;
        const float* src = q + (size_t)(b * SEQ + q0 + row) * DMODEL + hbase + c0;
        #pragma unroll
        for (int i = 0; i < 8; i++)
            cp_async16(QsB + (row * LDQ + c0 + i * 4) * 4, src + i * 4);
        CP_COMMIT();
    }

    float mprev0 = -1e30f, mprev1 = -1e30f;
    float l0 = 0.f, l1 = 0.f;
    float oacc[8][4];
    #pragma unroll
    for (int i = 0; i < 8; i++)
        #pragma unroll
        for (int j = 0; j < 4; j++) oacc[i][j] = 0.f;

    const int r0g = q0 + warpId * 16 + g;
    const size_t maskBase = (size_t)b * SEQ * SEQ;

    for (int jt = 0; jt < SEQ / 64; jt++) {
        const int j0 = jt * 64;
        {
            const int row = tid >> 2;
            const int c0 = (tid & 3) * 16;
            const float* ksrc = k + (size_t)(b * SEQ + j0 + row) * DMODEL + hbase + c0;
            const float* vsrc = v + (size_t)(b * SEQ + j0 + row) * DMODEL + hbase + c0;
            #pragma unroll
            for (int i = 0; i < 4; i++) {
                cp_async16(KsB + (row * LDK + c0 + i * 4) * 4, ksrc + i * 4);
                cp_async16(VsB + (row * LDV + c0 + i * 4) * 4, vsrc + i * 4);
            }
            CP_COMMIT();
            CP_WAIT0();
        }
        __syncthreads();

        float s[8][4];
        #pragma unroll
        for (int nt = 0; nt < 8; nt++)
            #pragma unroll
            for (int r = 0; r < 4; r++) s[nt][r] = 0.f;

        const uint32_t* Qb = (const uint32_t*)Qs;
        const uint32_t* Kb = (const uint32_t*)Ks;
        #pragma unroll
        for (int k8 = 0; k8 < 8; k8++) {
            const int kb = k8 * 8;
            uint32_t af[4];
            const int qr = warpId * 16 + g;
            af[0] = Qb[qr * LDQ + kb + t4];
            af[1] = Qb[(qr + 8) * LDQ + kb + t4];
            af[2] = Qb[qr * LDQ + kb + t4 + 4];
            af[3] = Qb[(qr + 8) * LDQ + kb + t4 + 4];
            #pragma unroll
            for (int nt = 0; nt < 8; nt++) {
                uint32_t bf[2];
                bf[0] = Kb[(nt * 8 + g) * LDK + kb + t4];
                bf[1] = Kb[(nt * 8 + g) * LDK + kb + t4 + 4];
                mma16n8k8(s[nt], af, bf, s[nt]);
            }
        }

        float mc0 = -1e30f, mc1 = -1e30f;
        #pragma unroll
        for (int nt = 0; nt < 8; nt++) {
            const int col = j0 + nt * 8 + 2 * t4;
            int2 m0 = *(const int2*)&mask[maskBase + (size_t)r0g * SEQ + col];
            int2 m1 = *(const int2*)&mask[maskBase + (size_t)(r0g + 8) * SEQ + col];
            s[nt][0] = (m0.x == 0) ? -1e9f : s[nt][0] * 0.125f;
            s[nt][1] = (m0.y == 0) ? -1e9f : s[nt][1] * 0.125f;
            s[nt][2] = (m1.x == 0) ? -1e9f : s[nt][2] * 0.125f;
            s[nt][3] = (m1.y == 0) ? -1e9f : s[nt][3] * 0.125f;
            mc0 = fmaxf(mc0, fmaxf(s[nt][0], s[nt][1]));
            mc1 = fmaxf(mc1, fmaxf(s[nt][2], s[nt][3]));
        }
        mc0 = fmaxf(mc0, __shfl_xor_sync(0xffffffffu, mc0, 1));
        mc0 = fmaxf(mc0, __shfl_xor_sync(0xffffffffu, mc0, 2));
        mc1 = fmaxf(mc1, __shfl_xor_sync(0xffffffffu, mc1, 1));
        mc1 = fmaxf(mc1, __shfl_xor_sync(0xffffffffu, mc1, 2));

        const float mn0 = fmaxf(mprev0, mc0);
        const float mn1 = fmaxf(mprev1, mc1);
        const float a0 = __expf(mprev0 - mn0);
        const float a1 = __expf(mprev1 - mn1);

        float lc0 = 0.f, lc1 = 0.f;
        #pragma unroll
        for (int nt = 0; nt < 8; nt++) {
            float p0 = __expf(s[nt][0] - mn0);
            float p1 = __expf(s[nt][1] - mn0);
            float p2 = __expf(s[nt][2] - mn1);
            float p3 = __expf(s[nt][3] - mn1);
            lc0 += p0 + p1;
            lc1 += p2 + p3;
            float2 w0; w0.x = p0; w0.y = p1;
            float2 w1; w1.x = p2; w1.y = p3;
            *(float2*)&Pw[g * LDP + nt * 8 + 2 * t4] = w0;
            *(float2*)&Pw[(g + 8) * LDP + nt * 8 + 2 * t4] = w1;
        }
        lc0 += __shfl_xor_sync(0xffffffffu, lc0, 1);
        lc0 += __shfl_xor_sync(0xffffffffu, lc0, 2);
        lc1 += __shfl_xor_sync(0xffffffffu, lc1, 1);
        lc1 += __shfl_xor_sync(0xffffffffu, lc1, 2);
        l0 = l0 * a0 + lc0;
        l1 = l1 * a1 + lc1;

        #pragma unroll
        for (int dn = 0; dn < 8; dn++) {
            oacc[dn][0] *= a0; oacc[dn][1] *= a0;
            oacc[dn][2] *= a1; oacc[dn][3] *= a1;
        }
        mprev0 = mn0; mprev1 = mn1;

        __syncwarp();

        const uint32_t* Pb = (const uint32_t*)Pw;
        const uint32_t* Vb = (const uint32_t*)Vs;
        #pragma unroll
        for (int j8 = 0; j8 < 8; j8++) {
            const int kb = j8 * 8;
            uint32_t af[4];
            af[0] = Pb[g * LDP + kb + t4];
            af[1] = Pb[(g + 8) * LDP + kb + t4];
            af[2] = Pb[g * LDP + kb + t4 + 4];
            af[3] = Pb[(g + 8) * LDP + kb + t4 + 4];
            #pragma unroll
            for (int dn = 0; dn < 8; dn++) {
                uint32_t bf[2];
                bf[0] = Vb[(kb + t4) * LDV + dn * 8 + g];
                bf[1] = Vb[(kb + t4 + 4) * LDV + dn * 8 + g];
                mma16n8k8(oacc[dn], af, bf, oacc[dn]);
            }
        }
        __syncthreads();
    }

    const float inv0 = 1.0f / l0;
    const float inv1 = 1.0f / l1;
    float* c0row = ctx + (size_t)(b * SEQ + r0g) * DMODEL + hbase;
    float* c1row = ctx + (size_t)(b * SEQ + r0g + 8) * DMODEL + hbase;
    #pragma unroll
    for (int dn = 0; dn < 8; dn++) {
        const int dc = dn * 8 + 2 * t4;
        float2 w0; w0.x = oacc[dn][0] * inv0; w0.y = oacc[dn][1] * inv0;
        float2 w1; w1.x = oacc[dn][2] * inv1; w1.y = oacc[dn][3] * inv1;
        *(float2*)&c0row[dc] = w0;
        *(float2*)&c1row[dc] = w1;
    }
}

// ---------------- launch ----------------
extern "C" void kernel_launch(void* const* d_in, const int* in_sizes, int n_in,
                              void* d_out, int out_size)
{
    const float* x    = (const float*)d_in[0];
    const int*   mask = (const int*)  d_in[1];
    const float* wq = (const float*)d_in[2];  const float* bq = (const float*)d_in[3];
    const float* wk = (const float*)d_in[4];  const float* bk = (const float*)d_in[5];
    const float* wv = (const float*)d_in[6];  const float* bv = (const float*)d_in[7];
    const float* wo = (const float*)d_in[8];  const float* bo = (const float*)d_in[9];
    const float* w1 = (const float*)d_in[10]; const float* b1 = (const float*)d_in[11];
    const float* w2 = (const float*)d_in[12]; const float* b2 = (const float*)d_in[13];
    const float* ln1_a = (const float*)d_in[14]; const float* ln1_b = (const float*)d_in[15];
    const float* ln2_a = (const float*)d_in[16]; const float* ln2_b = (const float*)d_in[17];
    float* out = (float*)d_out;

    float *p_q, *p_k, *p_v, *p_ctx, *p_x1, *p_ff, *p_l1, *p_l2;
    cudaGetSymbolAddress((void**)&p_q,  g_q);
    cudaGetSymbolAddress((void**)&p_k,  g_k);
    cudaGetSymbolAddress((void**)&p_v,  g_v);
    cudaGetSymbolAddress((void**)&p_ctx,g_ctx);
    cudaGetSymbolAddress((void**)&p_x1, g_x1);
    cudaGetSymbolAddress((void**)&p_ff, g_ff);
    cudaGetSymbolAddress((void**)&p_l1, g_ln1);
    cudaGetSymbolAddress((void**)&p_l2, g_ln2);

    cudaFuncSetAttribute(gemm_mma<0,0,1,1>, cudaFuncAttributeMaxDynamicSharedMemorySize, GEMM_SMEM);
    cudaFuncSetAttribute(gemm_mma<0,1,0,0>, cudaFuncAttributeMaxDynamicSharedMemorySize, GEMM_SMEM);
    cudaFuncSetAttribute(gemm_mma<1,0,1,0>, cudaFuncAttributeMaxDynamicSharedMemorySize, GEMM_SMEM);
    cudaFuncSetAttribute(flash_attn, cudaFuncAttributeMaxDynamicSharedMemorySize, FA_SMEM);

    // 1) LN1 stats
    ln_stats<<<MTOK, 256>>>(x, p_l1, ln1_a, ln1_b);

    // 2) Fused QKV projection (LN applied in staging)
    gemm_mma<0,0,1,1><<<dim3(24, MTOK / 128), 256, GEMM_SMEM>>>(
        x, wq, wk, wv, bq, bk, bv, nullptr, p_l1, p_q, p_k, p_v, DMODEL, DMODEL);

    // 3) fused attention -> ctx (merged heads)
    flash_attn<<<dim3(SEQ / 128, BATCH * NHEADS), 256, FA_SMEM>>>(p_q, p_k, p_v, mask, p_ctx);

    // 4) O projection + residual -> x1
    gemm_mma<0,1,0,0><<<dim3(8, MTOK / 128), 256, GEMM_SMEM>>>(
        p_ctx, wo, nullptr, nullptr, bo, nullptr, nullptr, x, nullptr,
        p_x1, nullptr, nullptr, DMODEL, DMODEL);

    // 5) LN2 stats
    ln_stats<<<MTOK, 256>>>(p_x1, p_l2, ln2_a, ln2_b);

    // 6) FFN1 + ReLU (LN applied in staging)
    gemm_mma<1,0,1,0><<<dim3(DFF / 128, MTOK / 128), 256, GEMM_SMEM>>>(
        p_x1, w1, nullptr, nullptr, b1, nullptr, nullptr, nullptr, p_l2,
        p_ff, nullptr, nullptr, DMODEL, DFF);

    // 7) FFN2 + residual -> out
    gemm_mma<0,1,0,0><<<dim3(8, MTOK / 128), 256, GEMM_SMEM>>>(
        p_ff, w2, nullptr, nullptr, b2, nullptr, nullptr, p_x1, nullptr,
        out, nullptr, nullptr, DFF, DMODEL);
}

// round 11
// speedup vs baseline: 3.4486x; 1.2577x over previous
#include <cuda_runtime.h>
#include <cuda_fp16.h>
#include <math.h>
#include <cstdint>

// Problem constants
#define BATCH 2
#define SEQ   2048
#define DMODEL 1024
#define NHEADS 16
#define DK    64
#define DFF   4096
#define MTOK  (BATCH*SEQ)
#define LNEPS 1e-6f

// ---------------- static device scratch ----------------
__device__ float g_q  [MTOK*DMODEL];
__device__ float g_k  [MTOK*DMODEL];
__device__ float g_v  [MTOK*DMODEL];
__device__ float g_ctx[MTOK*DMODEL];
__device__ float g_x1 [MTOK*DMODEL];
__device__ float g_ff [MTOK*DFF];
__device__ float g_ln1[MTOK*2];
__device__ float g_ln2[MTOK*2];
// transposed fp16 weights: wh[n][k]
__device__ __half g_whq[DMODEL*DMODEL];
__device__ __half g_whk[DMODEL*DMODEL];
__device__ __half g_whv[DMODEL*DMODEL];
__device__ __half g_who[DMODEL*DMODEL];
__device__ __half g_wh1[DFF*DMODEL];    // w1:[1024,4096] -> [4096][1024]
__device__ __half g_wh2[DMODEL*DFF];    // w2:[4096,1024] -> [1024][4096]

__device__ __forceinline__ uint32_t smem_u32(const void* p) {
    uint32_t a;
    asm("{ .reg .u64 t; cvta.to.shared.u64 t, %1; cvt.u32.u64 %0, t; }" : "=r"(a) : "l"(p));
    return a;
}
__device__ __forceinline__ void cp_async16(uint32_t saddr, const void* gaddr) {
    asm volatile("cp.async.cg.shared.global [%0], [%1], 16;" :: "r"(saddr), "l"(gaddr) : "memory");
}
#define CP_COMMIT() asm volatile("cp.async.commit_group;" ::: "memory")
#define CP_WAIT0()  asm volatile("cp.async.wait_group 0;" ::: "memory")

__device__ __forceinline__ float to_tf32(float x) {
    uint32_t r;
    asm("cvt.rna.tf32.f32 %0, %1;" : "=r"(r) : "f"(x));
    return __uint_as_float(r);
}
__device__ __forceinline__ uint32_t pack_h2(float a, float b) {
    __half2 h = __floats2half2_rn(a, b);
    return *(uint32_t*)&h;
}

// fp16 mma m16n8k16, fp32 accumulate
__device__ __forceinline__ void mma16816(float* d, const uint32_t* a, const uint32_t* b, const float* c) {
    asm volatile(
        "mma.sync.aligned.m16n8k16.row.col.f32.f16.f16.f32 "
        "{%0,%1,%2,%3}, {%4,%5,%6,%7}, {%8,%9}, {%10,%11,%12,%13};"
        : "=f"(d[0]), "=f"(d[1]), "=f"(d[2]), "=f"(d[3])
        : "r"(a[0]), "r"(a[1]), "r"(a[2]), "r"(a[3]),
          "r"(b[0]), "r"(b[1]),
          "f"(c[0]), "f"(c[1]), "f"(c[2]), "f"(c[3]));
}
// tf32 mma m16n8k8 (flash attention)
__device__ __forceinline__ void mma16n8k8(float* d, const uint32_t* a, const uint32_t* b, const float* c) {
    asm volatile(
        "mma.sync.aligned.m16n8k8.row.col.f32.tf32.tf32.f32 "
        "{%0,%1,%2,%3}, {%4,%5,%6,%7}, {%8,%9}, {%10,%11,%12,%13};"
        : "=f"(d[0]), "=f"(d[1]), "=f"(d[2]), "=f"(d[3])
        : "r"(a[0]), "r"(a[1]), "r"(a[2]), "r"(a[3]),
          "r"(b[0]), "r"(b[1]),
          "f"(c[0]), "f"(c[1]), "f"(c[2]), "f"(c[3]));
}

// ---------------- weight convert: out[n][k] = fp16(W[k][n]) ----------------
__global__ __launch_bounds__(256) void wconv(const float* __restrict__ W,
                                             __half* __restrict__ out,
                                             int K, int N)
{
    __shared__ float tile[64][65];
    const int k0 = blockIdx.y * 64;
    const int n0 = blockIdx.x * 64;
    const int tid = threadIdx.x;
    const int kl = tid >> 4;
    const int nl = (tid & 15) * 4;
    #pragma unroll
    for (int i = 0; i < 4; i++) {
        int kk = kl + i * 16;
        float4 v = *(const float4*)&W[(size_t)(k0 + kk) * N + n0 + nl];
        tile[kk][nl] = v.x; tile[kk][nl+1] = v.y; tile[kk][nl+2] = v.z; tile[kk][nl+3] = v.w;
    }
    __syncthreads();
    const int n = tid >> 2;
    const int ks = (tid & 3) * 16;
    uint32_t h[8];
    #pragma unroll
    for (int j = 0; j < 8; j++)
        h[j] = pack_h2(tile[ks + 2*j][n], tile[ks + 2*j + 1][n]);
    __half* orow = out + (size_t)(n0 + n) * K + k0 + ks;
    *(uint4*)orow = *(uint4*)&h[0];
    *(uint4*)(orow + 8) = *(uint4*)&h[4];
}

// ---------------- LN stats ----------------
__global__ __launch_bounds__(256) void ln_stats(const float* __restrict__ x,
                                                float* __restrict__ st,
                                                const float* __restrict__ alpha,
                                                const float* __restrict__ beta)
{
    const int row = blockIdx.x;
    const int tid = threadIdx.x;
    const float* xr = x + (size_t)row * DMODEL;
    float4 v = *(const float4*)&xr[tid * 4];

    float s1 = v.x + v.y + v.z + v.w;
    float s2 = v.x*v.x + v.y*v.y + v.z*v.z + v.w*v.w;
    for (int o = 16; o > 0; o >>= 1) {
        s1 += __shfl_down_sync(0xffffffffu, s1, o);
        s2 += __shfl_down_sync(0xffffffffu, s2, o);
    }
    __shared__ float ws1[8], ws2[8];
    int lane = tid & 31, wid = tid >> 5;
    if (lane == 0) { ws1[wid] = s1; ws2[wid] = s2; }
    __syncthreads();
    if (tid == 0) {
        float a = 0.f, b = 0.f;
        #pragma unroll
        for (int i = 0; i < 8; i++) { a += ws1[i]; b += ws2[i]; }
        float mean = a * (1.0f / DMODEL);
        float var  = (b - (float)DMODEL * mean * mean) * (1.0f / (DMODEL - 1));
        var = fmaxf(var, 0.0f);
        float s = alpha[0] / (sqrtf(var) + LNEPS);
        float t = beta[0] - mean * s;
        *(float2*)&st[row * 2] = make_float2(s, t);
    }
}

// =============================================================================
// FP16 GEMM: C = A*Wh^T + bias (+res)(relu); A fp32 (cvt at staging, optional LN),
// Wh pre-transposed fp16 [n][k] staged via cp.async. Tile 128x128, BK=32.
// =============================================================================
#define LDA_H 20   // words (16 data + 4 pad), 16B-multiple
#define LDB_H 20
#define GEMMH_SMEM ((2*128*LDA_H + 2*128*LDB_H) * 4)

template<int RELU, int RES, int LNA, int QKV>
__global__ __launch_bounds__(256, 2) void gemm_h(const float* __restrict__ A,
                                                 const __half* __restrict__ Wh0,
                                                 const __half* __restrict__ Wh1,
                                                 const __half* __restrict__ Wh2,
                                                 const float* __restrict__ bias0,
                                                 const float* __restrict__ bias1,
                                                 const float* __restrict__ bias2,
                                                 const float* __restrict__ res,
                                                 const float* __restrict__ lnst,
                                                 float* __restrict__ C0,
                                                 float* __restrict__ C1,
                                                 float* __restrict__ C2,
                                                 int K, int N)
{
    extern __shared__ uint32_t smh[];
    uint32_t* As32 = smh;                      // [2][128][LDA_H]
    uint32_t* Bs32 = smh + 2 * 128 * LDA_H;    // [2][128][LDB_H]
    const uint32_t BsB = smem_u32(Bs32);

    const int tid = threadIdx.x;
    const int warpId = tid >> 5;
    const int lane = tid & 31;
    const int g = lane >> 2;
    const int t4 = lane & 3;
    const int row0 = blockIdx.y * 128;

    const __half* Wh = Wh0;
    const float* bias = bias0;
    float* C = C0;
    int col0;
    if (QKV) {
        const int sel = blockIdx.x >> 3;
        col0 = (blockIdx.x & 7) * 128;
        if (sel == 1) { Wh = Wh1; bias = bias1; C = C1; }
        else if (sel == 2) { Wh = Wh2; bias = bias2; C = C2; }
    } else {
        col0 = blockIdx.x * 128;
    }

    const int wr = warpId & 1;
    const int wc = warpId >> 1;

    float acc[4][4][4];
    #pragma unroll
    for (int i = 0; i < 4; i++)
        #pragma unroll
        for (int j = 0; j < 4; j++)
            #pragma unroll
            for (int r = 0; r < 4; r++) acc[i][j][r] = 0.f;

    // staging maps
    const int aRow = tid >> 1;           // 0..127
    const int aHalf = tid & 1;           // which 16-float half of the 32-k chunk
    const int bRow = tid >> 1;           // 0..127 (n)
    const int bPart = tid & 1;

    float sA = 1.f, tA = 0.f;
    if (LNA) {
        float2 st = *(const float2*)&lnst[(row0 + aRow) * 2];
        sA = st.x; tA = st.y;
    }

    const float* aBase = A + (size_t)(row0 + aRow) * K + aHalf * 16;
    const __half* bBase = Wh + (size_t)(col0 + bRow) * K + bPart * 16;

    const int nChunks = K / 32;

    // helper lambdas (inlined by compiler)
    auto stageA = [&](const float4* v4, int buf) {
        uint32_t h[8];
        #pragma unroll
        for (int i = 0; i < 4; i++) {
            float4 v = v4[i];
            if (LNA) {
                v.x = fmaf(v.x, sA, tA); v.y = fmaf(v.y, sA, tA);
                v.z = fmaf(v.z, sA, tA); v.w = fmaf(v.w, sA, tA);
            }
            h[i*2]   = pack_h2(v.x, v.y);
            h[i*2+1] = pack_h2(v.z, v.w);
        }
        uint32_t* d = &As32[buf * 128 * LDA_H + aRow * LDA_H + aHalf * 8];
        *(uint4*)d = *(uint4*)&h[0];
        *(uint4*)(d + 4) = *(uint4*)&h[4];
    };

    // ---- prologue chunk 0 ----
    {
        float4 v4[4];
        #pragma unroll
        for (int i = 0; i < 4; i++) v4[i] = *(const float4*)(aBase + i * 4);
        stageA(v4, 0);
        cp_async16(BsB + (bRow * LDB_H + bPart * 8) * 4, bBase);
        cp_async16(BsB + (bRow * LDB_H + bPart * 8 + 4) * 4, bBase + 8);
        CP_COMMIT();
        CP_WAIT0();
    }
    __syncthreads();

    float4 ra[4];
    for (int c = 0; c < nChunks; c++) {
        const int buf = c & 1;
        const int nb = 1 - buf;
        if (c + 1 < nChunks) {
            const int k0 = (c + 1) * 32;
            #pragma unroll
            for (int i = 0; i < 4; i++) ra[i] = *(const float4*)(aBase + k0 + i * 4);
            cp_async16(BsB + (nb * 128 * LDB_H + bRow * LDB_H + bPart * 8) * 4, bBase + k0);
            cp_async16(BsB + (nb * 128 * LDB_H + bRow * LDB_H + bPart * 8 + 4) * 4, bBase + k0 + 8);
            CP_COMMIT();
        }

        const uint32_t* Ab = As32 + buf * 128 * LDA_H;
        const uint32_t* Bb = Bs32 + buf * 128 * LDB_H;

        #pragma unroll
        for (int s = 0; s < 2; s++) {
            const int kw = s * 8;
            uint32_t af[4][4];
            uint32_t bf[4][2];
            #pragma unroll
            for (int mi = 0; mi < 4; mi++) {
                const int r = wr * 64 + mi * 16 + g;
                af[mi][0] = Ab[r * LDA_H + kw + t4];
                af[mi][1] = Ab[(r + 8) * LDA_H + kw + t4];
                af[mi][2] = Ab[r * LDA_H + kw + t4 + 4];
                af[mi][3] = Ab[(r + 8) * LDA_H + kw + t4 + 4];
            }
            #pragma unroll
            for (int ni = 0; ni < 4; ni++) {
                const int n = wc * 32 + ni * 8 + g;
                bf[ni][0] = Bb[n * LDB_H + kw + t4];
                bf[ni][1] = Bb[n * LDB_H + kw + t4 + 4];
            }
            #pragma unroll
            for (int mi = 0; mi < 4; mi++)
                #pragma unroll
                for (int ni = 0; ni < 4; ni++)
                    mma16816(acc[mi][ni], af[mi], bf[ni], acc[mi][ni]);
        }

        __syncthreads();
        if (c + 1 < nChunks) {
            stageA(ra, nb);
            CP_WAIT0();
            __syncthreads();
        }
    }

    // ---- epilogue ----
    #pragma unroll
    for (int mi = 0; mi < 4; mi++) {
        #pragma unroll
        for (int half = 0; half < 2; half++) {
            const int gr = row0 + wr * 64 + mi * 16 + g + half * 8;
            float* crow = C + (size_t)gr * N;
            const float* rrow = RES ? (res + (size_t)gr * N) : nullptr;
            #pragma unroll
            for (int ni = 0; ni < 4; ni++) {
                const int gc = col0 + wc * 32 + ni * 8 + t4 * 2;
                float2 o;
                o.x = acc[mi][ni][half * 2 + 0];
                o.y = acc[mi][ni][half * 2 + 1];
                float2 bb = *(const float2*)&bias[gc];
                o.x += bb.x; o.y += bb.y;
                if (RES) {
                    float2 rr = *(const float2*)&rrow[gc];
                    o.x += rr.x; o.y += rr.y;
                }
                if (RELU) {
                    o.x = fmaxf(o.x, 0.f);
                    o.y = fmaxf(o.y, 0.f);
                }
                *(float2*)&crow[gc] = o;
            }
        }
    }
}

// =============================================================================
// Flash attention (tf32 mma, online softmax) — R9 proven version
// =============================================================================
#define LDQ 68
#define LDK 68
#define LDV 72
#define LDP 68
#define FA_Q_OFF 0
#define FA_K_OFF (128*LDQ)
#define FA_V_OFF (FA_K_OFF + 64*LDK)
#define FA_P_OFF (FA_V_OFF + 64*LDV)
#define FA_SMEM  ((FA_P_OFF + 8*16*LDP) * 4)

__global__ __launch_bounds__(256, 2) void flash_attn(const float* __restrict__ q,
                                                     const float* __restrict__ k,
                                                     const float* __restrict__ v,
                                                     const int* __restrict__ mask,
                                                     float* __restrict__ ctx)
{
    extern __shared__ float fsm[];
    float* Qs = fsm + FA_Q_OFF;
    float* Ks = fsm + FA_K_OFF;
    float* Vs = fsm + FA_V_OFF;

    const int bh = blockIdx.y;
    const int b = bh >> 4;
    const int h = bh & 15;
    const int hbase = h * DK;
    const int q0 = blockIdx.x * 128;
    const int tid = threadIdx.x;
    const int warpId = tid >> 5;
    const int lane = tid & 31;
    const int g = lane >> 2;
    const int t4 = lane & 3;

    float* Pw = fsm + FA_P_OFF + warpId * 16 * LDP;

    {
        const int row = tid >> 1;
        const int c0 = (tid & 1) * 32;
        const float* src = q + (size_t)(b * SEQ + q0 + row) * DMODEL + hbase + c0;
        float* dst = &Qs[row * LDQ + c0];
        #pragma unroll
        for (int i = 0; i < 8; i++) {
            float4 x = *(const float4*)(src + i * 4);
            float4 y;
            y.x = to_tf32(x.x); y.y = to_tf32(x.y); y.z = to_tf32(x.z); y.w = to_tf32(x.w);
            *(float4*)(dst + i * 4) = y;
        }
    }
    __syncthreads();

    float mprev0 = -1e30f, mprev1 = -1e30f;
    float l0 = 0.f, l1 = 0.f;
    float oacc[8][4];
    #pragma unroll
    for (int i = 0; i < 8; i++)
        #pragma unroll
        for (int j = 0; j < 4; j++) oacc[i][j] = 0.f;

    const int r0g = q0 + warpId * 16 + g;
    const size_t maskBase = (size_t)b * SEQ * SEQ;

    for (int jt = 0; jt < SEQ / 64; jt++) {
        const int j0 = jt * 64;
        {
            const int row = tid >> 2;
            const int c0 = (tid & 3) * 16;
            const float* ksrc = k + (size_t)(b * SEQ + j0 + row) * DMODEL + hbase + c0;
            const float* vsrc = v + (size_t)(b * SEQ + j0 + row) * DMODEL + hbase + c0;
            float* kdst = &Ks[row * LDK + c0];
            float* vdst = &Vs[row * LDV + c0];
            #pragma unroll
            for (int i = 0; i < 4; i++) {
                float4 x = *(const float4*)(ksrc + i * 4);
                float4 y;
                y.x = to_tf32(x.x); y.y = to_tf32(x.y); y.z = to_tf32(x.z); y.w = to_tf32(x.w);
                *(float4*)(kdst + i * 4) = y;
                float4 xv = *(const float4*)(vsrc + i * 4);
                float4 yv;
                yv.x = to_tf32(xv.x); yv.y = to_tf32(xv.y); yv.z = to_tf32(xv.z); yv.w = to_tf32(xv.w);
                *(float4*)(vdst + i * 4) = yv;
            }
        }
        __syncthreads();

        float s[8][4];
        #pragma unroll
        for (int nt = 0; nt < 8; nt++)
            #pragma unroll
            for (int r = 0; r < 4; r++) s[nt][r] = 0.f;

        const uint32_t* Qb = (const uint32_t*)Qs;
        const uint32_t* Kb = (const uint32_t*)Ks;
        #pragma unroll
        for (int k8 = 0; k8 < 8; k8++) {
            const int kb = k8 * 8;
            uint32_t af[4];
            const int qr = warpId * 16 + g;
            af[0] = Qb[qr * LDQ + kb + t4];
            af[1] = Qb[(qr + 8) * LDQ + kb + t4];
            af[2] = Qb[qr * LDQ + kb + t4 + 4];
            af[3] = Qb[(qr + 8) * LDQ + kb + t4 + 4];
            #pragma unroll
            for (int nt = 0; nt < 8; nt++) {
                uint32_t bf[2];
                bf[0] = Kb[(nt * 8 + g) * LDK + kb + t4];
                bf[1] = Kb[(nt * 8 + g) * LDK + kb + t4 + 4];
                mma16n8k8(s[nt], af, bf, s[nt]);
            }
        }

        float mc0 = -1e30f, mc1 = -1e30f;
        #pragma unroll
        for (int nt = 0; nt < 8; nt++) {
            const int col = j0 + nt * 8 + 2 * t4;
            int2 m0 = *(const int2*)&mask[maskBase + (size_t)r0g * SEQ + col];
            int2 m1 = *(const int2*)&mask[maskBase + (size_t)(r0g + 8) * SEQ + col];
            s[nt][0] = (m0.x == 0) ? -1e9f : s[nt][0] * 0.125f;
            s[nt][1] = (m0.y == 0) ? -1e9f : s[nt][1] * 0.125f;
            s[nt][2] = (m1.x == 0) ? -1e9f : s[nt][2] * 0.125f;
            s[nt][3] = (m1.y == 0) ? -1e9f : s[nt][3] * 0.125f;
            mc0 = fmaxf(mc0, fmaxf(s[nt][0], s[nt][1]));
            mc1 = fmaxf(mc1, fmaxf(s[nt][2], s[nt][3]));
        }
        mc0 = fmaxf(mc0, __shfl_xor_sync(0xffffffffu, mc0, 1));
        mc0 = fmaxf(mc0, __shfl_xor_sync(0xffffffffu, mc0, 2));
        mc1 = fmaxf(mc1, __shfl_xor_sync(0xffffffffu, mc1, 1));
        mc1 = fmaxf(mc1, __shfl_xor_sync(0xffffffffu, mc1, 2));

        const float mn0 = fmaxf(mprev0, mc0);
        const float mn1 = fmaxf(mprev1, mc1);
        const float a0 = __expf(mprev0 - mn0);
        const float a1 = __expf(mprev1 - mn1);

        float lc0 = 0.f, lc1 = 0.f;
        #pragma unroll
        for (int nt = 0; nt < 8; nt++) {
            float p0 = __expf(s[nt][0] - mn0);
            float p1 = __expf(s[nt][1] - mn0);
            float p2 = __expf(s[nt][2] - mn1);
            float p3 = __expf(s[nt][3] - mn1);
            lc0 += p0 + p1;
            lc1 += p2 + p3;
            float2 w0; w0.x = to_tf32(p0); w0.y = to_tf32(p1);
            float2 w1; w1.x = to_tf32(p2); w1.y = to_tf32(p3);
            *(float2*)&Pw[g * LDP + nt * 8 + 2 * t4] = w0;
            *(float2*)&Pw[(g + 8) * LDP + nt * 8 + 2 * t4] = w1;
        }
        lc0 += __shfl_xor_sync(0xffffffffu, lc0, 1);
        lc0 += __shfl_xor_sync(0xffffffffu, lc0, 2);
        lc1 += __shfl_xor_sync(0xffffffffu, lc1, 1);
        lc1 += __shfl_xor_sync(0xffffffffu, lc1, 2);
        l0 = l0 * a0 + lc0;
        l1 = l1 * a1 + lc1;

        #pragma unroll
        for (int dn = 0; dn < 8; dn++) {
            oacc[dn][0] *= a0; oacc[dn][1] *= a0;
            oacc[dn][2] *= a1; oacc[dn][3] *= a1;
        }
        mprev0 = mn0; mprev1 = mn1;

        __syncwarp();

        const uint32_t* Pb = (const uint32_t*)Pw;
        const uint32_t* Vb = (const uint32_t*)Vs;
        #pragma unroll
        for (int j8 = 0; j8 < 8; j8++) {
            const int kb = j8 * 8;
            uint32_t af[4];
            af[0] = Pb[g * LDP + kb + t4];
            af[1] = Pb[(g + 8) * LDP + kb + t4];
            af[2] = Pb[g * LDP + kb + t4 + 4];
            af[3] = Pb[(g + 8) * LDP + kb + t4 + 4];
            #pragma unroll
            for (int dn = 0; dn < 8; dn++) {
                uint32_t bf[2];
                bf[0] = Vb[(kb + t4) * LDV + dn * 8 + g];
                bf[1] = Vb[(kb + t4 + 4) * LDV + dn * 8 + g];
                mma16n8k8(oacc[dn], af, bf, oacc[dn]);
            }
        }
        __syncthreads();
    }

    const float inv0 = 1.0f / l0;
    const float inv1 = 1.0f / l1;
    float* c0row = ctx + (size_t)(b * SEQ + r0g) * DMODEL + hbase;
    float* c1row = ctx + (size_t)(b * SEQ + r0g + 8) * DMODEL + hbase;
    #pragma unroll
    for (int dn = 0; dn < 8; dn++) {
        const int dc = dn * 8 + 2 * t4;
        float2 w0; w0.x = oacc[dn][0] * inv0; w0.y = oacc[dn][1] * inv0;
        float2 w1; w1.x = oacc[dn][2] * inv1; w1.y = oacc[dn][3] * inv1;
        *(float2*)&c0row[dc] = w0;
        *(float2*)&c1row[dc] = w1;
    }
}

// ---------------- launch ----------------
extern "C" void kernel_launch(void* const* d_in, const int* in_sizes, int n_in,
                              void* d_out, int out_size)
{
    const float* x    = (const float*)d_in[0];
    const int*   mask = (const int*)  d_in[1];
    const float* wq = (const float*)d_in[2];  const float* bq = (const float*)d_in[3];
    const float* wk = (const float*)d_in[4];  const float* bk = (const float*)d_in[5];
    const float* wv = (const float*)d_in[6];  const float* bv = (const float*)d_in[7];
    const float* wo = (const float*)d_in[8];  const float* bo = (const float*)d_in[9];
    const float* w1 = (const float*)d_in[10]; const float* b1 = (const float*)d_in[11];
    const float* w2 = (const float*)d_in[12]; const float* b2 = (const float*)d_in[13];
    const float* ln1_a = (const float*)d_in[14]; const float* ln1_b = (const float*)d_in[15];
    const float* ln2_a = (const float*)d_in[16]; const float* ln2_b = (const float*)d_in[17];
    float* out = (float*)d_out;

    float *p_q, *p_k, *p_v, *p_ctx, *p_x1, *p_ff, *p_l1, *p_l2;
    __half *p_whq, *p_whk, *p_whv, *p_who, *p_wh1, *p_wh2;
    cudaGetSymbolAddress((void**)&p_q,  g_q);
    cudaGetSymbolAddress((void**)&p_k,  g_k);
    cudaGetSymbolAddress((void**)&p_v,  g_v);
    cudaGetSymbolAddress((void**)&p_ctx,g_ctx);
    cudaGetSymbolAddress((void**)&p_x1, g_x1);
    cudaGetSymbolAddress((void**)&p_ff, g_ff);
    cudaGetSymbolAddress((void**)&p_l1, g_ln1);
    cudaGetSymbolAddress((void**)&p_l2, g_ln2);
    cudaGetSymbolAddress((void**)&p_whq, g_whq);
    cudaGetSymbolAddress((void**)&p_whk, g_whk);
    cudaGetSymbolAddress((void**)&p_whv, g_whv);
    cudaGetSymbolAddress((void**)&p_who, g_who);
    cudaGetSymbolAddress((void**)&p_wh1, g_wh1);
    cudaGetSymbolAddress((void**)&p_wh2, g_wh2);

    cudaFuncSetAttribute(gemm_h<0,0,1,1>, cudaFuncAttributeMaxDynamicSharedMemorySize, GEMMH_SMEM);
    cudaFuncSetAttribute(gemm_h<0,1,0,0>, cudaFuncAttributeMaxDynamicSharedMemorySize, GEMMH_SMEM);
    cudaFuncSetAttribute(gemm_h<1,0,1,0>, cudaFuncAttributeMaxDynamicSharedMemorySize, GEMMH_SMEM);
    cudaFuncSetAttribute(flash_attn, cudaFuncAttributeMaxDynamicSharedMemorySize, FA_SMEM);

    // 0) weight conversion (fp32 [K][N] -> fp16 [N][K])
    wconv<<<dim3(DMODEL/64, DMODEL/64), 256>>>(wq, p_whq, DMODEL, DMODEL);
    wconv<<<dim3(DMODEL/64, DMODEL/64), 256>>>(wk, p_whk, DMODEL, DMODEL);
    wconv<<<dim3(DMODEL/64, DMODEL/64), 256>>>(wv, p_whv, DMODEL, DMODEL);
    wconv<<<dim3(DMODEL/64, DMODEL/64), 256>>>(wo, p_who, DMODEL, DMODEL);
    wconv<<<dim3(DFF/64, DMODEL/64), 256>>>(w1, p_wh1, DMODEL, DFF);
    wconv<<<dim3(DMODEL/64, DFF/64), 256>>>(w2, p_wh2, DFF, DMODEL);

    // 1) LN1 stats
    ln_stats<<<MTOK, 256>>>(x, p_l1, ln1_a, ln1_b);

    // 2) Fused QKV projection (LN applied in staging)
    gemm_h<0,0,1,1><<<dim3(24, MTOK / 128), 256, GEMMH_SMEM>>>(
        x, p_whq, p_whk, p_whv, bq, bk, bv, nullptr, p_l1, p_q, p_k, p_v, DMODEL, DMODEL);

    // 3) fused attention -> ctx (merged heads)
    flash_attn<<<dim3(SEQ / 128, BATCH * NHEADS), 256, FA_SMEM>>>(p_q, p_k, p_v, mask, p_ctx);

    // 4) O projection + residual -> x1
    gemm_h<0,1,0,0><<<dim3(8, MTOK / 128), 256, GEMMH_SMEM>>>(
        p_ctx, p_who, nullptr, nullptr, bo, nullptr, nullptr, x, nullptr,
        p_x1, nullptr, nullptr, DMODEL, DMODEL);

    // 5) LN2 stats
    ln_stats<<<MTOK, 256>>>(p_x1, p_l2, ln2_a, ln2_b);

    // 6) FFN1 + ReLU (LN applied in staging)
    gemm_h<1,0,1,0><<<dim3(DFF / 128, MTOK / 128), 256, GEMMH_SMEM>>>(
        p_x1, p_wh1, nullptr, nullptr, b1, nullptr, nullptr, nullptr, p_l2,
        p_ff, nullptr, nullptr, DMODEL, DFF);

    // 7) FFN2 + residual -> out
    gemm_h<0,1,0,0><<<dim3(8, MTOK / 128), 256, GEMMH_SMEM>>>(
        p_ff, p_wh2, nullptr, nullptr, b2, nullptr, nullptr, p_x1, nullptr,
        out, nullptr, nullptr, DFF, DMODEL);
}

// round 14
// speedup vs baseline: 3.7819x; 1.0966x over previous
#include <cuda_runtime.h>
#include <cuda_fp16.h>
#include <math.h>
#include <cstdint>

// Problem constants
#define BATCH 2
#define SEQ   2048
#define DMODEL 1024
#define NHEADS 16
#define DK    64
#define DFF   4096
#define MTOK  (BATCH*SEQ)
#define LNEPS 1e-6f

// ---------------- static device scratch ----------------
__device__ float g_q  [MTOK*DMODEL];
__device__ float g_k  [MTOK*DMODEL];
__device__ float g_v  [MTOK*DMODEL];
__device__ float g_ctx[MTOK*DMODEL];
__device__ float g_x1 [MTOK*DMODEL];
__device__ float g_ff [MTOK*DFF];
__device__ float g_ln1[MTOK*2];
__device__ float g_ln2[MTOK*2];
// transposed fp16 weights: wh[n][k]
__device__ __half g_whq[DMODEL*DMODEL];
__device__ __half g_whk[DMODEL*DMODEL];
__device__ __half g_whv[DMODEL*DMODEL];
__device__ __half g_who[DMODEL*DMODEL];
__device__ __half g_wh1[DFF*DMODEL];
__device__ __half g_wh2[DMODEL*DFF];

__device__ __forceinline__ uint32_t smem_u32(const void* p) {
    uint32_t a;
    asm("{ .reg .u64 t; cvta.to.shared.u64 t, %1; cvt.u32.u64 %0, t; }" : "=r"(a) : "l"(p));
    return a;
}
__device__ __forceinline__ void cp_async16(uint32_t saddr, const void* gaddr) {
    asm volatile("cp.async.cg.shared.global [%0], [%1], 16;" :: "r"(saddr), "l"(gaddr) : "memory");
}
#define CP_COMMIT() asm volatile("cp.async.commit_group;" ::: "memory")
#define CP_WAIT0()  asm volatile("cp.async.wait_group 0;" ::: "memory")

__device__ __forceinline__ float to_tf32(float x) {
    uint32_t r;
    asm("cvt.rna.tf32.f32 %0, %1;" : "=r"(r) : "f"(x));
    return __uint_as_float(r);
}
__device__ __forceinline__ uint32_t pack_h2(float a, float b) {
    __half2 h = __floats2half2_rn(a, b);
    return *(uint32_t*)&h;
}
__device__ __forceinline__ void ldsm_x4(uint32_t* r, uint32_t a) {
    asm volatile("ldmatrix.sync.aligned.m8n8.x4.shared.b16 {%0,%1,%2,%3}, [%4];"
        : "=r"(r[0]), "=r"(r[1]), "=r"(r[2]), "=r"(r[3]) : "r"(a));
}

// fp16 mma m16n8k16, fp32 accumulate
__device__ __forceinline__ void mma16816(float* d, const uint32_t* a, const uint32_t* b, const float* c) {
    asm volatile(
        "mma.sync.aligned.m16n8k16.row.col.f32.f16.f16.f32 "
        "{%0,%1,%2,%3}, {%4,%5,%6,%7}, {%8,%9}, {%10,%11,%12,%13};"
        : "=f"(d[0]), "=f"(d[1]), "=f"(d[2]), "=f"(d[3])
        : "r"(a[0]), "r"(a[1]), "r"(a[2]), "r"(a[3]),
          "r"(b[0]), "r"(b[1]),
          "f"(c[0]), "f"(c[1]), "f"(c[2]), "f"(c[3]));
}
// tf32 mma m16n8k8 (flash attention)
__device__ __forceinline__ void mma16n8k8(float* d, const uint32_t* a, const uint32_t* b, const float* c) {
    asm volatile(
        "mma.sync.aligned.m16n8k8.row.col.f32.tf32.tf32.f32 "
        "{%0,%1,%2,%3}, {%4,%5,%6,%7}, {%8,%9}, {%10,%11,%12,%13};"
        : "=f"(d[0]), "=f"(d[1]), "=f"(d[2]), "=f"(d[3])
        : "r"(a[0]), "r"(a[1]), "r"(a[2]), "r"(a[3]),
          "r"(b[0]), "r"(b[1]),
          "f"(c[0]), "f"(c[1]), "f"(c[2]), "f"(c[3]));
}

// ---------------- weight convert: out[n][k] = fp16(W[k][n]) ----------------
__global__ __launch_bounds__(256) void wconv(const float* __restrict__ W,
                                             __half* __restrict__ out,
                                             int K, int N)
{
    __shared__ float tile[64][65];
    const int k0 = blockIdx.y * 64;
    const int n0 = blockIdx.x * 64;
    const int tid = threadIdx.x;
    const int kl = tid >> 4;
    const int nl = (tid & 15) * 4;
    #pragma unroll
    for (int i = 0; i < 4; i++) {
        int kk = kl + i * 16;
        float4 v = *(const float4*)&W[(size_t)(k0 + kk) * N + n0 + nl];
        tile[kk][nl] = v.x; tile[kk][nl+1] = v.y; tile[kk][nl+2] = v.z; tile[kk][nl+3] = v.w;
    }
    __syncthreads();
    const int n = tid >> 2;
    const int ks = (tid & 3) * 16;
    uint32_t h[8];
    #pragma unroll
    for (int j = 0; j < 8; j++)
        h[j] = pack_h2(tile[ks + 2*j][n], tile[ks + 2*j + 1][n]);
    __half* orow = out + (size_t)(n0 + n) * K + k0 + ks;
    *(uint4*)orow = *(uint4*)&h[0];
    *(uint4*)(orow + 8) = *(uint4*)&h[4];
}

// ---------------- LN stats ----------------
__global__ __launch_bounds__(256) void ln_stats(const float* __restrict__ x,
                                                float* __restrict__ st,
                                                const float* __restrict__ alpha,
                                                const float* __restrict__ beta)
{
    const int row = blockIdx.x;
    const int tid = threadIdx.x;
    const float* xr = x + (size_t)row * DMODEL;
    float4 v = *(const float4*)&xr[tid * 4];

    float s1 = v.x + v.y + v.z + v.w;
    float s2 = v.x*v.x + v.y*v.y + v.z*v.z + v.w*v.w;
    for (int o = 16; o > 0; o >>= 1) {
        s1 += __shfl_down_sync(0xffffffffu, s1, o);
        s2 += __shfl_down_sync(0xffffffffu, s2, o);
    }
    __shared__ float ws1[8], ws2[8];
    int lane = tid & 31, wid = tid >> 5;
    if (lane == 0) { ws1[wid] = s1; ws2[wid] = s2; }
    __syncthreads();
    if (tid == 0) {
        float a = 0.f, b = 0.f;
        #pragma unroll
        for (int i = 0; i < 8; i++) { a += ws1[i]; b += ws2[i]; }
        float mean = a * (1.0f / DMODEL);
        float var  = (b - (float)DMODEL * mean * mean) * (1.0f / (DMODEL - 1));
        var = fmaxf(var, 0.0f);
        float s = alpha[0] / (sqrtf(var) + LNEPS);
        float t = beta[0] - mean * s;
        *(float2*)&st[row * 2] = make_float2(s, t);
    }
}

// =============================================================================
// FP16 GEMM with ldmatrix: C = A*Wh^T + bias (+res)(relu); optional LN on A.
// Tile 128x128, BK=32. A fp32->fp16 at staging; B pre-transposed fp16 via cp.async.
// =============================================================================
#define LDA_H 20   // words per A smem row (16 data + 4 pad)
#define LDB_H 20
#define GEMMH_SMEM ((2*128*LDA_H + 2*128*LDB_H) * 4)

template<int RELU, int RES, int LNA, int QKV>
__global__ __launch_bounds__(256, 2) void gemm_h(const float* __restrict__ A,
                                                 const __half* __restrict__ Wh0,
                                                 const __half* __restrict__ Wh1,
                                                 const __half* __restrict__ Wh2,
                                                 const float* __restrict__ bias0,
                                                 const float* __restrict__ bias1,
                                                 const float* __restrict__ bias2,
                                                 const float* __restrict__ res,
                                                 const float* __restrict__ lnst,
                                                 float* __restrict__ C0,
                                                 float* __restrict__ C1,
                                                 float* __restrict__ C2,
                                                 int K, int N)
{
    extern __shared__ uint32_t smh[];
    uint32_t* As32 = smh;                      // [2][128][LDA_H]
    uint32_t* Bs32 = smh + 2 * 128 * LDA_H;    // [2][128][LDB_H]
    const uint32_t AsByte = smem_u32(As32);
    const uint32_t BsByte = smem_u32(Bs32);

    const int tid = threadIdx.x;
    const int warpId = tid >> 5;
    const int lane = tid & 31;
    const int g = lane >> 2;
    const int t4 = lane & 3;
    const int l8 = lane & 7;
    const int sub = lane >> 3;
    const int row0 = blockIdx.y * 128;

    const __half* Wh = Wh0;
    const float* bias = bias0;
    float* C = C0;
    int col0;
    if (QKV) {
        const int sel = blockIdx.x >> 3;
        col0 = (blockIdx.x & 7) * 128;
        if (sel == 1) { Wh = Wh1; bias = bias1; C = C1; }
        else if (sel == 2) { Wh = Wh2; bias = bias2; C = C2; }
    } else {
        col0 = blockIdx.x * 128;
    }

    const int wr = warpId & 1;
    const int wc = warpId >> 1;

    float acc[4][4][4];
    #pragma unroll
    for (int i = 0; i < 4; i++)
        #pragma unroll
        for (int j = 0; j < 4; j++)
            #pragma unroll
            for (int r = 0; r < 4; r++) acc[i][j][r] = 0.f;

    const int aRow = tid >> 1;
    const int aHalf = tid & 1;
    const int bRow = tid >> 1;
    const int bPart = tid & 1;

    float sA = 1.f, tA = 0.f;
    if (LNA) {
        float2 st = *(const float2*)&lnst[(row0 + aRow) * 2];
        sA = st.x; tA = st.y;
    }

    const float* aBase = A + (size_t)(row0 + aRow) * K + aHalf * 16;
    const __half* bBase = Wh + (size_t)(col0 + bRow) * K + bPart * 16;

    const int nChunks = K / 32;

    auto stageA = [&](const float4* v4, int buf) {
        uint32_t h[8];
        #pragma unroll
        for (int i = 0; i < 4; i++) {
            float4 v = v4[i];
            if (LNA) {
                v.x = fmaf(v.x, sA, tA); v.y = fmaf(v.y, sA, tA);
                v.z = fmaf(v.z, sA, tA); v.w = fmaf(v.w, sA, tA);
            }
            h[i*2]   = pack_h2(v.x, v.y);
            h[i*2+1] = pack_h2(v.z, v.w);
        }
        uint32_t* d = &As32[buf * 128 * LDA_H + aRow * LDA_H + aHalf * 8];
        *(uint4*)d = *(uint4*)&h[0];
        *(uint4*)(d + 4) = *(uint4*)&h[4];
    };

    // prologue chunk 0
    {
        float4 v4[4];
        #pragma unroll
        for (int i = 0; i < 4; i++) v4[i] = *(const float4*)(aBase + i * 4);
        stageA(v4, 0);
        cp_async16(BsByte + (bRow * LDB_H + bPart * 8) * 4, bBase);
        cp_async16(BsByte + (bRow * LDB_H + bPart * 8 + 4) * 4, bBase + 8);
        CP_COMMIT();
        CP_WAIT0();
    }
    __syncthreads();

    float4 ra[4];
    for (int c = 0; c < nChunks; c++) {
        const int buf = c & 1;
        const int nb = 1 - buf;
        if (c + 1 < nChunks) {
            const int k0 = (c + 1) * 32;
            #pragma unroll
            for (int i = 0; i < 4; i++) ra[i] = *(const float4*)(aBase + k0 + i * 4);
            cp_async16(BsByte + (nb * 128 * LDB_H + bRow * LDB_H + bPart * 8) * 4, bBase + k0);
            cp_async16(BsByte + (nb * 128 * LDB_H + bRow * LDB_H + bPart * 8 + 4) * 4, bBase + k0 + 8);
            CP_COMMIT();
        }

        const uint32_t AbB = AsByte + buf * 128 * LDA_H * 4;
        const uint32_t BbB = BsByte + buf * 128 * LDB_H * 4;

        #pragma unroll
        for (int s = 0; s < 2; s++) {
            const int kh = s * 16;   // halves
            uint32_t af[4][4];
            uint32_t bf[4][2];
            #pragma unroll
            for (int mi = 0; mi < 4; mi++) {
                uint32_t a = AbB + (uint32_t)(wr * 64 + mi * 16 + l8 + (sub & 1) * 8) * (LDA_H * 4)
                           + (kh + (sub >> 1) * 8) * 2;
                ldsm_x4(af[mi], a);
            }
            #pragma unroll
            for (int pi = 0; pi < 2; pi++) {
                uint32_t a = BbB + (uint32_t)(wc * 32 + pi * 16 + l8 + (sub >> 1) * 8) * (LDB_H * 4)
                           + (kh + (sub & 1) * 8) * 2;
                uint32_t bb[4];
                ldsm_x4(bb, a);
                bf[pi*2][0] = bb[0]; bf[pi*2][1] = bb[1];
                bf[pi*2+1][0] = bb[2]; bf[pi*2+1][1] = bb[3];
            }
            #pragma unroll
            for (int mi = 0; mi < 4; mi++)
                #pragma unroll
                for (int ni = 0; ni < 4; ni++)
                    mma16816(acc[mi][ni], af[mi], bf[ni], acc[mi][ni]);
        }

        __syncthreads();
        if (c + 1 < nChunks) {
            stageA(ra, nb);
            CP_WAIT0();
            __syncthreads();
        }
    }

    // epilogue
    #pragma unroll
    for (int mi = 0; mi < 4; mi++) {
        #pragma unroll
        for (int half = 0; half < 2; half++) {
            const int gr = row0 + wr * 64 + mi * 16 + g + half * 8;
            float* crow = C + (size_t)gr * N;
            const float* rrow = RES ? (res + (size_t)gr * N) : nullptr;
            #pragma unroll
            for (int ni = 0; ni < 4; ni++) {
                const int gc = col0 + wc * 32 + ni * 8 + t4 * 2;
                float ox = acc[mi][ni][half * 2 + 0];
                float oy = acc[mi][ni][half * 2 + 1];
                float2 bb = *(const float2*)&bias[gc];
                ox += bb.x; oy += bb.y;
                if (RES) {
                    float2 rr = *(const float2*)&rrow[gc];
                    ox += rr.x; oy += rr.y;
                }
                if (RELU) {
                    ox = fmaxf(ox, 0.f);
                    oy = fmaxf(oy, 0.f);
                }
                *(float2*)&crow[gc] = make_float2(ox, oy);
            }
        }
    }
}

// =============================================================================
// Flash attention (tf32 mma, online softmax) — R11 proven version
// =============================================================================
#define LDQ 68
#define LDK 68
#define LDV 72
#define LDP 68
#define FA_Q_OFF 0
#define FA_K_OFF (128*LDQ)
#define FA_V_OFF (FA_K_OFF + 64*LDK)
#define FA_P_OFF (FA_V_OFF + 64*LDV)
#define FA_SMEM  ((FA_P_OFF + 8*16*LDP) * 4)

__global__ __launch_bounds__(256, 2) void flash_attn(const float* __restrict__ q,
                                                     const float* __restrict__ k,
                                                     const float* __restrict__ v,
                                                     const int* __restrict__ mask,
                                                     float* __restrict__ ctx)
{
    extern __shared__ float fsm[];
    float* Qs = fsm + FA_Q_OFF;
    float* Ks = fsm + FA_K_OFF;
    float* Vs = fsm + FA_V_OFF;

    const int bh = blockIdx.y;
    const int b = bh >> 4;
    const int h = bh & 15;
    const int hbase = h * DK;
    const int q0 = blockIdx.x * 128;
    const int tid = threadIdx.x;
    const int warpId = tid >> 5;
    const int lane = tid & 31;
    const int g = lane >> 2;
    const int t4 = lane & 3;

    float* Pw = fsm + FA_P_OFF + warpId * 16 * LDP;

    {
        const int row = tid >> 1;
        const int c0 = (tid & 1) * 32;
        const float* src = q + (size_t)(b * SEQ + q0 + row) * DMODEL + hbase + c0;
        float* dst = &Qs[row * LDQ + c0];
        #pragma unroll
        for (int i = 0; i < 8; i++) {
            float4 x = *(const float4*)(src + i * 4);
            float4 y;
            y.x = to_tf32(x.x); y.y = to_tf32(x.y); y.z = to_tf32(x.z); y.w = to_tf32(x.w);
            *(float4*)(dst + i * 4) = y;
        }
    }
    __syncthreads();

    float mprev0 = -1e30f, mprev1 = -1e30f;
    float l0 = 0.f, l1 = 0.f;
    float oacc[8][4];
    #pragma unroll
    for (int i = 0; i < 8; i++)
        #pragma unroll
        for (int j = 0; j < 4; j++) oacc[i][j] = 0.f;

    const int r0g = q0 + warpId * 16 + g;
    const size_t maskBase = (size_t)b * SEQ * SEQ;

    for (int jt = 0; jt < SEQ / 64; jt++) {
        const int j0 = jt * 64;
        {
            const int row = tid >> 2;
            const int c0 = (tid & 3) * 16;
            const float* ksrc = k + (size_t)(b * SEQ + j0 + row) * DMODEL + hbase + c0;
            const float* vsrc = v + (size_t)(b * SEQ + j0 + row) * DMODEL + hbase + c0;
            float* kdst = &Ks[row * LDK + c0];
            float* vdst = &Vs[row * LDV + c0];
            #pragma unroll
            for (int i = 0; i < 4; i++) {
                float4 x = *(const float4*)(ksrc + i * 4);
                float4 y;
                y.x = to_tf32(x.x); y.y = to_tf32(x.y); y.z = to_tf32(x.z); y.w = to_tf32(x.w);
                *(float4*)(kdst + i * 4) = y;
                float4 xv = *(const float4*)(vsrc + i * 4);
                float4 yv;
                yv.x = to_tf32(xv.x); yv.y = to_tf32(xv.y); yv.z = to_tf32(xv.z); yv.w = to_tf32(xv.w);
                *(float4*)(vdst + i * 4) = yv;
            }
        }
        __syncthreads();

        float s[8][4];
        #pragma unroll
        for (int nt = 0; nt < 8; nt++)
            #pragma unroll
            for (int r = 0; r < 4; r++) s[nt][r] = 0.f;

        const uint32_t* Qb = (const uint32_t*)Qs;
        const uint32_t* Kb = (const uint32_t*)Ks;
        #pragma unroll
        for (int k8 = 0; k8 < 8; k8++) {
            const int kb = k8 * 8;
            uint32_t af[4];
            const int qr = warpId * 16 + g;
            af[0] = Qb[qr * LDQ + kb + t4];
            af[1] = Qb[(qr + 8) * LDQ + kb + t4];
            af[2] = Qb[qr * LDQ + kb + t4 + 4];
            af[3] = Qb[(qr + 8) * LDQ + kb + t4 + 4];
            #pragma unroll
            for (int nt = 0; nt < 8; nt++) {
                uint32_t bf[2];
                bf[0] = Kb[(nt * 8 + g) * LDK + kb + t4];
                bf[1] = Kb[(nt * 8 + g) * LDK + kb + t4 + 4];
                mma16n8k8(s[nt], af, bf, s[nt]);
            }
        }

        float mc0 = -1e30f, mc1 = -1e30f;
        #pragma unroll
        for (int nt = 0; nt < 8; nt++) {
            const int col = j0 + nt * 8 + 2 * t4;
            int2 m0 = *(const int2*)&mask[maskBase + (size_t)r0g * SEQ + col];
            int2 m1 = *(const int2*)&mask[maskBase + (size_t)(r0g + 8) * SEQ + col];
            s[nt][0] = (m0.x == 0) ? -1e9f : s[nt][0] * 0.125f;
            s[nt][1] = (m0.y == 0) ? -1e9f : s[nt][1] * 0.125f;
            s[nt][2] = (m1.x == 0) ? -1e9f : s[nt][2] * 0.125f;
            s[nt][3] = (m1.y == 0) ? -1e9f : s[nt][3] * 0.125f;
            mc0 = fmaxf(mc0, fmaxf(s[nt][0], s[nt][1]));
            mc1 = fmaxf(mc1, fmaxf(s[nt][2], s[nt][3]));
        }
        mc0 = fmaxf(mc0, __shfl_xor_sync(0xffffffffu, mc0, 1));
        mc0 = fmaxf(mc0, __shfl_xor_sync(0xffffffffu, mc0, 2));
        mc1 = fmaxf(mc1, __shfl_xor_sync(0xffffffffu, mc1, 1));
        mc1 = fmaxf(mc1, __shfl_xor_sync(0xffffffffu, mc1, 2));

        const float mn0 = fmaxf(mprev0, mc0);
        const float mn1 = fmaxf(mprev1, mc1);
        const float a0 = __expf(mprev0 - mn0);
        const float a1 = __expf(mprev1 - mn1);

        float lc0 = 0.f, lc1 = 0.f;
        #pragma unroll
        for (int nt = 0; nt < 8; nt++) {
            float p0 = __expf(s[nt][0] - mn0);
            float p1 = __expf(s[nt][1] - mn0);
            float p2 = __expf(s[nt][2] - mn1);
            float p3 = __expf(s[nt][3] - mn1);
            lc0 += p0 + p1;
            lc1 += p2 + p3;
            float2 w0; w0.x = to_tf32(p0); w0.y = to_tf32(p1);
            float2 w1; w1.x = to_tf32(p2); w1.y = to_tf32(p3);
            *(float2*)&Pw[g * LDP + nt * 8 + 2 * t4] = w0;
            *(float2*)&Pw[(g + 8) * LDP + nt * 8 + 2 * t4] = w1;
        }
        lc0 += __shfl_xor_sync(0xffffffffu, lc0, 1);
        lc0 += __shfl_xor_sync(0xffffffffu, lc0, 2);
        lc1 += __shfl_xor_sync(0xffffffffu, lc1, 1);
        lc1 += __shfl_xor_sync(0xffffffffu, lc1, 2);
        l0 = l0 * a0 + lc0;
        l1 = l1 * a1 + lc1;

        #pragma unroll
        for (int dn = 0; dn < 8; dn++) {
            oacc[dn][0] *= a0; oacc[dn][1] *= a0;
            oacc[dn][2] *= a1; oacc[dn][3] *= a1;
        }
        mprev0 = mn0; mprev1 = mn1;

        __syncwarp();

        const uint32_t* Pb = (const uint32_t*)Pw;
        const uint32_t* Vb = (const uint32_t*)Vs;
        #pragma unroll
        for (int j8 = 0; j8 < 8; j8++) {
            const int kb = j8 * 8;
            uint32_t af[4];
            af[0] = Pb[g * LDP + kb + t4];
            af[1] = Pb[(g + 8) * LDP + kb + t4];
            af[2] = Pb[g * LDP + kb + t4 + 4];
            af[3] = Pb[(g + 8) * LDP + kb + t4 + 4];
            #pragma unroll
            for (int dn = 0; dn < 8; dn++) {
                uint32_t bf[2];
                bf[0] = Vb[(kb + t4) * LDV + dn * 8 + g];
                bf[1] = Vb[(kb + t4 + 4) * LDV + dn * 8 + g];
                mma16n8k8(oacc[dn], af, bf, oacc[dn]);
            }
        }
        __syncthreads();
    }

    const float inv0 = 1.0f / l0;
    const float inv1 = 1.0f / l1;
    float* c0row = ctx + (size_t)(b * SEQ + r0g) * DMODEL + hbase;
    float* c1row = ctx + (size_t)(b * SEQ + r0g + 8) * DMODEL + hbase;
    #pragma unroll
    for (int dn = 0; dn < 8; dn++) {
        const int dc = dn * 8 + 2 * t4;
        *(float2*)&c0row[dc] = make_float2(oacc[dn][0] * inv0, oacc[dn][1] * inv0);
        *(float2*)&c1row[dc] = make_float2(oacc[dn][2] * inv1, oacc[dn][3] * inv1);
    }
}

// ---------------- launch ----------------
extern "C" void kernel_launch(void* const* d_in, const int* in_sizes, int n_in,
                              void* d_out, int out_size)
{
    const float* x    = (const float*)d_in[0];
    const int*   mask = (const int*)  d_in[1];
    const float* wq = (const float*)d_in[2];  const float* bq = (const float*)d_in[3];
    const float* wk = (const float*)d_in[4];  const float* bk = (const float*)d_in[5];
    const float* wv = (const float*)d_in[6];  const float* bv = (const float*)d_in[7];
    const float* wo = (const float*)d_in[8];  const float* bo = (const float*)d_in[9];
    const float* w1 = (const float*)d_in[10]; const float* b1 = (const float*)d_in[11];
    const float* w2 = (const float*)d_in[12]; const float* b2 = (const float*)d_in[13];
    const float* ln1_a = (const float*)d_in[14]; const float* ln1_b = (const float*)d_in[15];
    const float* ln2_a = (const float*)d_in[16]; const float* ln2_b = (const float*)d_in[17];
    float* out = (float*)d_out;

    float *p_q, *p_k, *p_v, *p_ctx, *p_x1, *p_ff, *p_l1, *p_l2;
    __half *p_whq, *p_whk, *p_whv, *p_who, *p_wh1, *p_wh2;
    cudaGetSymbolAddress((void**)&p_q,  g_q);
    cudaGetSymbolAddress((void**)&p_k,  g_k);
    cudaGetSymbolAddress((void**)&p_v,  g_v);
    cudaGetSymbolAddress((void**)&p_ctx,g_ctx);
    cudaGetSymbolAddress((void**)&p_x1, g_x1);
    cudaGetSymbolAddress((void**)&p_ff, g_ff);
    cudaGetSymbolAddress((void**)&p_l1, g_ln1);
    cudaGetSymbolAddress((void**)&p_l2, g_ln2);
    cudaGetSymbolAddress((void**)&p_whq, g_whq);
    cudaGetSymbolAddress((void**)&p_whk, g_whk);
    cudaGetSymbolAddress((void**)&p_whv, g_whv);
    cudaGetSymbolAddress((void**)&p_who, g_who);
    cudaGetSymbolAddress((void**)&p_wh1, g_wh1);
    cudaGetSymbolAddress((void**)&p_wh2, g_wh2);

    cudaFuncSetAttribute(gemm_h<0,0,1,1>, cudaFuncAttributeMaxDynamicSharedMemorySize, GEMMH_SMEM);
    cudaFuncSetAttribute(gemm_h<0,1,0,0>, cudaFuncAttributeMaxDynamicSharedMemorySize, GEMMH_SMEM);
    cudaFuncSetAttribute(gemm_h<1,0,1,0>, cudaFuncAttributeMaxDynamicSharedMemorySize, GEMMH_SMEM);
    cudaFuncSetAttribute(flash_attn, cudaFuncAttributeMaxDynamicSharedMemorySize, FA_SMEM);

    // 0) weight conversion
    wconv<<<dim3(DMODEL/64, DMODEL/64), 256>>>(wq, p_whq, DMODEL, DMODEL);
    wconv<<<dim3(DMODEL/64, DMODEL/64), 256>>>(wk, p_whk, DMODEL, DMODEL);
    wconv<<<dim3(DMODEL/64, DMODEL/64), 256>>>(wv, p_whv, DMODEL, DMODEL);
    wconv<<<dim3(DMODEL/64, DMODEL/64), 256>>>(wo, p_who, DMODEL, DMODEL);
    wconv<<<dim3(DFF/64, DMODEL/64), 256>>>(w1, p_wh1, DMODEL, DFF);
    wconv<<<dim3(DMODEL/64, DFF/64), 256>>>(w2, p_wh2, DFF, DMODEL);

    // 1) LN1 stats
    ln_stats<<<MTOK, 256>>>(x, p_l1, ln1_a, ln1_b);

    // 2) QKV projection (LN fused)
    gemm_h<0,0,1,1><<<dim3(24, MTOK / 128), 256, GEMMH_SMEM>>>(
        x, p_whq, p_whk, p_whv, bq, bk, bv, nullptr, p_l1, p_q, p_k, p_v, DMODEL, DMODEL);

    // 3) flash attention
    flash_attn<<<dim3(SEQ / 128, BATCH * NHEADS), 256, FA_SMEM>>>(p_q, p_k, p_v, mask, p_ctx);

    // 4) O projection + residual
    gemm_h<0,1,0,0><<<dim3(8, MTOK / 128), 256, GEMMH_SMEM>>>(
        p_ctx, p_who, nullptr, nullptr, bo, nullptr, nullptr, x, nullptr,
        p_x1, nullptr, nullptr, DMODEL, DMODEL);

    // 5) LN2 stats
    ln_stats<<<MTOK, 256>>>(p_x1, p_l2, ln2_a, ln2_b);

    // 6) FFN1 + ReLU (LN fused)
    gemm_h<1,0,1,0><<<dim3(DFF / 128, MTOK / 128), 256, GEMMH_SMEM>>>(
        p_x1, p_wh1, nullptr, nullptr, b1, nullptr, nullptr, nullptr, p_l2,
        p_ff, nullptr, nullptr, DMODEL, DFF);

    // 7) FFN2 + residual -> out
    gemm_h<0,1,0,0><<<dim3(8, MTOK / 128), 256, GEMMH_SMEM>>>(
        p_ff, p_wh2, nullptr, nullptr, b2, nullptr, nullptr, p_x1, nullptr,
        out, nullptr, nullptr, DFF, DMODEL);
}

// round 16
// speedup vs baseline: 3.9508x; 1.0447x over previous
#include <cuda_runtime.h>
#include <cuda_fp16.h>
#include <math.h>
#include <cstdint>

// Problem constants
#define BATCH 2
#define SEQ   2048
#define DMODEL 1024
#define NHEADS 16
#define DK    64
#define DFF   4096
#define MTOK  (BATCH*SEQ)
#define LNEPS 1e-6f

// ---------------- static device scratch ----------------
__device__ float  g_q  [MTOK*DMODEL];
__device__ float  g_k  [MTOK*DMODEL];
__device__ float  g_v  [MTOK*DMODEL];
__device__ __half g_ctxh[MTOK*DMODEL];
__device__ float  g_x1 [MTOK*DMODEL];
__device__ __half g_ffh[MTOK*DFF];
__device__ float  g_ln1[MTOK*2];
__device__ float  g_ln2[MTOK*2];
// transposed fp16 weights: wh[n][k]
__device__ __half g_whq[DMODEL*DMODEL];
__device__ __half g_whk[DMODEL*DMODEL];
__device__ __half g_whv[DMODEL*DMODEL];
__device__ __half g_who[DMODEL*DMODEL];
__device__ __half g_wh1[DFF*DMODEL];
__device__ __half g_wh2[DMODEL*DFF];

__device__ __forceinline__ uint32_t smem_u32(const void* p) {
    uint32_t a;
    asm("{ .reg .u64 t; cvta.to.shared.u64 t, %1; cvt.u32.u64 %0, t; }" : "=r"(a) : "l"(p));
    return a;
}
__device__ __forceinline__ void cp_async16(uint32_t saddr, const void* gaddr) {
    asm volatile("cp.async.cg.shared.global [%0], [%1], 16;" :: "r"(saddr), "l"(gaddr) : "memory");
}
#define CP_COMMIT() asm volatile("cp.async.commit_group;" ::: "memory")
#define CP_WAIT0()  asm volatile("cp.async.wait_group 0;" ::: "memory")

__device__ __forceinline__ float to_tf32(float x) {
    uint32_t r;
    asm("cvt.rna.tf32.f32 %0, %1;" : "=r"(r) : "f"(x));
    return __uint_as_float(r);
}
__device__ __forceinline__ uint32_t pack_h2(float a, float b) {
    __half2 h = __floats2half2_rn(a, b);
    return *(uint32_t*)&h;
}
__device__ __forceinline__ void ldsm_x4(uint32_t* r, uint32_t a) {
    asm volatile("ldmatrix.sync.aligned.m8n8.x4.shared.b16 {%0,%1,%2,%3}, [%4];"
        : "=r"(r[0]), "=r"(r[1]), "=r"(r[2]), "=r"(r[3]) : "r"(a));
}

// fp16 mma m16n8k16, fp32 accumulate
__device__ __forceinline__ void mma16816(float* d, const uint32_t* a, const uint32_t* b, const float* c) {
    asm volatile(
        "mma.sync.aligned.m16n8k16.row.col.f32.f16.f16.f32 "
        "{%0,%1,%2,%3}, {%4,%5,%6,%7}, {%8,%9}, {%10,%11,%12,%13};"
        : "=f"(d[0]), "=f"(d[1]), "=f"(d[2]), "=f"(d[3])
        : "r"(a[0]), "r"(a[1]), "r"(a[2]), "r"(a[3]),
          "r"(b[0]), "r"(b[1]),
          "f"(c[0]), "f"(c[1]), "f"(c[2]), "f"(c[3]));
}
// tf32 mma m16n8k8 (flash attention)
__device__ __forceinline__ void mma16n8k8(float* d, const uint32_t* a, const uint32_t* b, const float* c) {
    asm volatile(
        "mma.sync.aligned.m16n8k8.row.col.f32.tf32.tf32.f32 "
        "{%0,%1,%2,%3}, {%4,%5,%6,%7}, {%8,%9}, {%10,%11,%12,%13};"
        : "=f"(d[0]), "=f"(d[1]), "=f"(d[2]), "=f"(d[3])
        : "r"(a[0]), "r"(a[1]), "r"(a[2]), "r"(a[3]),
          "r"(b[0]), "r"(b[1]),
          "f"(c[0]), "f"(c[1]), "f"(c[2]), "f"(c[3]));
}

__device__ __forceinline__ void store2(float* p, float x, float y) {
    *(float2*)p = make_float2(x, y);
}
__device__ __forceinline__ void store2(__half* p, float x, float y) {
    *(uint32_t*)p = pack_h2(x, y);
}

// ---------------- weight convert: out[n][k] = fp16(W[k][n]) ----------------
__device__ __forceinline__ void wconv_body(const float* __restrict__ W,
                                           __half* __restrict__ out,
                                           int K, int N, int bx, int by)
{
    __shared__ float tile[64][65];
    const int k0 = by * 64;
    const int n0 = bx * 64;
    const int tid = threadIdx.x;
    const int kl = tid >> 4;
    const int nl = (tid & 15) * 4;
    #pragma unroll
    for (int i = 0; i < 4; i++) {
        int kk = kl + i * 16;
        float4 v = *(const float4*)&W[(size_t)(k0 + kk) * N + n0 + nl];
        tile[kk][nl] = v.x; tile[kk][nl+1] = v.y; tile[kk][nl+2] = v.z; tile[kk][nl+3] = v.w;
    }
    __syncthreads();
    const int n = tid >> 2;
    const int ks = (tid & 3) * 16;
    uint32_t h[8];
    #pragma unroll
    for (int j = 0; j < 8; j++)
        h[j] = pack_h2(tile[ks + 2*j][n], tile[ks + 2*j + 1][n]);
    __half* orow = out + (size_t)(n0 + n) * K + k0 + ks;
    *(uint4*)orow = *(uint4*)&h[0];
    *(uint4*)(orow + 8) = *(uint4*)&h[4];
}

__global__ __launch_bounds__(256) void wconv(const float* __restrict__ W,
                                             __half* __restrict__ out,
                                             int K, int N)
{
    wconv_body(W, out, K, N, blockIdx.x, blockIdx.y);
}

__global__ __launch_bounds__(256) void wconv4(const float* __restrict__ W0, __half* __restrict__ O0,
                                              const float* __restrict__ W1, __half* __restrict__ O1,
                                              const float* __restrict__ W2, __half* __restrict__ O2,
                                              const float* __restrict__ W3, __half* __restrict__ O3)
{
    const float* W; __half* O;
    switch (blockIdx.z) {
        case 0: W = W0; O = O0; break;
        case 1: W = W1; O = O1; break;
        case 2: W = W2; O = O2; break;
        default: W = W3; O = O3; break;
    }
    wconv_body(W, O, DMODEL, DMODEL, blockIdx.x, blockIdx.y);
}

// ---------------- LN stats ----------------
__global__ __launch_bounds__(256) void ln_stats(const float* __restrict__ x,
                                                float* __restrict__ st,
                                                const float* __restrict__ alpha,
                                                const float* __restrict__ beta)
{
    const int row = blockIdx.x;
    const int tid = threadIdx.x;
    const float* xr = x + (size_t)row * DMODEL;
    float4 v = *(const float4*)&xr[tid * 4];

    float s1 = v.x + v.y + v.z + v.w;
    float s2 = v.x*v.x + v.y*v.y + v.z*v.z + v.w*v.w;
    for (int o = 16; o > 0; o >>= 1) {
        s1 += __shfl_down_sync(0xffffffffu, s1, o);
        s2 += __shfl_down_sync(0xffffffffu, s2, o);
    }
    __shared__ float ws1[8], ws2[8];
    int lane = tid & 31, wid = tid >> 5;
    if (lane == 0) { ws1[wid] = s1; ws2[wid] = s2; }
    __syncthreads();
    if (tid == 0) {
        float a = 0.f, b = 0.f;
        #pragma unroll
        for (int i = 0; i < 8; i++) { a += ws1[i]; b += ws2[i]; }
        float mean = a * (1.0f / DMODEL);
        float var  = (b - (float)DMODEL * mean * mean) * (1.0f / (DMODEL - 1));
        var = fmaxf(var, 0.0f);
        float s = alpha[0] / (sqrtf(var) + LNEPS);
        float t = beta[0] - mean * s;
        *(float2*)&st[row * 2] = make_float2(s, t);
    }
}

// =============================================================================
// FP16 GEMM with ldmatrix. A: fp32 (+optional LN, register path) when AH=0,
// fp16 gmem via cp.async when AH=1. R14-proven double-barrier pipeline.
// =============================================================================
#define LDA_H 20
#define LDB_H 20
#define GEMMH_SMEM ((2*128*LDA_H + 2*128*LDB_H) * 4)

template<int RELU, int RES, int LNA, int QKV, int AH, typename TOut>
__global__ __launch_bounds__(256, 2) void gemm_h(const float* __restrict__ Af,
                                                 const __half* __restrict__ Ah,
                                                 const __half* __restrict__ Wh0,
                                                 const __half* __restrict__ Wh1,
                                                 const __half* __restrict__ Wh2,
                                                 const float* __restrict__ bias0,
                                                 const float* __restrict__ bias1,
                                                 const float* __restrict__ bias2,
                                                 const float* __restrict__ res,
                                                 const float* __restrict__ lnst,
                                                 TOut* __restrict__ C0,
                                                 TOut* __restrict__ C1,
                                                 TOut* __restrict__ C2,
                                                 int K, int N)
{
    extern __shared__ uint32_t smh[];
    uint32_t* As32 = smh;                      // [2][128][LDA_H]
    uint32_t* Bs32 = smh + 2 * 128 * LDA_H;    // [2][128][LDB_H]
    const uint32_t AsByte = smem_u32(As32);
    const uint32_t BsByte = smem_u32(Bs32);

    const int tid = threadIdx.x;
    const int warpId = tid >> 5;
    const int lane = tid & 31;
    const int g = lane >> 2;
    const int t4 = lane & 3;
    const int l8 = lane & 7;
    const int sub = lane >> 3;
    const int row0 = blockIdx.y * 128;

    const __half* Wh = Wh0;
    const float* bias = bias0;
    TOut* C = C0;
    int col0;
    if (QKV) {
        const int sel = blockIdx.x >> 3;
        col0 = (blockIdx.x & 7) * 128;
        if (sel == 1) { Wh = Wh1; bias = bias1; C = C1; }
        else if (sel == 2) { Wh = Wh2; bias = bias2; C = C2; }
    } else {
        col0 = blockIdx.x * 128;
    }

    const int wr = warpId & 1;
    const int wc = warpId >> 1;

    float acc[4][4][4];
    #pragma unroll
    for (int i = 0; i < 4; i++)
        #pragma unroll
        for (int j = 0; j < 4; j++)
            #pragma unroll
            for (int r = 0; r < 4; r++) acc[i][j][r] = 0.f;

    const int aRow = tid >> 1;
    const int aHalf = tid & 1;
    const int bRow = tid >> 1;
    const int bPart = tid & 1;

    float sA = 1.f, tA = 0.f;
    if (LNA) {
        float2 st = *(const float2*)&lnst[(row0 + aRow) * 2];
        sA = st.x; tA = st.y;
    }

    const float*  aBaseF = AH ? nullptr : (Af + (size_t)(row0 + aRow) * K + aHalf * 16);
    const __half* aBaseH = AH ? (Ah + (size_t)(row0 + aRow) * K + aHalf * 16) : nullptr;
    const __half* bBase  = Wh + (size_t)(col0 + bRow) * K + bPart * 16;

    const int nChunks = K / 32;

    auto stageA = [&](const float4* v4, int buf) {
        uint32_t h[8];
        #pragma unroll
        for (int i = 0; i < 4; i++) {
            float4 v = v4[i];
            if (LNA) {
                v.x = fmaf(v.x, sA, tA); v.y = fmaf(v.y, sA, tA);
                v.z = fmaf(v.z, sA, tA); v.w = fmaf(v.w, sA, tA);
            }
            h[i*2]   = pack_h2(v.x, v.y);
            h[i*2+1] = pack_h2(v.z, v.w);
        }
        uint32_t* d = &As32[buf * 128 * LDA_H + aRow * LDA_H + aHalf * 8];
        *(uint4*)d = *(uint4*)&h[0];
        *(uint4*)(d + 4) = *(uint4*)&h[4];
    };

    // ---- prologue chunk 0 ----
    {
        if (AH) {
            cp_async16(AsByte + (aRow * LDA_H + aHalf * 8) * 4, aBaseH);
            cp_async16(AsByte + (aRow * LDA_H + aHalf * 8 + 4) * 4, aBaseH + 8);
        } else {
            float4 v4[4];
            #pragma unroll
            for (int i = 0; i < 4; i++) v4[i] = *(const float4*)(aBaseF + i * 4);
            stageA(v4, 0);
        }
        cp_async16(BsByte + (bRow * LDB_H + bPart * 8) * 4, bBase);
        cp_async16(BsByte + (bRow * LDB_H + bPart * 8 + 4) * 4, bBase + 8);
        CP_COMMIT();
        CP_WAIT0();
    }
    __syncthreads();

    float4 ra[4];
    for (int c = 0; c < nChunks; c++) {
        const int buf = c & 1;
        const int nb = 1 - buf;
        const bool hasNext = (c + 1 < nChunks);
        if (hasNext) {
            const int k0 = (c + 1) * 32;
            if (AH) {
                cp_async16(AsByte + (nb * 128 * LDA_H + aRow * LDA_H + aHalf * 8) * 4, aBaseH + k0);
                cp_async16(AsByte + (nb * 128 * LDA_H + aRow * LDA_H + aHalf * 8 + 4) * 4, aBaseH + k0 + 8);
            } else {
                #pragma unroll
                for (int i = 0; i < 4; i++) ra[i] = *(const float4*)(aBaseF + k0 + i * 4);
            }
            cp_async16(BsByte + (nb * 128 * LDB_H + bRow * LDB_H + bPart * 8) * 4, bBase + k0);
            cp_async16(BsByte + (nb * 128 * LDB_H + bRow * LDB_H + bPart * 8 + 4) * 4, bBase + k0 + 8);
            CP_COMMIT();
        }

        const uint32_t AbB = AsByte + buf * 128 * LDA_H * 4;
        const uint32_t BbB = BsByte + buf * 128 * LDB_H * 4;

        #pragma unroll
        for (int s = 0; s < 2; s++) {
            const int kh = s * 16;
            uint32_t af[4][4];
            uint32_t bf[4][2];
            #pragma unroll
            for (int mi = 0; mi < 4; mi++) {
                uint32_t a = AbB + (uint32_t)(wr * 64 + mi * 16 + l8 + (sub & 1) * 8) * (LDA_H * 4)
                           + (kh + (sub >> 1) * 8) * 2;
                ldsm_x4(af[mi], a);
            }
            #pragma unroll
            for (int pi = 0; pi < 2; pi++) {
                uint32_t a = BbB + (uint32_t)(wc * 32 + pi * 16 + l8 + (sub >> 1) * 8) * (LDB_H * 4)
                           + (kh + (sub & 1) * 8) * 2;
                uint32_t bb[4];
                ldsm_x4(bb, a);
                bf[pi*2][0] = bb[0]; bf[pi*2][1] = bb[1];
                bf[pi*2+1][0] = bb[2]; bf[pi*2+1][1] = bb[3];
            }
            #pragma unroll
            for (int mi = 0; mi < 4; mi++)
                #pragma unroll
                for (int ni = 0; ni < 4; ni++)
                    mma16816(acc[mi][ni], af[mi], bf[ni], acc[mi][ni]);
        }

        __syncthreads();
        if (hasNext) {
            if (!AH) stageA(ra, nb);
            CP_WAIT0();
            __syncthreads();
        }
    }

    // ---- epilogue ----
    #pragma unroll
    for (int mi = 0; mi < 4; mi++) {
        #pragma unroll
        for (int half = 0; half < 2; half++) {
            const int gr = row0 + wr * 64 + mi * 16 + g + half * 8;
            TOut* crow = C + (size_t)gr * N;
            const float* rrow = RES ? (res + (size_t)gr * N) : nullptr;
            #pragma unroll
            for (int ni = 0; ni < 4; ni++) {
                const int gc = col0 + wc * 32 + ni * 8 + t4 * 2;
                float ox = acc[mi][ni][half * 2 + 0];
                float oy = acc[mi][ni][half * 2 + 1];
                float2 bb = *(const float2*)&bias[gc];
                ox += bb.x; oy += bb.y;
                if (RES) {
                    float2 rr = *(const float2*)&rrow[gc];
                    ox += rr.x; oy += rr.y;
                }
                if (RELU) {
                    ox = fmaxf(ox, 0.f);
                    oy = fmaxf(oy, 0.f);
                }
                store2(&crow[gc], ox, oy);
            }
        }
    }
}

// =============================================================================
// Flash attention (tf32 mma, online softmax) — R14-proven body, fp16 ctx out.
// =============================================================================
#define LDQ 68
#define LDK 68
#define LDV 72
#define LDP 68
#define FA_Q_OFF 0
#define FA_K_OFF (128*LDQ)
#define FA_V_OFF (FA_K_OFF + 64*LDK)
#define FA_P_OFF (FA_V_OFF + 64*LDV)
#define FA_SMEM  ((FA_P_OFF + 8*16*LDP) * 4)

__global__ __launch_bounds__(256, 2) void flash_attn(const float* __restrict__ q,
                                                     const float* __restrict__ k,
                                                     const float* __restrict__ v,
                                                     const int* __restrict__ mask,
                                                     __half* __restrict__ ctx)
{
    extern __shared__ float fsm[];
    float* Qs = fsm + FA_Q_OFF;
    float* Ks = fsm + FA_K_OFF;
    float* Vs = fsm + FA_V_OFF;

    const int bh = blockIdx.y;
    const int b = bh >> 4;
    const int h = bh & 15;
    const int hbase = h * DK;
    const int q0 = blockIdx.x * 128;
    const int tid = threadIdx.x;
    const int warpId = tid >> 5;
    const int lane = tid & 31;
    const int g = lane >> 2;
    const int t4 = lane & 3;

    float* Pw = fsm + FA_P_OFF + warpId * 16 * LDP;

    {
        const int row = tid >> 1;
        const int c0 = (tid & 1) * 32;
        const float* src = q + (size_t)(b * SEQ + q0 + row) * DMODEL + hbase + c0;
        float* dst = &Qs[row * LDQ + c0];
        #pragma unroll
        for (int i = 0; i < 8; i++) {
            float4 x = *(const float4*)(src + i * 4);
            float4 y;
            y.x = to_tf32(x.x); y.y = to_tf32(x.y); y.z = to_tf32(x.z); y.w = to_tf32(x.w);
            *(float4*)(dst + i * 4) = y;
        }
    }
    __syncthreads();

    float mprev0 = -1e30f, mprev1 = -1e30f;
    float l0 = 0.f, l1 = 0.f;
    float oacc[8][4];
    #pragma unroll
    for (int i = 0; i < 8; i++)
        #pragma unroll
        for (int j = 0; j < 4; j++) oacc[i][j] = 0.f;

    const int r0g = q0 + warpId * 16 + g;
    const size_t maskBase = (size_t)b * SEQ * SEQ;

    for (int jt = 0; jt < SEQ / 64; jt++) {
        const int j0 = jt * 64;
        {
            const int row = tid >> 2;
            const int c0 = (tid & 3) * 16;
            const float* ksrc = k + (size_t)(b * SEQ + j0 + row) * DMODEL + hbase + c0;
            const float* vsrc = v + (size_t)(b * SEQ + j0 + row) * DMODEL + hbase + c0;
            float* kdst = &Ks[row * LDK + c0];
            float* vdst = &Vs[row * LDV + c0];
            #pragma unroll
            for (int i = 0; i < 4; i++) {
                float4 x = *(const float4*)(ksrc + i * 4);
                float4 y;
                y.x = to_tf32(x.x); y.y = to_tf32(x.y); y.z = to_tf32(x.z); y.w = to_tf32(x.w);
                *(float4*)(kdst + i * 4) = y;
                float4 xv = *(const float4*)(vsrc + i * 4);
                float4 yv;
                yv.x = to_tf32(xv.x); yv.y = to_tf32(xv.y); yv.z = to_tf32(xv.z); yv.w = to_tf32(xv.w);
                *(float4*)(vdst + i * 4) = yv;
            }
        }
        __syncthreads();

        float s[8][4];
        #pragma unroll
        for (int nt = 0; nt < 8; nt++)
            #pragma unroll
            for (int r = 0; r < 4; r++) s[nt][r] = 0.f;

        const uint32_t* Qb = (const uint32_t*)Qs;
        const uint32_t* Kb = (const uint32_t*)Ks;
        #pragma unroll
        for (int k8 = 0; k8 < 8; k8++) {
            const int kb = k8 * 8;
            uint32_t af[4];
            const int qr = warpId * 16 + g;
            af[0] = Qb[qr * LDQ + kb + t4];
            af[1] = Qb[(qr + 8) * LDQ + kb + t4];
            af[2] = Qb[qr * LDQ + kb + t4 + 4];
            af[3] = Qb[(qr + 8) * LDQ + kb + t4 + 4];
            #pragma unroll
            for (int nt = 0; nt < 8; nt++) {
                uint32_t bf[2];
                bf[0] = Kb[(nt * 8 + g) * LDK + kb + t4];
                bf[1] = Kb[(nt * 8 + g) * LDK + kb + t4 + 4];
                mma16n8k8(s[nt], af, bf, s[nt]);
            }
        }

        float mc0 = -1e30f, mc1 = -1e30f;
        #pragma unroll
        for (int nt = 0; nt < 8; nt++) {
            const int col = j0 + nt * 8 + 2 * t4;
            int2 m0 = *(const int2*)&mask[maskBase + (size_t)r0g * SEQ + col];
            int2 m1 = *(const int2*)&mask[maskBase + (size_t)(r0g + 8) * SEQ + col];
            s[nt][0] = (m0.x == 0) ? -1e9f : s[nt][0] * 0.125f;
            s[nt][1] = (m0.y == 0) ? -1e9f : s[nt][1] * 0.125f;
            s[nt][2] = (m1.x == 0) ? -1e9f : s[nt][2] * 0.125f;
            s[nt][3] = (m1.y == 0) ? -1e9f : s[nt][3] * 0.125f;
            mc0 = fmaxf(mc0, fmaxf(s[nt][0], s[nt][1]));
            mc1 = fmaxf(mc1, fmaxf(s[nt][2], s[nt][3]));
        }
        mc0 = fmaxf(mc0, __shfl_xor_sync(0xffffffffu, mc0, 1));
        mc0 = fmaxf(mc0, __shfl_xor_sync(0xffffffffu, mc0, 2));
        mc1 = fmaxf(mc1, __shfl_xor_sync(0xffffffffu, mc1, 1));
        mc1 = fmaxf(mc1, __shfl_xor_sync(0xffffffffu, mc1, 2));

        const float mn0 = fmaxf(mprev0, mc0);
        const float mn1 = fmaxf(mprev1, mc1);
        const float a0 = __expf(mprev0 - mn0);
        const float a1 = __expf(mprev1 - mn1);

        float lc0 = 0.f, lc1 = 0.f;
        #pragma unroll
        for (int nt = 0; nt < 8; nt++) {
            float p0 = __expf(s[nt][0] - mn0);
            float p1 = __expf(s[nt][1] - mn0);
            float p2 = __expf(s[nt][2] - mn1);
            float p3 = __expf(s[nt][3] - mn1);
            lc0 += p0 + p1;
            lc1 += p2 + p3;
            float2 w0; w0.x = to_tf32(p0); w0.y = to_tf32(p1);
            float2 w1; w1.x = to_tf32(p2); w1.y = to_tf32(p3);
            *(float2*)&Pw[g * LDP + nt * 8 + 2 * t4] = w0;
            *(float2*)&Pw[(g + 8) * LDP + nt * 8 + 2 * t4] = w1;
        }
        lc0 += __shfl_xor_sync(0xffffffffu, lc0, 1);
        lc0 += __shfl_xor_sync(0xffffffffu, lc0, 2);
        lc1 += __shfl_xor_sync(0xffffffffu, lc1, 1);
        lc1 += __shfl_xor_sync(0xffffffffu, lc1, 2);
        l0 = l0 * a0 + lc0;
        l1 = l1 * a1 + lc1;

        #pragma unroll
        for (int dn = 0; dn < 8; dn++) {
            oacc[dn][0] *= a0; oacc[dn][1] *= a0;
            oacc[dn][2] *= a1; oacc[dn][3] *= a1;
        }
        mprev0 = mn0; mprev1 = mn1;

        __syncwarp();

        const uint32_t* Pb = (const uint32_t*)Pw;
        const uint32_t* Vb = (const uint32_t*)Vs;
        #pragma unroll
        for (int j8 = 0; j8 < 8; j8++) {
            const int kb = j8 * 8;
            uint32_t af[4];
            af[0] = Pb[g * LDP + kb + t4];
            af[1] = Pb[(g + 8) * LDP + kb + t4];
            af[2] = Pb[g * LDP + kb + t4 + 4];
            af[3] = Pb[(g + 8) * LDP + kb + t4 + 4];
            #pragma unroll
            for (int dn = 0; dn < 8; dn++) {
                uint32_t bf[2];
                bf[0] = Vb[(kb + t4) * LDV + dn * 8 + g];
                bf[1] = Vb[(kb + t4 + 4) * LDV + dn * 8 + g];
                mma16n8k8(oacc[dn], af, bf, oacc[dn]);
            }
        }
        __syncthreads();
    }

    const float inv0 = 1.0f / l0;
    const float inv1 = 1.0f / l1;
    __half* c0row = ctx + (size_t)(b * SEQ + r0g) * DMODEL + hbase;
    __half* c1row = ctx + (size_t)(b * SEQ + r0g + 8) * DMODEL + hbase;
    #pragma unroll
    for (int dn = 0; dn < 8; dn++) {
        const int dc = dn * 8 + 2 * t4;
        *(uint32_t*)&c0row[dc] = pack_h2(oacc[dn][0] * inv0, oacc[dn][1] * inv0);
        *(uint32_t*)&c1row[dc] = pack_h2(oacc[dn][2] * inv1, oacc[dn][3] * inv1);
    }
}

// ---------------- launch ----------------
extern "C" void kernel_launch(void* const* d_in, const int* in_sizes, int n_in,
                              void* d_out, int out_size)
{
    const float* x    = (const float*)d_in[0];
    const int*   mask = (const int*)  d_in[1];
    const float* wq = (const float*)d_in[2];  const float* bq = (const float*)d_in[3];
    const float* wk = (const float*)d_in[4];  const float* bk = (const float*)d_in[5];
    const float* wv = (const float*)d_in[6];  const float* bv = (const float*)d_in[7];
    const float* wo = (const float*)d_in[8];  const float* bo = (const float*)d_in[9];
    const float* w1 = (const float*)d_in[10]; const float* b1 = (const float*)d_in[11];
    const float* w2 = (const float*)d_in[12]; const float* b2 = (const float*)d_in[13];
    const float* ln1_a = (const float*)d_in[14]; const float* ln1_b = (const float*)d_in[15];
    const float* ln2_a = (const float*)d_in[16]; const float* ln2_b = (const float*)d_in[17];
    float* out = (float*)d_out;

    float *p_q, *p_k, *p_v, *p_x1, *p_l1, *p_l2;
    __half *p_ctxh, *p_ffh;
    __half *p_whq, *p_whk, *p_whv, *p_who, *p_wh1, *p_wh2;
    cudaGetSymbolAddress((void**)&p_q,  g_q);
    cudaGetSymbolAddress((void**)&p_k,  g_k);
    cudaGetSymbolAddress((void**)&p_v,  g_v);
    cudaGetSymbolAddress((void**)&p_ctxh, g_ctxh);
    cudaGetSymbolAddress((void**)&p_x1, g_x1);
    cudaGetSymbolAddress((void**)&p_ffh, g_ffh);
    cudaGetSymbolAddress((void**)&p_l1, g_ln1);
    cudaGetSymbolAddress((void**)&p_l2, g_ln2);
    cudaGetSymbolAddress((void**)&p_whq, g_whq);
    cudaGetSymbolAddress((void**)&p_whk, g_whk);
    cudaGetSymbolAddress((void**)&p_whv, g_whv);
    cudaGetSymbolAddress((void**)&p_who, g_who);
    cudaGetSymbolAddress((void**)&p_wh1, g_wh1);
    cudaGetSymbolAddress((void**)&p_wh2, g_wh2);

    // templated (no-cast) attribute calls — matches every previously passing round
    cudaFuncSetAttribute(gemm_h<0,0,1,1,0,float>, cudaFuncAttributeMaxDynamicSharedMemorySize, GEMMH_SMEM);
    cudaFuncSetAttribute(gemm_h<0,1,0,0,1,float>, cudaFuncAttributeMaxDynamicSharedMemorySize, GEMMH_SMEM);
    cudaFuncSetAttribute(gemm_h<1,0,1,0,0,__half>, cudaFuncAttributeMaxDynamicSharedMemorySize, GEMMH_SMEM);
    cudaFuncSetAttribute(flash_attn, cudaFuncAttributeMaxDynamicSharedMemorySize, FA_SMEM);

    // 0) weight conversion
    wconv4<<<dim3(DMODEL/64, DMODEL/64, 4), 256>>>(wq, p_whq, wk, p_whk, wv, p_whv, wo, p_who);
    wconv<<<dim3(DFF/64, DMODEL/64), 256>>>(w1, p_wh1, DMODEL, DFF);
    wconv<<<dim3(DMODEL/64, DFF/64), 256>>>(w2, p_wh2, DFF, DMODEL);

    // 1) LN1 stats
    ln_stats<<<MTOK, 256>>>(x, p_l1, ln1_a, ln1_b);

    // 2) QKV projection (LN fused, fp32 A register path)
    gemm_h<0,0,1,1,0,float><<<dim3(24, MTOK / 128), 256, GEMMH_SMEM>>>(
        x, nullptr, p_whq, p_whk, p_whv, bq, bk, bv, nullptr, p_l1,
        p_q, p_k, p_v, DMODEL, DMODEL);

    // 3) flash attention -> fp16 ctx
    flash_attn<<<dim3(SEQ / 128, BATCH * NHEADS), 256, FA_SMEM>>>(p_q, p_k, p_v, mask, p_ctxh);

    // 4) O projection + residual (A = fp16 ctx via cp.async)
    gemm_h<0,1,0,0,1,float><<<dim3(8, MTOK / 128), 256, GEMMH_SMEM>>>(
        nullptr, p_ctxh, p_who, nullptr, nullptr, bo, nullptr, nullptr, x, nullptr,
        p_x1, nullptr, nullptr, DMODEL, DMODEL);

    // 5) LN2 stats
    ln_stats<<<MTOK, 256>>>(p_x1, p_l2, ln2_a, ln2_b);

    // 6) FFN1 + ReLU (LN fused) -> fp16
    gemm_h<1,0,1,0,0,__half><<<dim3(DFF / 128, MTOK / 128), 256, GEMMH_SMEM>>>(
        p_x1, nullptr, p_wh1, nullptr, nullptr, b1, nullptr, nullptr, nullptr, p_l2,
        p_ffh, nullptr, nullptr, DMODEL, DFF);

    // 7) FFN2 + residual -> out (A = fp16 ff via cp.async)
    gemm_h<0,1,0,0,1,float><<<dim3(8, MTOK / 128), 256, GEMMH_SMEM>>>(
        nullptr, p_ffh, p_wh2, nullptr, nullptr, b2, nullptr, nullptr, p_x1, nullptr,
        out, nullptr, nullptr, DFF, DMODEL);
}